// round 1
// baseline (speedup 1.0000x reference)
#include <cuda_runtime.h>
#include <cuda_bf16.h>

// Problem constants
#define BB   2
#define SS   2048
#define DIM  512
#define NH   8
#define HD   64
#define QK   512          // NH*HD
#define ROWQ 1536         // 2*QK + DIM
#define NP   4096         // B*S positions

// ---------------- scratch (device globals: allocation-free) ----------------
__device__ float g_qkv[NP * ROWQ];     // [4096,1536] q|k|v
__device__ float g_att[NP * DIM];      // [4096,512]
__device__ float g_mask[NP];           // normalized 0/1 mask

// ---------------- mask dtype sniff + normalize ----------------
// jax bool may arrive as u8(1B), int32, or float32. Detect by byte pattern in
// the first 512 bytes (safe under every interpretation: min buffer = 4096 B).
__global__ void convert_mask_kernel(const unsigned char* __restrict__ raw) {
    __shared__ int typ_s;
    if (threadIdx.x == 0) {
        int t = 1; // default int32
        for (int i = 0; i < 512; i++) {
            unsigned char b = raw[i];
            if ((i & 3) != 0 && b != 0) {
                t = (b == 0x3f || b == 0x80) ? 2 : 0;  // f32 : u8
                break;
            }
        }
        typ_s = t;
    }
    __syncthreads();
    int t = typ_s;
    for (int i = threadIdx.x; i < NP; i += blockDim.x) {
        float m;
        if (t == 0)      m = raw[i] ? 1.0f : 0.0f;
        else if (t == 1) m = (((const int*)raw)[i] != 0) ? 1.0f : 0.0f;
        else             m = (((const float*)raw)[i] != 0.0f) ? 1.0f : 0.0f;
        g_mask[i] = m;
    }
}

// ---------------- generic C = A @ B^T  (A:[M,K] rm, B:[N,K] rm) ----------------
// 128x128 tile, BK=8, 256 threads, 8x8 microtile, float4 smem reads.
__global__ void __launch_bounds__(256) gemm_tn_kernel(
    const float* __restrict__ A, const float* __restrict__ Bm,
    float* __restrict__ C, int M, int N, int K)
{
    __shared__ float As[8][128];
    __shared__ float Bs[8][128];

    const int bm = blockIdx.y, bn = blockIdx.x;
    const int tid = threadIdx.x;
    const int tx = tid & 15, ty = tid >> 4;
    const int r  = tid >> 1;          // 0..127
    const int kq = (tid & 1) * 4;     // 0 or 4

    const float* Aptr = A + (size_t)(bm * 128 + r) * K + kq;
    const float* Bptr = Bm + (size_t)(bn * 128 + r) * K + kq;

    float acc[8][8];
#pragma unroll
    for (int i = 0; i < 8; i++)
#pragma unroll
        for (int j = 0; j < 8; j++) acc[i][j] = 0.0f;

    for (int k0 = 0; k0 < K; k0 += 8) {
        float4 av = *(const float4*)(Aptr + k0);
        float4 bv = *(const float4*)(Bptr + k0);
        __syncthreads();
        As[kq + 0][r] = av.x; As[kq + 1][r] = av.y;
        As[kq + 2][r] = av.z; As[kq + 3][r] = av.w;
        Bs[kq + 0][r] = bv.x; Bs[kq + 1][r] = bv.y;
        Bs[kq + 2][r] = bv.z; Bs[kq + 3][r] = bv.w;
        __syncthreads();
#pragma unroll
        for (int kk = 0; kk < 8; kk++) {
            float a[8], b[8];
            *(float4*)(a)     = *(const float4*)&As[kk][ty * 4];
            *(float4*)(a + 4) = *(const float4*)&As[kk][64 + ty * 4];
            *(float4*)(b)     = *(const float4*)&Bs[kk][tx * 4];
            *(float4*)(b + 4) = *(const float4*)&Bs[kk][64 + tx * 4];
#pragma unroll
            for (int i = 0; i < 8; i++)
#pragma unroll
                for (int j = 0; j < 8; j++)
                    acc[i][j] = fmaf(a[i], b[j], acc[i][j]);
        }
    }

#pragma unroll
    for (int i = 0; i < 8; i++) {
        int row = bm * 128 + ((i < 4) ? (ty * 4 + i) : (64 + ty * 4 + i - 4));
        float4 v0 = make_float4(acc[i][0], acc[i][1], acc[i][2], acc[i][3]);
        float4 v1 = make_float4(acc[i][4], acc[i][5], acc[i][6], acc[i][7]);
        *(float4*)&C[(size_t)row * N + bn * 128 + tx * 4]      = v0;
        *(float4*)&C[(size_t)row * N + bn * 128 + 64 + tx * 4] = v1;
    }
}

// ---------------- per-position rotation of q,k heads where masked ----------------
// qkv row p, cols [0,1024) = 16 vectors of 64 (8 q heads, 8 k heads).
// v_new[i] = sum_j R[i][j] * v[j]
__global__ void __launch_bounds__(256) rotate_kernel(
    const float* __restrict__ rot)
{
    const int p = blockIdx.x;
    if (g_mask[p] == 0.0f) return;

    __shared__ float Rt[64 * 65];   // transposed, padded
    __shared__ float X[1024];

    const int tid = threadIdx.x;
    const float* R = rot + (size_t)p * 4096;
#pragma unroll
    for (int t = 0; t < 16; t++) {
        int idx = tid + 256 * t;
        int i = idx >> 6, j = idx & 63;
        Rt[j * 65 + i] = R[idx];
    }
#pragma unroll
    for (int t = 0; t < 4; t++) {
        int idx = tid + 256 * t;
        X[idx] = g_qkv[(size_t)p * ROWQ + idx];
    }
    __syncthreads();

    const int i  = tid & 63;
    const int vb = tid >> 6;
#pragma unroll
    for (int ii = 0; ii < 4; ii++) {
        int v = vb + 4 * ii;
        float acc = 0.0f;
#pragma unroll 8
        for (int j = 0; j < 64; j++)
            acc = fmaf(Rt[j * 65 + i], X[v * 64 + j], acc);
        g_qkv[(size_t)p * ROWQ + v * 64 + i] = acc;
    }
}

// ---------------- flash-style Taylor attention ----------------
// grid (32 qtiles, 16 b*h), 256 threads, 64x64 tiles, 4x4 microtile.
__global__ void __launch_bounds__(256) attn_kernel(float* __restrict__ out)
{
    extern __shared__ float sm[];
    float* Qs = sm;                    // 64*65
    float* Ks = sm + 4160;
    float* Vs = sm + 2 * 4160;
    float* Ws = sm + 3 * 4160;
    float* mk = sm + 4 * 4160;         // 64
    float* dn = mk + 64;               // 64

    const int qt = blockIdx.x;
    const int bh = blockIdx.y;
    const int b = bh >> 3, h = bh & 7;
    const int tid = threadIdx.x;
    const int tx = tid & 15, ty = tid >> 4;
    const int prow0 = b * SS;

    // load Q tile
    for (int i = tid; i < 64 * 64; i += 256) {
        int r = i >> 6, d = i & 63;
        Qs[r * 65 + d] = g_qkv[(size_t)(prow0 + qt * 64 + r) * ROWQ + h * 64 + d];
    }

    float num[4][4];
#pragma unroll
    for (int a = 0; a < 4; a++)
#pragma unroll
        for (int c = 0; c < 4; c++) num[a][c] = 0.0f;
    float den = 0.0f;  // valid for tid<64 (query tid)

    for (int kt = 0; kt < 32; kt++) {
        __syncthreads();  // protect Qs (first iter) / Ks,Vs,Ws reuse
        for (int i = tid; i < 64 * 64; i += 256) {
            int r = i >> 6, d = i & 63;
            const float* src = &g_qkv[(size_t)(prow0 + kt * 64 + r) * ROWQ + QK + h * 64 + d];
            Ks[r * 65 + d] = src[0];
            Vs[r * 65 + d] = src[QK];
        }
        if (tid < 64) mk[tid] = g_mask[prow0 + kt * 64 + tid];
        __syncthreads();

        // S = Q K^T
        float s[4][4];
#pragma unroll
        for (int a = 0; a < 4; a++)
#pragma unroll
            for (int c = 0; c < 4; c++) s[a][c] = 0.0f;
#pragma unroll 8
        for (int d = 0; d < 64; d++) {
            float qv[4], kv[4];
#pragma unroll
            for (int a = 0; a < 4; a++) qv[a] = Qs[(ty + 16 * a) * 65 + d];
#pragma unroll
            for (int c = 0; c < 4; c++) kv[c] = Ks[(tx + 16 * c) * 65 + d];
#pragma unroll
            for (int a = 0; a < 4; a++)
#pragma unroll
                for (int c = 0; c < 4; c++)
                    s[a][c] = fmaf(qv[a], kv[c], s[a][c]);
        }
        // w = (1 + sc + 0.5 sc^2) * mask,  sc = s/8
#pragma unroll
        for (int a = 0; a < 4; a++)
#pragma unroll
            for (int c = 0; c < 4; c++) {
                float sc = s[a][c] * 0.125f;
                float w = fmaf(sc, fmaf(0.5f, sc, 1.0f), 1.0f);
                w *= mk[tx + 16 * c];
                Ws[(ty + 16 * a) * 65 + (tx + 16 * c)] = w;
            }
        __syncthreads();

        if (tid < 64) {
            float acc = 0.0f;
#pragma unroll 8
            for (int k = 0; k < 64; k++) acc += Ws[tid * 65 + k];
            den += acc;
        }
        // num += W V
#pragma unroll 8
        for (int k = 0; k < 64; k++) {
            float wv[4], vv[4];
#pragma unroll
            for (int a = 0; a < 4; a++) wv[a] = Ws[(ty + 16 * a) * 65 + k];
#pragma unroll
            for (int c = 0; c < 4; c++) vv[c] = Vs[k * 65 + tx + 16 * c];
#pragma unroll
            for (int a = 0; a < 4; a++)
#pragma unroll
                for (int c = 0; c < 4; c++)
                    num[a][c] = fmaf(wv[a], vv[c], num[a][c]);
        }
    }
    __syncthreads();
    if (tid < 64) dn[tid] = den;
    __syncthreads();

#pragma unroll
    for (int a = 0; a < 4; a++) {
        int q = ty + 16 * a;
        float inv = 1.0f / dn[q];
#pragma unroll
        for (int c = 0; c < 4; c++) {
            int vd = tx + 16 * c;
            out[(size_t)(prow0 + qt * 64 + q) * DIM + h * 64 + vd] = num[a][c] * inv;
        }
    }
}

// ---------------- launch ----------------
extern "C" void kernel_launch(void* const* d_in, const int* in_sizes, int n_in,
                              void* d_out, int out_size)
{
    const float*         x    = (const float*)d_in[0];
    const unsigned char* mask = (const unsigned char*)d_in[1];
    const float*         rot  = (const float*)d_in[2];
    const float*         Wt   = (const float*)d_in[3];
    const float*         Wo   = (const float*)d_in[4];
    float*               out  = (float*)d_out;

    float *qkv_p, *att_p;
    cudaGetSymbolAddress((void**)&qkv_p, g_qkv);
    cudaGetSymbolAddress((void**)&att_p, g_att);

    // attention kernel needs 67072 B dynamic smem
    static const int ATT_SMEM = (4 * 4160 + 128) * (int)sizeof(float);
    cudaFuncSetAttribute(attn_kernel, cudaFuncAttributeMaxDynamicSharedMemorySize, ATT_SMEM);

    convert_mask_kernel<<<1, 256>>>(mask);

    // qkv = x @ W_trans^T : M=4096, N=1536, K=512
    gemm_tn_kernel<<<dim3(ROWQ / 128, NP / 128), 256>>>(x, Wt, qkv_p, NP, ROWQ, DIM);

    // rotate q,k heads where masked
    rotate_kernel<<<NP, 256>>>(rot);

    // attention -> g_att
    attn_kernel<<<dim3(SS / 64, BB * NH), 256, ATT_SMEM>>>(att_p);

    // out = att @ W_o^T : M=4096, N=512, K=512
    gemm_tn_kernel<<<dim3(DIM / 128, NP / 128), 256>>>(att_p, Wo, out, NP, DIM, DIM);
}

// round 3
// speedup vs baseline: 1.7323x; 1.7323x over previous
#include <cuda_runtime.h>
#include <cuda_bf16.h>
#include <cstdint>

// Problem constants
#define BB   2
#define SS   2048
#define DIM  512
#define NH   8
#define HD   64
#define QK   512          // NH*HD
#define ROWQ 1536         // 2*QK + DIM
#define NP   4096         // B*S positions

#define PADQ 68           // row pitch (words) for Q/K/V tiles
#define PADW 132          // row pitch (words) for W tile

// ---------------- scratch ----------------
__device__ float g_qkv[NP * ROWQ];
__device__ float g_att[NP * DIM];
__device__ float g_mask[NP];

// ---------------- helpers ----------------
__device__ __forceinline__ uint32_t f2tf32(float f) {
    uint32_t r; asm("cvt.rn.tf32.f32 %0, %1;" : "=r"(r) : "f"(f)); return r;
}

__device__ __forceinline__ void mma_tf32(float* c,
    uint32_t a0, uint32_t a1, uint32_t a2, uint32_t a3, uint32_t b0, uint32_t b1)
{
    asm volatile(
        "mma.sync.aligned.m16n8k8.row.col.f32.tf32.tf32.f32 "
        "{%0,%1,%2,%3}, {%4,%5,%6,%7}, {%8,%9}, {%0,%1,%2,%3};"
        : "+f"(c[0]), "+f"(c[1]), "+f"(c[2]), "+f"(c[3])
        : "r"(a0), "r"(a1), "r"(a2), "r"(a3), "r"(b0), "r"(b1));
}

// ---------------- mask sniff ----------------
__global__ void convert_mask_kernel(const unsigned char* __restrict__ raw) {
    __shared__ int typ_s;
    if (threadIdx.x == 0) {
        int t = 1;
        for (int i = 0; i < 512; i++) {
            unsigned char b = raw[i];
            if ((i & 3) != 0 && b != 0) { t = (b == 0x3f || b == 0x80) ? 2 : 0; break; }
        }
        typ_s = t;
    }
    __syncthreads();
    int t = typ_s;
    for (int i = threadIdx.x; i < NP; i += blockDim.x) {
        float m;
        if (t == 0)      m = raw[i] ? 1.0f : 0.0f;
        else if (t == 1) m = (((const int*)raw)[i] != 0) ? 1.0f : 0.0f;
        else             m = (((const float*)raw)[i] != 0.0f) ? 1.0f : 0.0f;
        g_mask[i] = m;
    }
}

// ---------------- fp32 SIMT GEMM  C = A @ B^T ----------------
__global__ void __launch_bounds__(256) gemm_tn_kernel(
    const float* __restrict__ A, const float* __restrict__ Bm,
    float* __restrict__ C, int M, int N, int K)
{
    __shared__ float As[8][128];
    __shared__ float Bs[8][128];

    const int bm = blockIdx.y, bn = blockIdx.x;
    const int tid = threadIdx.x;
    const int tx = tid & 15, ty = tid >> 4;
    const int r  = tid >> 1;
    const int kq = (tid & 1) * 4;

    const float* Aptr = A + (size_t)(bm * 128 + r) * K + kq;
    const float* Bptr = Bm + (size_t)(bn * 128 + r) * K + kq;

    float acc[8][8];
#pragma unroll
    for (int i = 0; i < 8; i++)
#pragma unroll
        for (int j = 0; j < 8; j++) acc[i][j] = 0.0f;

    for (int k0 = 0; k0 < K; k0 += 8) {
        float4 av = *(const float4*)(Aptr + k0);
        float4 bv = *(const float4*)(Bptr + k0);
        __syncthreads();
        As[kq + 0][r] = av.x; As[kq + 1][r] = av.y;
        As[kq + 2][r] = av.z; As[kq + 3][r] = av.w;
        Bs[kq + 0][r] = bv.x; Bs[kq + 1][r] = bv.y;
        Bs[kq + 2][r] = bv.z; Bs[kq + 3][r] = bv.w;
        __syncthreads();
#pragma unroll
        for (int kk = 0; kk < 8; kk++) {
            float a[8], b[8];
            *(float4*)(a)     = *(const float4*)&As[kk][ty * 4];
            *(float4*)(a + 4) = *(const float4*)&As[kk][64 + ty * 4];
            *(float4*)(b)     = *(const float4*)&Bs[kk][tx * 4];
            *(float4*)(b + 4) = *(const float4*)&Bs[kk][64 + tx * 4];
#pragma unroll
            for (int i = 0; i < 8; i++)
#pragma unroll
                for (int j = 0; j < 8; j++)
                    acc[i][j] = fmaf(a[i], b[j], acc[i][j]);
        }
    }

#pragma unroll
    for (int i = 0; i < 8; i++) {
        int row = bm * 128 + ((i < 4) ? (ty * 4 + i) : (64 + ty * 4 + i - 4));
        float4 v0 = make_float4(acc[i][0], acc[i][1], acc[i][2], acc[i][3]);
        float4 v1 = make_float4(acc[i][4], acc[i][5], acc[i][6], acc[i][7]);
        *(float4*)&C[(size_t)row * N + bn * 128 + tx * 4]      = v0;
        *(float4*)&C[(size_t)row * N + bn * 128 + 64 + tx * 4] = v1;
    }
}

// ---------------- rotation ----------------
__global__ void __launch_bounds__(256) rotate_kernel(const float* __restrict__ rot)
{
    const int p = blockIdx.x;
    if (g_mask[p] == 0.0f) return;

    __shared__ float Rt[64 * 65];
    __shared__ float X[1024];

    const int tid = threadIdx.x;
    const float* R = rot + (size_t)p * 4096;
#pragma unroll
    for (int t = 0; t < 16; t++) {
        int idx = tid + 256 * t;
        int i = idx >> 6, j = idx & 63;
        Rt[j * 65 + i] = R[idx];
    }
#pragma unroll
    for (int t = 0; t < 4; t++) {
        int idx = tid + 256 * t;
        X[idx] = g_qkv[(size_t)p * ROWQ + idx];
    }
    __syncthreads();

    const int i  = tid & 63;
    const int vb = tid >> 6;
#pragma unroll
    for (int ii = 0; ii < 4; ii++) {
        int v = vb + 4 * ii;
        float acc = 0.0f;
#pragma unroll 8
        for (int j = 0; j < 64; j++)
            acc = fmaf(Rt[j * 65 + i], X[v * 64 + j], acc);
        g_qkv[(size_t)p * ROWQ + v * 64 + i] = acc;
    }
}

// ---------------- mma.sync tf32 Taylor attention ----------------
// grid (16 qtiles, 16 bh), 256 threads = 8 warps.
// Per CTA: q rows [qt*128, qt*128+128), loop over 16 key tiles of 128.
// Warp w owns q rows w*16..w*16+15 (m16), all 128 keys (16 n8), HD=64 (8 k8).

#define SM_WORDS (3 * 128 * PADQ + 128 * PADW + 128)

__global__ void __launch_bounds__(256) attn_mma_kernel(float* __restrict__ outp)
{
    extern __shared__ uint32_t sm[];
    uint32_t* Qs = sm;                       // 128 x PADQ (tf32 bits)
    uint32_t* Ks = Qs + 128 * PADQ;
    uint32_t* Vs = Ks + 128 * PADQ;
    uint32_t* Ws = Vs + 128 * PADQ;          // 128 x PADW
    float*    mk = (float*)(Ws + 128 * PADW);

    const int tid = threadIdx.x;
    const int w = tid >> 5, lane = tid & 31;
    const int g = lane >> 2, t = lane & 3;   // groupID / threadID-in-group
    const int qt = blockIdx.x, bh = blockIdx.y;
    const int b = bh >> 3, h = bh & 7;
    const int prow0 = b * SS;

    // ---- load Q tile once (fp32 -> tf32 bits) ----
    {
        const int r = tid >> 1, half = tid & 1;
        const float* src = &g_qkv[(size_t)(prow0 + qt * 128 + r) * ROWQ + h * 64 + half * 32];
        uint32_t* dst = &Qs[r * PADQ + half * 32];
#pragma unroll
        for (int i = 0; i < 8; i++) {
            float4 v = *(const float4*)(src + 4 * i);
            *(uint4*)(dst + 4 * i) =
                make_uint4(f2tf32(v.x), f2tf32(v.y), f2tf32(v.z), f2tf32(v.w));
        }
    }

    float outr[8][4];
#pragma unroll
    for (int n = 0; n < 8; n++)
#pragma unroll
        for (int j = 0; j < 4; j++) outr[n][j] = 0.0f;
    float den0 = 0.0f, den1 = 0.0f;   // rows g and g+8 (pre quad-reduce)

    const int rowA = w * 16 + g;      // this thread's upper q row
    const int rowB = rowA + 8;

    for (int kt = 0; kt < 16; kt++) {
        __syncthreads();   // prev iter's MMA2 reads done before K/V/W overwrite

        // ---- load K + V tiles (fp32 -> tf32), mask ----
        {
            const int r = tid >> 1, half = tid & 1;
            const size_t grow = (size_t)(prow0 + kt * 128 + r) * ROWQ;
            const float* ksrc = &g_qkv[grow + QK + h * 64 + half * 32];
            const float* vsrc = &g_qkv[grow + 2 * QK + h * 64 + half * 32];
            uint32_t* kdst = &Ks[r * PADQ + half * 32];
            uint32_t* vdst = &Vs[r * PADQ + half * 32];
#pragma unroll
            for (int i = 0; i < 8; i++) {
                float4 kv = *(const float4*)(ksrc + 4 * i);
                float4 vv = *(const float4*)(vsrc + 4 * i);
                *(uint4*)(kdst + 4 * i) =
                    make_uint4(f2tf32(kv.x), f2tf32(kv.y), f2tf32(kv.z), f2tf32(kv.w));
                *(uint4*)(vdst + 4 * i) =
                    make_uint4(f2tf32(vv.x), f2tf32(vv.y), f2tf32(vv.z), f2tf32(vv.w));
            }
            if (tid < 128) mk[tid] = g_mask[prow0 + kt * 128 + tid];
        }
        __syncthreads();

        // ---- MMA1: S[16,128] = Q @ K^T ----
        float sc[16][4];
#pragma unroll
        for (int n = 0; n < 16; n++)
#pragma unroll
            for (int j = 0; j < 4; j++) sc[n][j] = 0.0f;

#pragma unroll
        for (int k = 0; k < 8; k++) {
            uint32_t a0 = Qs[rowA * PADQ + k * 8 + t];
            uint32_t a1 = Qs[rowB * PADQ + k * 8 + t];
            uint32_t a2 = Qs[rowA * PADQ + k * 8 + t + 4];
            uint32_t a3 = Qs[rowB * PADQ + k * 8 + t + 4];
#pragma unroll
            for (int n = 0; n < 16; n++) {
                uint32_t b0 = Ks[(n * 8 + g) * PADQ + k * 8 + t];
                uint32_t b1 = Ks[(n * 8 + g) * PADQ + k * 8 + t + 4];
                mma_tf32(sc[n], a0, a1, a2, a3, b0, b1);
            }
        }

        // ---- Taylor weights + mask + denominators; W -> smem (tf32) ----
#pragma unroll
        for (int n = 0; n < 16; n++) {
            float m0 = mk[n * 8 + 2 * t];
            float m1 = mk[n * 8 + 2 * t + 1];
            float s0 = sc[n][0] * 0.125f, s1 = sc[n][1] * 0.125f;
            float s2 = sc[n][2] * 0.125f, s3 = sc[n][3] * 0.125f;
            float w0 = fmaf(s0, fmaf(0.5f, s0, 1.0f), 1.0f) * m0;
            float w1 = fmaf(s1, fmaf(0.5f, s1, 1.0f), 1.0f) * m1;
            float w2 = fmaf(s2, fmaf(0.5f, s2, 1.0f), 1.0f) * m0;
            float w3 = fmaf(s3, fmaf(0.5f, s3, 1.0f), 1.0f) * m1;
            den0 += w0 + w1;
            den1 += w2 + w3;
            *(uint2*)&Ws[rowA * PADW + n * 8 + 2 * t] = make_uint2(f2tf32(w0), f2tf32(w1));
            *(uint2*)&Ws[rowB * PADW + n * 8 + 2 * t] = make_uint2(f2tf32(w2), f2tf32(w3));
        }
        __syncthreads();

        // ---- MMA2: O[16,64] += W[16,128] @ V[128,64] ----
#pragma unroll
        for (int k = 0; k < 16; k++) {
            uint32_t a0 = Ws[rowA * PADW + k * 8 + t];
            uint32_t a1 = Ws[rowB * PADW + k * 8 + t];
            uint32_t a2 = Ws[rowA * PADW + k * 8 + t + 4];
            uint32_t a3 = Ws[rowB * PADW + k * 8 + t + 4];
#pragma unroll
            for (int n = 0; n < 8; n++) {
                uint32_t b0 = Vs[(k * 8 + t) * PADQ + n * 8 + g];
                uint32_t b1 = Vs[(k * 8 + t + 4) * PADQ + n * 8 + g];
                mma_tf32(outr[n], a0, a1, a2, a3, b0, b1);
            }
        }
    }

    // ---- quad-reduce denominators (sum across t within the quad) ----
    den0 += __shfl_xor_sync(0xffffffffu, den0, 1);
    den0 += __shfl_xor_sync(0xffffffffu, den0, 2);
    den1 += __shfl_xor_sync(0xffffffffu, den1, 1);
    den1 += __shfl_xor_sync(0xffffffffu, den1, 2);
    float inv0 = 1.0f / den0;
    float inv1 = 1.0f / den1;

    // ---- normalize + store ----
    {
        float* dA = &outp[(size_t)(prow0 + qt * 128 + rowA) * DIM + h * 64];
        float* dB = &outp[(size_t)(prow0 + qt * 128 + rowB) * DIM + h * 64];
#pragma unroll
        for (int n = 0; n < 8; n++) {
            int c = n * 8 + 2 * t;
            *(float2*)(dA + c) = make_float2(outr[n][0] * inv0, outr[n][1] * inv0);
            *(float2*)(dB + c) = make_float2(outr[n][2] * inv1, outr[n][3] * inv1);
        }
    }
}

// ---------------- launch ----------------
extern "C" void kernel_launch(void* const* d_in, const int* in_sizes, int n_in,
                              void* d_out, int out_size)
{
    const float*         x    = (const float*)d_in[0];
    const unsigned char* mask = (const unsigned char*)d_in[1];
    const float*         rot  = (const float*)d_in[2];
    const float*         Wt   = (const float*)d_in[3];
    const float*         Wo   = (const float*)d_in[4];
    float*               out  = (float*)d_out;

    float *qkv_p, *att_p;
    cudaGetSymbolAddress((void**)&qkv_p, g_qkv);
    cudaGetSymbolAddress((void**)&att_p, g_att);

    static const int ATT_SMEM = SM_WORDS * (int)sizeof(uint32_t);  // 172,544 B
    cudaFuncSetAttribute(attn_mma_kernel, cudaFuncAttributeMaxDynamicSharedMemorySize, ATT_SMEM);

    convert_mask_kernel<<<1, 256>>>(mask);

    // qkv = x @ W_trans^T
    gemm_tn_kernel<<<dim3(ROWQ / 128, NP / 128), 256>>>(x, Wt, qkv_p, NP, ROWQ, DIM);

    // rotate q,k heads where masked
    rotate_kernel<<<NP, 256>>>(rot);

    // attention (mma.sync tf32) -> g_att
    attn_mma_kernel<<<dim3(SS / 128, BB * NH), 256, ATT_SMEM>>>(att_p);

    // out = att @ W_o^T
    gemm_tn_kernel<<<dim3(DIM / 128, NP / 128), 256>>>(att_p, Wo, out, NP, DIM, DIM);
}

// round 4
// speedup vs baseline: 2.4373x; 1.4069x over previous
#include <cuda_runtime.h>
#include <cuda_bf16.h>
#include <cstdint>

// Problem constants
#define BB   2
#define SS   2048
#define DIM  512
#define NH   8
#define HD   64
#define QK   512          // NH*HD
#define ROWQ 1536         // 2*QK + DIM
#define NP   4096         // B*S positions

#define PADQ 68           // row pitch (words) for Q/K tiles
#define PADV 132          // row pitch (words) for V^T tile

// ---------------- scratch ----------------
__device__ float g_qkv[NP * ROWQ];
__device__ float g_att[NP * DIM];
__device__ float g_mask[NP];

// ---------------- helpers ----------------
__device__ __forceinline__ uint32_t f2tf32(float f) {
    uint32_t r; asm("cvt.rn.tf32.f32 %0, %1;" : "=r"(r) : "f"(f)); return r;
}

__device__ __forceinline__ void mma_tf32(float* c,
    uint32_t a0, uint32_t a1, uint32_t a2, uint32_t a3, uint32_t b0, uint32_t b1)
{
    asm volatile(
        "mma.sync.aligned.m16n8k8.row.col.f32.tf32.tf32.f32 "
        "{%0,%1,%2,%3}, {%4,%5,%6,%7}, {%8,%9}, {%0,%1,%2,%3};"
        : "+f"(c[0]), "+f"(c[1]), "+f"(c[2]), "+f"(c[3])
        : "r"(a0), "r"(a1), "r"(a2), "r"(a3), "r"(b0), "r"(b1));
}

// ---------------- mask sniff ----------------
__global__ void convert_mask_kernel(const unsigned char* __restrict__ raw) {
    __shared__ int typ_s;
    if (threadIdx.x == 0) {
        int t = 1;
        for (int i = 0; i < 512; i++) {
            unsigned char b = raw[i];
            if ((i & 3) != 0 && b != 0) { t = (b == 0x3f || b == 0x80) ? 2 : 0; break; }
        }
        typ_s = t;
    }
    __syncthreads();
    int t = typ_s;
    for (int i = threadIdx.x; i < NP; i += blockDim.x) {
        float m;
        if (t == 0)      m = raw[i] ? 1.0f : 0.0f;
        else if (t == 1) m = (((const int*)raw)[i] != 0) ? 1.0f : 0.0f;
        else             m = (((const float*)raw)[i] != 0.0f) ? 1.0f : 0.0f;
        g_mask[i] = m;
    }
}

// ---------------- tf32 mma GEMM  C = A @ B^T ----------------
// A:[M,K] rm, B:[N,K] rm. CTA 128x128, BK=32, 8 warps (2x4), warp 64m x 32n.
__global__ void __launch_bounds__(256, 2) gemm_tf32_kernel(
    const float* __restrict__ A, const float* __restrict__ Bm,
    float* __restrict__ C, int M, int N, int K)
{
    __shared__ uint32_t As[128 * 36];
    __shared__ uint32_t Bs[128 * 36];

    const int tid = threadIdx.x;
    const int w = tid >> 5, lane = tid & 31;
    const int g = lane >> 2, t = lane & 3;
    const int wm = w >> 2, wn = w & 3;
    const int bm = blockIdx.y, bn = blockIdx.x;

    const int r = tid >> 1, seg = (tid & 1) * 16;
    const float* gA = A + (size_t)(bm * 128 + r) * K + seg;
    const float* gB = Bm + (size_t)(bn * 128 + r) * K + seg;

    float4 pa[4], pb[4];
#pragma unroll
    for (int i = 0; i < 4; i++) {
        pa[i] = *(const float4*)(gA + 4 * i);
        pb[i] = *(const float4*)(gB + 4 * i);
    }

    float acc[4][4][4];
#pragma unroll
    for (int mf = 0; mf < 4; mf++)
#pragma unroll
        for (int nf = 0; nf < 4; nf++)
#pragma unroll
            for (int c = 0; c < 4; c++) acc[mf][nf][c] = 0.0f;

    const int nch = K >> 5;
    for (int ch = 0; ch < nch; ch++) {
        if (ch) __syncthreads();
#pragma unroll
        for (int i = 0; i < 4; i++) {
            uint32_t* d = &As[r * 36 + seg + 4 * i];
            d[0] = f2tf32(pa[i].x); d[1] = f2tf32(pa[i].y);
            d[2] = f2tf32(pa[i].z); d[3] = f2tf32(pa[i].w);
            uint32_t* e = &Bs[r * 36 + seg + 4 * i];
            e[0] = f2tf32(pb[i].x); e[1] = f2tf32(pb[i].y);
            e[2] = f2tf32(pb[i].z); e[3] = f2tf32(pb[i].w);
        }
        __syncthreads();
        if (ch + 1 < nch) {
#pragma unroll
            for (int i = 0; i < 4; i++) {
                pa[i] = *(const float4*)(gA + (ch + 1) * 32 + 4 * i);
                pb[i] = *(const float4*)(gB + (ch + 1) * 32 + 4 * i);
            }
        }
#pragma unroll
        for (int k8 = 0; k8 < 4; k8++) {
            uint32_t a[4][4];
#pragma unroll
            for (int mf = 0; mf < 4; mf++) {
                int rm = wm * 64 + mf * 16;
                a[mf][0] = As[(rm + g) * 36 + k8 * 8 + t];
                a[mf][1] = As[(rm + g + 8) * 36 + k8 * 8 + t];
                a[mf][2] = As[(rm + g) * 36 + k8 * 8 + t + 4];
                a[mf][3] = As[(rm + g + 8) * 36 + k8 * 8 + t + 4];
            }
#pragma unroll
            for (int nf = 0; nf < 4; nf++) {
                int rn = wn * 32 + nf * 8;
                uint32_t b0 = Bs[(rn + g) * 36 + k8 * 8 + t];
                uint32_t b1 = Bs[(rn + g) * 36 + k8 * 8 + t + 4];
#pragma unroll
                for (int mf = 0; mf < 4; mf++)
                    mma_tf32(acc[mf][nf], a[mf][0], a[mf][1], a[mf][2], a[mf][3], b0, b1);
            }
        }
    }

#pragma unroll
    for (int mf = 0; mf < 4; mf++) {
        int row = bm * 128 + wm * 64 + mf * 16 + g;
#pragma unroll
        for (int nf = 0; nf < 4; nf++) {
            int col = bn * 128 + wn * 32 + nf * 8 + 2 * t;
            *(float2*)&C[(size_t)row * N + col]       = make_float2(acc[mf][nf][0], acc[mf][nf][1]);
            *(float2*)&C[(size_t)(row + 8) * N + col] = make_float2(acc[mf][nf][2], acc[mf][nf][3]);
        }
    }
}

// ---------------- rotation ----------------
__global__ void __launch_bounds__(256) rotate_kernel(const float* __restrict__ rot)
{
    const int p = blockIdx.x;
    if (g_mask[p] == 0.0f) return;

    __shared__ float Rt[64 * 65];
    __shared__ float X[1024];

    const int tid = threadIdx.x;
    const float* R = rot + (size_t)p * 4096;
#pragma unroll
    for (int t = 0; t < 16; t++) {
        int idx = tid + 256 * t;
        int i = idx >> 6, j = idx & 63;
        Rt[j * 65 + i] = R[idx];
    }
#pragma unroll
    for (int t = 0; t < 4; t++) {
        int idx = tid + 256 * t;
        X[idx] = g_qkv[(size_t)p * ROWQ + idx];
    }
    __syncthreads();

    const int i  = tid & 63;
    const int vb = tid >> 6;
#pragma unroll
    for (int ii = 0; ii < 4; ii++) {
        int v = vb + 4 * ii;
        float acc = 0.0f;
#pragma unroll 8
        for (int j = 0; j < 64; j++)
            acc = fmaf(Rt[j * 65 + i], X[v * 64 + j], acc);
        g_qkv[(size_t)p * ROWQ + v * 64 + i] = acc;
    }
}

// ---------------- mma.sync tf32 Taylor attention (shfl W-permute, 2 CTA/SM) ----
// grid (16 qtiles, 16 bh), 256 threads = 8 warps.
// Warp w: q rows w*16..w*16+15; 128 keys processed in two halves of 8 k8-blocks.

#define ATT_WORDS (2 * 128 * PADQ + 64 * PADV + 128)

__global__ void __launch_bounds__(256, 2) attn_mma_kernel(float* __restrict__ outp)
{
    extern __shared__ uint32_t sm[];
    uint32_t* Qs = sm;                       // [qrow][d] 128 x PADQ
    uint32_t* Ks = Qs + 128 * PADQ;          // [key][d]  128 x PADQ
    uint32_t* Vt = Ks + 128 * PADQ;          // [d][key]  64 x PADV
    float*    mk = (float*)(Vt + 64 * PADV); // 128

    const int tid = threadIdx.x;
    const int w = tid >> 5, lane = tid & 31;
    const int g = lane >> 2, t = lane & 3;
    const int qt = blockIdx.x, bh = blockIdx.y;
    const int b = bh >> 3, h = bh & 7;
    const int prow0 = b * SS;

    const int r = tid >> 1, hf = tid & 1;

    // ---- load Q tile once (fp32 -> tf32 bits) ----
    {
        const float* src = &g_qkv[(size_t)(prow0 + qt * 128 + r) * ROWQ + h * 64 + hf * 32];
        uint32_t* dst = &Qs[r * PADQ + hf * 32];
#pragma unroll
        for (int i = 0; i < 8; i++) {
            float4 v = *(const float4*)(src + 4 * i);
            *(uint4*)(dst + 4 * i) =
                make_uint4(f2tf32(v.x), f2tf32(v.y), f2tf32(v.z), f2tf32(v.w));
        }
    }

    float outr[8][4];
#pragma unroll
    for (int n = 0; n < 8; n++)
#pragma unroll
        for (int j = 0; j < 4; j++) outr[n][j] = 0.0f;
    float den0 = 0.0f, den1 = 0.0f;

    const int rowA = w * 16 + g;
    const int rowB = rowA + 8;
    const int srcL = (lane & ~3) | (t >> 1);
    const int srcH = srcL + 2;
    const bool odd = (t & 1);

    for (int kt = 0; kt < 16; kt++) {
        __syncthreads();   // prev iter reads done before overwrite

        // ---- load K (row-major) + V (transposed) tiles, mask ----
        {
            const size_t grow = (size_t)(prow0 + kt * 128 + r) * ROWQ;
            const float* ksrc = &g_qkv[grow + QK + h * 64 + hf * 32];
            const float* vsrc = &g_qkv[grow + 2 * QK + h * 64 + hf * 32];
            uint32_t* kdst = &Ks[r * PADQ + hf * 32];
#pragma unroll
            for (int i = 0; i < 8; i++) {
                float4 kv = *(const float4*)(ksrc + 4 * i);
                *(uint4*)(kdst + 4 * i) =
                    make_uint4(f2tf32(kv.x), f2tf32(kv.y), f2tf32(kv.z), f2tf32(kv.w));
                float4 vv = *(const float4*)(vsrc + 4 * i);
                int d0 = hf * 32 + 4 * i;
                Vt[(d0 + 0) * PADV + r] = f2tf32(vv.x);
                Vt[(d0 + 1) * PADV + r] = f2tf32(vv.y);
                Vt[(d0 + 2) * PADV + r] = f2tf32(vv.z);
                Vt[(d0 + 3) * PADV + r] = f2tf32(vv.w);
            }
            if (tid < 128) mk[tid] = g_mask[prow0 + kt * 128 + tid];
        }
        __syncthreads();

#pragma unroll
        for (int h2 = 0; h2 < 2; h2++) {
            const int nb0 = h2 * 8;

            // ---- MMA1: S[16, 64keys] = Q @ K^T ----
            float sc[8][4];
#pragma unroll
            for (int n = 0; n < 8; n++)
#pragma unroll
                for (int j = 0; j < 4; j++) sc[n][j] = 0.0f;

#pragma unroll
            for (int k = 0; k < 8; k++) {
                uint32_t a0 = Qs[rowA * PADQ + k * 8 + t];
                uint32_t a1 = Qs[rowB * PADQ + k * 8 + t];
                uint32_t a2 = Qs[rowA * PADQ + k * 8 + t + 4];
                uint32_t a3 = Qs[rowB * PADQ + k * 8 + t + 4];
#pragma unroll
                for (int n = 0; n < 8; n++) {
                    uint32_t b0 = Ks[((nb0 + n) * 8 + g) * PADQ + k * 8 + t];
                    uint32_t b1 = Ks[((nb0 + n) * 8 + g) * PADQ + k * 8 + t + 4];
                    mma_tf32(sc[n], a0, a1, a2, a3, b0, b1);
                }
            }

            // ---- Taylor weights + mask + denominators (in place) ----
#pragma unroll
            for (int n = 0; n < 8; n++) {
                int kc = (nb0 + n) * 8 + 2 * t;
                float m0 = mk[kc], m1 = mk[kc + 1];
                float s0 = sc[n][0] * 0.125f, s1 = sc[n][1] * 0.125f;
                float s2 = sc[n][2] * 0.125f, s3 = sc[n][3] * 0.125f;
                float w0 = fmaf(s0, fmaf(0.5f, s0, 1.0f), 1.0f) * m0;
                float w1 = fmaf(s1, fmaf(0.5f, s1, 1.0f), 1.0f) * m1;
                float w2 = fmaf(s2, fmaf(0.5f, s2, 1.0f), 1.0f) * m0;
                float w3 = fmaf(s3, fmaf(0.5f, s3, 1.0f), 1.0f) * m1;
                den0 += w0 + w1;
                den1 += w2 + w3;
                sc[n][0] = w0; sc[n][1] = w1; sc[n][2] = w2; sc[n][3] = w3;
            }

            // ---- MMA2: O += W @ V, W frags built via quad shfl ----
#pragma unroll
            for (int n = 0; n < 8; n++) {
                float u0 = __shfl_sync(0xffffffffu, sc[n][0], srcL);
                float u1 = __shfl_sync(0xffffffffu, sc[n][1], srcL);
                float v0 = __shfl_sync(0xffffffffu, sc[n][2], srcL);
                float v1 = __shfl_sync(0xffffffffu, sc[n][3], srcL);
                float x0 = __shfl_sync(0xffffffffu, sc[n][0], srcH);
                float x1 = __shfl_sync(0xffffffffu, sc[n][1], srcH);
                float y0 = __shfl_sync(0xffffffffu, sc[n][2], srcH);
                float y1 = __shfl_sync(0xffffffffu, sc[n][3], srcH);
                uint32_t a0 = f2tf32(odd ? u1 : u0);
                uint32_t a1 = f2tf32(odd ? v1 : v0);
                uint32_t a2 = f2tf32(odd ? x1 : x0);
                uint32_t a3 = f2tf32(odd ? y1 : y0);
                const int kb = (nb0 + n) * 8;
#pragma unroll
                for (int dn = 0; dn < 8; dn++) {
                    uint32_t b0 = Vt[(dn * 8 + g) * PADV + kb + t];
                    uint32_t b1 = Vt[(dn * 8 + g) * PADV + kb + t + 4];
                    mma_tf32(outr[dn], a0, a1, a2, a3, b0, b1);
                }
            }
        }
    }

    // ---- quad-reduce denominators ----
    den0 += __shfl_xor_sync(0xffffffffu, den0, 1);
    den0 += __shfl_xor_sync(0xffffffffu, den0, 2);
    den1 += __shfl_xor_sync(0xffffffffu, den1, 1);
    den1 += __shfl_xor_sync(0xffffffffu, den1, 2);
    float inv0 = 1.0f / den0;
    float inv1 = 1.0f / den1;

    // ---- normalize + store ----
    {
        float* dA = &outp[(size_t)(prow0 + qt * 128 + rowA) * DIM + h * 64];
        float* dB = &outp[(size_t)(prow0 + qt * 128 + rowB) * DIM + h * 64];
#pragma unroll
        for (int n = 0; n < 8; n++) {
            int c = n * 8 + 2 * t;
            *(float2*)(dA + c) = make_float2(outr[n][0] * inv0, outr[n][1] * inv0);
            *(float2*)(dB + c) = make_float2(outr[n][2] * inv1, outr[n][3] * inv1);
        }
    }
}

// ---------------- launch ----------------
extern "C" void kernel_launch(void* const* d_in, const int* in_sizes, int n_in,
                              void* d_out, int out_size)
{
    const float*         x    = (const float*)d_in[0];
    const unsigned char* mask = (const unsigned char*)d_in[1];
    const float*         rot  = (const float*)d_in[2];
    const float*         Wt   = (const float*)d_in[3];
    const float*         Wo   = (const float*)d_in[4];
    float*               out  = (float*)d_out;

    float *qkv_p, *att_p;
    cudaGetSymbolAddress((void**)&qkv_p, g_qkv);
    cudaGetSymbolAddress((void**)&att_p, g_att);

    static const int ATT_SMEM = ATT_WORDS * (int)sizeof(uint32_t);  // 103,936 B
    cudaFuncSetAttribute(attn_mma_kernel, cudaFuncAttributeMaxDynamicSharedMemorySize, ATT_SMEM);

    convert_mask_kernel<<<1, 256>>>(mask);

    // qkv = x @ W_trans^T : [4096,512] @ [1536,512]^T
    gemm_tf32_kernel<<<dim3(ROWQ / 128, NP / 128), 256>>>(x, Wt, qkv_p, NP, ROWQ, DIM);

    // rotate q,k heads where masked
    rotate_kernel<<<NP, 256>>>(rot);

    // attention (mma.sync tf32) -> g_att
    attn_mma_kernel<<<dim3(SS / 128, BB * NH), 256, ATT_SMEM>>>(att_p);

    // out = att @ W_o^T : [4096,512] @ [512,512]^T
    gemm_tf32_kernel<<<dim3(DIM / 128, NP / 128), 256>>>(att_p, Wo, out, NP, DIM, DIM);
}

// round 5
// speedup vs baseline: 2.7290x; 1.1197x over previous
#include <cuda_runtime.h>
#include <cuda_bf16.h>
#include <cstdint>

// Problem constants
#define BB   2
#define SS   2048
#define DIM  512
#define NH   8
#define HD   64
#define QK   512          // NH*HD
#define ROWQ 1536         // 2*QK + DIM
#define NP   4096         // B*S positions

// ---------------- scratch ----------------
__device__ float g_qkv[NP * ROWQ];
__device__ float g_att[NP * DIM];
__device__ float g_mask[NP];
__device__ float g_x[NP * DIM];        // pre-rounded x
__device__ float g_wt[ROWQ * DIM];     // pre-rounded W_trans
__device__ float g_wo[DIM * DIM];      // pre-rounded W_o

// ---------------- helpers ----------------
__device__ __forceinline__ uint32_t f2tf32(float f) {
    uint32_t r; asm("cvt.rn.tf32.f32 %0, %1;" : "=r"(r) : "f"(f)); return r;
}
__device__ __forceinline__ float rtf(float f) { return __uint_as_float(f2tf32(f)); }

__device__ __forceinline__ void mma_tf32(float* c,
    uint32_t a0, uint32_t a1, uint32_t a2, uint32_t a3, uint32_t b0, uint32_t b1)
{
    asm volatile(
        "mma.sync.aligned.m16n8k8.row.col.f32.tf32.tf32.f32 "
        "{%0,%1,%2,%3}, {%4,%5,%6,%7}, {%8,%9}, {%0,%1,%2,%3};"
        : "+f"(c[0]), "+f"(c[1]), "+f"(c[2]), "+f"(c[3])
        : "r"(a0), "r"(a1), "r"(a2), "r"(a3), "r"(b0), "r"(b1));
}

// ---------------- mask sniff ----------------
__global__ void convert_mask_kernel(const unsigned char* __restrict__ raw) {
    __shared__ int typ_s;
    if (threadIdx.x == 0) {
        int t = 1;
        for (int i = 0; i < 512; i++) {
            unsigned char b = raw[i];
            if ((i & 3) != 0 && b != 0) { t = (b == 0x3f || b == 0x80) ? 2 : 0; break; }
        }
        typ_s = t;
    }
    __syncthreads();
    int t = typ_s;
    for (int i = threadIdx.x; i < NP; i += blockDim.x) {
        float m;
        if (t == 0)      m = raw[i] ? 1.0f : 0.0f;
        else if (t == 1) m = (((const int*)raw)[i] != 0) ? 1.0f : 0.0f;
        else             m = (((const float*)raw)[i] != 0.0f) ? 1.0f : 0.0f;
        g_mask[i] = m;
    }
}

// ---------------- pre-round to tf32 ----------------
__global__ void round_kernel(const float4* __restrict__ src, float4* __restrict__ dst, int n4) {
    int i = blockIdx.x * blockDim.x + threadIdx.x;
    if (i < n4) {
        float4 v = src[i];
        dst[i] = make_float4(rtf(v.x), rtf(v.y), rtf(v.z), rtf(v.w));
    }
}

// ---------------- tf32 mma GEMM  C = A @ B^T  (pre-rounded inputs) ----------------
// A:[M,K] rm, B:[N,K] rm, both already tf32-rounded. CTA 128x128, BK=32.
__global__ void __launch_bounds__(256, 2) gemm_tf32_kernel(
    const float* __restrict__ A, const float* __restrict__ Bm,
    float* __restrict__ C, int M, int N, int K)
{
    __shared__ uint32_t As[128 * 36];
    __shared__ uint32_t Bs[128 * 36];

    const int tid = threadIdx.x;
    const int w = tid >> 5, lane = tid & 31;
    const int g = lane >> 2, t = lane & 3;
    const int wm = w >> 2, wn = w & 3;
    const int bm = blockIdx.y, bn = blockIdx.x;

    const int r = tid >> 1, seg = (tid & 1) * 16;
    const uint4* gA = (const uint4*)(A + (size_t)(bm * 128 + r) * K + seg);
    const uint4* gB = (const uint4*)(Bm + (size_t)(bn * 128 + r) * K + seg);

    uint4 pa[4], pb[4];
#pragma unroll
    for (int i = 0; i < 4; i++) { pa[i] = gA[i]; pb[i] = gB[i]; }

    float acc[4][4][4];
#pragma unroll
    for (int mf = 0; mf < 4; mf++)
#pragma unroll
        for (int nf = 0; nf < 4; nf++)
#pragma unroll
            for (int c = 0; c < 4; c++) acc[mf][nf][c] = 0.0f;

    const int nch = K >> 5;
    for (int ch = 0; ch < nch; ch++) {
        if (ch) __syncthreads();
#pragma unroll
        for (int i = 0; i < 4; i++) {
            *(uint4*)&As[r * 36 + seg + 4 * i] = pa[i];
            *(uint4*)&Bs[r * 36 + seg + 4 * i] = pb[i];
        }
        __syncthreads();
        if (ch + 1 < nch) {
#pragma unroll
            for (int i = 0; i < 4; i++) {
                pa[i] = gA[(ch + 1) * 8 + i];
                pb[i] = gB[(ch + 1) * 8 + i];
            }
        }
#pragma unroll
        for (int k8 = 0; k8 < 4; k8++) {
            uint32_t a[4][4];
#pragma unroll
            for (int mf = 0; mf < 4; mf++) {
                int rm = wm * 64 + mf * 16;
                a[mf][0] = As[(rm + g) * 36 + k8 * 8 + t];
                a[mf][1] = As[(rm + g + 8) * 36 + k8 * 8 + t];
                a[mf][2] = As[(rm + g) * 36 + k8 * 8 + t + 4];
                a[mf][3] = As[(rm + g + 8) * 36 + k8 * 8 + t + 4];
            }
#pragma unroll
            for (int nf = 0; nf < 4; nf++) {
                int rn = wn * 32 + nf * 8;
                uint32_t b0 = Bs[(rn + g) * 36 + k8 * 8 + t];
                uint32_t b1 = Bs[(rn + g) * 36 + k8 * 8 + t + 4];
#pragma unroll
                for (int mf = 0; mf < 4; mf++)
                    mma_tf32(acc[mf][nf], a[mf][0], a[mf][1], a[mf][2], a[mf][3], b0, b1);
            }
        }
    }

#pragma unroll
    for (int mf = 0; mf < 4; mf++) {
        int row = bm * 128 + wm * 64 + mf * 16 + g;
#pragma unroll
        for (int nf = 0; nf < 4; nf++) {
            int col = bn * 128 + wn * 32 + nf * 8 + 2 * t;
            *(float2*)&C[(size_t)row * N + col]       = make_float2(acc[mf][nf][0], acc[mf][nf][1]);
            *(float2*)&C[(size_t)(row + 8) * N + col] = make_float2(acc[mf][nf][2], acc[mf][nf][3]);
        }
    }
}

// ---------------- rotation + tf32 rounding of q,k,v ----------------
__global__ void __launch_bounds__(256) rotate_kernel(const float* __restrict__ rot)
{
    const int p = blockIdx.x;
    const int tid = threadIdx.x;
    float* row = &g_qkv[(size_t)p * ROWQ];

    if (g_mask[p] != 0.0f) {
        __shared__ float Rt[64 * 65];
        __shared__ float X[1024];
        const float* R = rot + (size_t)p * 4096;
#pragma unroll
        for (int t = 0; t < 16; t++) {
            int idx = tid + 256 * t;
            int i = idx >> 6, j = idx & 63;
            Rt[j * 65 + i] = R[idx];
        }
#pragma unroll
        for (int t = 0; t < 4; t++) {
            int idx = tid + 256 * t;
            X[idx] = row[idx];
        }
        __syncthreads();

        const int i  = tid & 63;
        const int vb = tid >> 6;
#pragma unroll
        for (int ii = 0; ii < 4; ii++) {
            int v = vb + 4 * ii;
            float acc = 0.0f;
#pragma unroll 8
            for (int j = 0; j < 64; j++)
                acc = fmaf(Rt[j * 65 + i], X[v * 64 + j], acc);
            row[v * 64 + i] = rtf(acc);
        }
    } else {
#pragma unroll
        for (int t = 0; t < 4; t++) {
            int idx = tid + 256 * t;
            row[idx] = rtf(row[idx]);
        }
    }
    // round v columns [1024, 1536)
#pragma unroll
    for (int t = 0; t < 2; t++) {
        int idx = 1024 + tid + 256 * t;
        row[idx] = rtf(row[idx]);
    }
}

// ---------------- mma.sync tf32 Taylor attention ----------------
// grid (16 qtiles, 16 bh), 256 threads = 8 warps. 2 CTAs/SM.
// Inputs pre-rounded to tf32 -> zero CVT in the load path.
// K/V staged in fragment order: block stride 66 words, one LDS.64 per B-frag.

#define ATT_WORDS (2 * 8448 + 128)

__global__ void __launch_bounds__(256, 2) attn_mma_kernel(float* __restrict__ outp)
{
    extern __shared__ uint32_t sm[];
    uint32_t* Kf = sm;                  // 128 blocks (n8*8+k8) x 66
    uint32_t* Vf = sm + 8448;           // 128 blocks (kb*8+dn) x 66
    float*    mk = (float*)(sm + 16896);

    const int tid = threadIdx.x;
    const int w = tid >> 5, lane = tid & 31;
    const int g = lane >> 2, t = lane & 3;
    const int qt = blockIdx.x, bh = blockIdx.y;
    const int b = bh >> 3, h = bh & 7;
    const int prow0 = b * SS;
    const int r = tid >> 1, hf = tid & 1;

    // ---- Q fragments in registers (pre-rounded bits, direct from gmem) ----
    uint32_t qa[8][4];
    {
        const float* qA = &g_qkv[(size_t)(prow0 + qt * 128 + w * 16 + g) * ROWQ + h * 64];
        const float* qB = qA + 8 * ROWQ;
#pragma unroll
        for (int k8 = 0; k8 < 8; k8++) {
            qa[k8][0] = __float_as_uint(qA[k8 * 8 + t]);
            qa[k8][1] = __float_as_uint(qB[k8 * 8 + t]);
            qa[k8][2] = __float_as_uint(qA[k8 * 8 + t + 4]);
            qa[k8][3] = __float_as_uint(qB[k8 * 8 + t + 4]);
        }
    }

    float outr[8][4];
#pragma unroll
    for (int n = 0; n < 8; n++)
#pragma unroll
        for (int j = 0; j < 4; j++) outr[n][j] = 0.0f;
    float den0 = 0.0f, den1 = 0.0f;

    const int srcL = (lane & ~3) | (t >> 1);
    const int srcH = srcL + 2;
    const bool odd = (t & 1);

    for (int kt = 0; kt < 16; kt++) {
        __syncthreads();   // previous iter reads done before overwrite

        // ---- stage K and V tiles into fragment-order smem ----
        {
            const size_t grow = (size_t)(prow0 + kt * 128 + r) * ROWQ;
            const uint4* ks4 = (const uint4*)&g_qkv[grow + QK + h * 64 + hf * 32];
            const uint4* vs4 = (const uint4*)&g_qkv[grow + 2 * QK + h * 64 + hf * 32];
            uint32_t pk[32], pv[32];
#pragma unroll
            for (int i = 0; i < 8; i++) {
                uint4 a = ks4[i];
                pk[4 * i] = a.x; pk[4 * i + 1] = a.y; pk[4 * i + 2] = a.z; pk[4 * i + 3] = a.w;
                uint4 c = vs4[i];
                pv[4 * i] = c.x; pv[4 * i + 1] = c.y; pv[4 * i + 2] = c.z; pv[4 * i + 3] = c.w;
            }
            // K: block (n8*8 + k8)*66, word 8g+2t holds {K[n8*8+g][k8*8+t], [..t+4]}
            const int n8 = r >> 3, gk = r & 7;
#pragma unroll
            for (int k8p = 0; k8p < 4; k8p++) {
                uint32_t base = (uint32_t)((n8 * 8 + 4 * hf + k8p) * 66 + gk * 8);
#pragma unroll
                for (int t2 = 0; t2 < 4; t2++)
                    *(uint2*)&Kf[base + 2 * t2] = make_uint2(pk[k8p * 8 + t2], pk[k8p * 8 + t2 + 4]);
            }
            // V: block (kb*8 + dn)*66, word 8(d&7)+2(rl&3)+(rl>>2) holds V[key][d]
            const int kb = r >> 3, rl = r & 7;
            const int vlow = 2 * (rl & 3) + (rl >> 2);
#pragma unroll
            for (int l = 0; l < 32; l++) {
                int dn = 4 * hf + (l >> 3);
                Vf[(kb * 8 + dn) * 66 + (l & 7) * 8 + vlow] = pv[l];
            }
            if (tid < 128) mk[tid] = g_mask[prow0 + kt * 128 + tid];
        }
        __syncthreads();

#pragma unroll
        for (int h2 = 0; h2 < 2; h2++) {
            const int nb0 = h2 * 8;

            // ---- MMA1: S = Q @ K^T (B-frags: one LDS.64 each) ----
            float sc[8][4];
#pragma unroll
            for (int n = 0; n < 8; n++)
#pragma unroll
                for (int j = 0; j < 4; j++) sc[n][j] = 0.0f;

#pragma unroll
            for (int k8 = 0; k8 < 8; k8++) {
#pragma unroll
                for (int n = 0; n < 8; n++) {
                    uint2 kf = *(const uint2*)&Kf[((nb0 + n) * 8 + k8) * 66 + 2 * lane];
                    mma_tf32(sc[n], qa[k8][0], qa[k8][1], qa[k8][2], qa[k8][3], kf.x, kf.y);
                }
            }

            // ---- Taylor weights + mask + denominators ----
#pragma unroll
            for (int n = 0; n < 8; n++) {
                int kc = (nb0 + n) * 8 + 2 * t;
                float m0 = mk[kc], m1 = mk[kc + 1];
                float s0 = sc[n][0] * 0.125f, s1 = sc[n][1] * 0.125f;
                float s2 = sc[n][2] * 0.125f, s3 = sc[n][3] * 0.125f;
                float w0 = fmaf(s0, fmaf(0.5f, s0, 1.0f), 1.0f) * m0;
                float w1 = fmaf(s1, fmaf(0.5f, s1, 1.0f), 1.0f) * m1;
                float w2 = fmaf(s2, fmaf(0.5f, s2, 1.0f), 1.0f) * m0;
                float w3 = fmaf(s3, fmaf(0.5f, s3, 1.0f), 1.0f) * m1;
                den0 += w0 + w1;
                den1 += w2 + w3;
                sc[n][0] = w0; sc[n][1] = w1; sc[n][2] = w2; sc[n][3] = w3;
            }

            // ---- MMA2: O += W @ V (A via quad shfl, B: one LDS.64 each) ----
#pragma unroll
            for (int n = 0; n < 8; n++) {
                float u0 = __shfl_sync(0xffffffffu, sc[n][0], srcL);
                float u1 = __shfl_sync(0xffffffffu, sc[n][1], srcL);
                float v0 = __shfl_sync(0xffffffffu, sc[n][2], srcL);
                float v1 = __shfl_sync(0xffffffffu, sc[n][3], srcL);
                float x0 = __shfl_sync(0xffffffffu, sc[n][0], srcH);
                float x1 = __shfl_sync(0xffffffffu, sc[n][1], srcH);
                float y0 = __shfl_sync(0xffffffffu, sc[n][2], srcH);
                float y1 = __shfl_sync(0xffffffffu, sc[n][3], srcH);
                uint32_t a0 = f2tf32(odd ? u1 : u0);
                uint32_t a1 = f2tf32(odd ? v1 : v0);
                uint32_t a2 = f2tf32(odd ? x1 : x0);
                uint32_t a3 = f2tf32(odd ? y1 : y0);
#pragma unroll
                for (int dn = 0; dn < 8; dn++) {
                    uint2 vf = *(const uint2*)&Vf[((nb0 + n) * 8 + dn) * 66 + 2 * lane];
                    mma_tf32(outr[dn], a0, a1, a2, a3, vf.x, vf.y);
                }
            }
        }
    }

    // ---- quad-reduce denominators ----
    den0 += __shfl_xor_sync(0xffffffffu, den0, 1);
    den0 += __shfl_xor_sync(0xffffffffu, den0, 2);
    den1 += __shfl_xor_sync(0xffffffffu, den1, 1);
    den1 += __shfl_xor_sync(0xffffffffu, den1, 2);
    float inv0 = 1.0f / den0;
    float inv1 = 1.0f / den1;

    // ---- normalize + tf32-round + store (gemm2 reads raw bits) ----
    {
        const int rowA = w * 16 + g;
        float* dA = &outp[(size_t)(prow0 + qt * 128 + rowA) * DIM + h * 64];
        float* dB = dA + 8 * DIM;
#pragma unroll
        for (int n = 0; n < 8; n++) {
            int c = n * 8 + 2 * t;
            *(float2*)(dA + c) = make_float2(rtf(outr[n][0] * inv0), rtf(outr[n][1] * inv0));
            *(float2*)(dB + c) = make_float2(rtf(outr[n][2] * inv1), rtf(outr[n][3] * inv1));
        }
    }
}

// ---------------- launch ----------------
extern "C" void kernel_launch(void* const* d_in, const int* in_sizes, int n_in,
                              void* d_out, int out_size)
{
    const float*         x    = (const float*)d_in[0];
    const unsigned char* mask = (const unsigned char*)d_in[1];
    const float*         rot  = (const float*)d_in[2];
    const float*         Wt   = (const float*)d_in[3];
    const float*         Wo   = (const float*)d_in[4];
    float*               out  = (float*)d_out;

    float *qkv_p, *att_p, *x_p, *wt_p, *wo_p;
    cudaGetSymbolAddress((void**)&qkv_p, g_qkv);
    cudaGetSymbolAddress((void**)&att_p, g_att);
    cudaGetSymbolAddress((void**)&x_p,  g_x);
    cudaGetSymbolAddress((void**)&wt_p, g_wt);
    cudaGetSymbolAddress((void**)&wo_p, g_wo);

    static const int ATT_SMEM = ATT_WORDS * (int)sizeof(uint32_t);  // 68,096 B
    cudaFuncSetAttribute(attn_mma_kernel, cudaFuncAttributeMaxDynamicSharedMemorySize, ATT_SMEM);

    convert_mask_kernel<<<1, 256>>>(mask);

    // pre-round inputs to tf32
    round_kernel<<<(NP * DIM / 4 + 255) / 256, 256>>>((const float4*)x, (float4*)x_p, NP * DIM / 4);
    round_kernel<<<(ROWQ * DIM / 4 + 255) / 256, 256>>>((const float4*)Wt, (float4*)wt_p, ROWQ * DIM / 4);
    round_kernel<<<(DIM * DIM / 4 + 255) / 256, 256>>>((const float4*)Wo, (float4*)wo_p, DIM * DIM / 4);

    // qkv = x @ W_trans^T
    gemm_tf32_kernel<<<dim3(ROWQ / 128, NP / 128), 256>>>(x_p, wt_p, qkv_p, NP, ROWQ, DIM);

    // rotate q,k where masked; round q,k,v to tf32
    rotate_kernel<<<NP, 256>>>(rot);

    // attention (mma.sync tf32) -> g_att (tf32-rounded)
    attn_mma_kernel<<<dim3(SS / 128, BB * NH), 256, ATT_SMEM>>>(att_p);

    // out = att @ W_o^T
    gemm_tf32_kernel<<<dim3(DIM / 128, NP / 128), 256>>>(att_p, wo_p, out, NP, DIM, DIM);
}

// round 6
// speedup vs baseline: 3.0414x; 1.1145x over previous
#include <cuda_runtime.h>
#include <cuda_bf16.h>
#include <cstdint>

// Problem constants
#define BB   2
#define SS   2048
#define DIM  512
#define NH   8
#define HD   64
#define QK   512          // NH*HD
#define ROWQ 1536         // 2*QK + DIM
#define NP   4096         // B*S positions

// ---------------- scratch ----------------
__device__ float g_qkv[NP * ROWQ];     // natural layout (q used by attn, k/v by rotate)
__device__ float g_att[NP * DIM];
__device__ float g_mask[NP];
__device__ float g_x[NP * DIM];        // pre-rounded x
__device__ float g_wt[ROWQ * DIM];     // pre-rounded W_trans
__device__ float g_wo[DIM * DIM];      // pre-rounded W_o
// fragment-ordered K/V: [bh][stage][block 0..63][word 0..63]
__device__ float g_kf[16 * 32 * 64 * 64];
__device__ float g_vf[16 * 32 * 64 * 64];

// ---------------- helpers ----------------
__device__ __forceinline__ uint32_t f2tf32(float f) {
    uint32_t r; asm("cvt.rn.tf32.f32 %0, %1;" : "=r"(r) : "f"(f)); return r;
}
__device__ __forceinline__ float rtf(float f) { return __uint_as_float(f2tf32(f)); }

__device__ __forceinline__ uint32_t smem_u32(const void* p) {
    uint32_t a;
    asm("{ .reg .u64 t; cvta.to.shared.u64 t, %1; cvt.u32.u64 %0, t; }" : "=r"(a) : "l"(p));
    return a;
}
__device__ __forceinline__ void cp16(uint32_t dst, const void* src) {
    asm volatile("cp.async.ca.shared.global [%0], [%1], 16;" :: "r"(dst), "l"(src) : "memory");
}
#define CP_COMMIT() asm volatile("cp.async.commit_group;" ::: "memory")
#define CP_WAIT0()  asm volatile("cp.async.wait_group 0;" ::: "memory")

__device__ __forceinline__ void mma_tf32(float* c,
    uint32_t a0, uint32_t a1, uint32_t a2, uint32_t a3, uint32_t b0, uint32_t b1)
{
    asm volatile(
        "mma.sync.aligned.m16n8k8.row.col.f32.tf32.tf32.f32 "
        "{%0,%1,%2,%3}, {%4,%5,%6,%7}, {%8,%9}, {%0,%1,%2,%3};"
        : "+f"(c[0]), "+f"(c[1]), "+f"(c[2]), "+f"(c[3])
        : "r"(a0), "r"(a1), "r"(a2), "r"(a3), "r"(b0), "r"(b1));
}

// permuted K index: element K[b,h][key][d]
__device__ __forceinline__ size_t kf_off(int b, int h, int key, int d) {
    int stage = key >> 6, n8 = (key >> 3) & 7, g = key & 7;
    return ((size_t)(((b * 8 + h) * 32 + stage) * 64 + n8 * 8 + (d >> 3))) * 64
           + 8 * g + 2 * (d & 3) + ((d & 7) >> 2);
}
// permuted V index: element V[b,h][key][d]
__device__ __forceinline__ size_t vf_off(int b, int h, int key, int d) {
    int stage = key >> 6, kb = (key >> 3) & 7;
    return ((size_t)(((b * 8 + h) * 32 + stage) * 64 + kb * 8 + (d >> 3))) * 64
           + 8 * (d & 7) + 2 * (key & 3) + ((key & 7) >> 2);
}

// ---------------- mask sniff ----------------
__global__ void convert_mask_kernel(const unsigned char* __restrict__ raw) {
    __shared__ int typ_s;
    if (threadIdx.x == 0) {
        int t = 1;
        for (int i = 0; i < 512; i++) {
            unsigned char b = raw[i];
            if ((i & 3) != 0 && b != 0) { t = (b == 0x3f || b == 0x80) ? 2 : 0; break; }
        }
        typ_s = t;
    }
    __syncthreads();
    int t = typ_s;
    for (int i = threadIdx.x; i < NP; i += blockDim.x) {
        float m;
        if (t == 0)      m = raw[i] ? 1.0f : 0.0f;
        else if (t == 1) m = (((const int*)raw)[i] != 0) ? 1.0f : 0.0f;
        else             m = (((const float*)raw)[i] != 0.0f) ? 1.0f : 0.0f;
        g_mask[i] = m;
    }
}

// ---------------- pre-round to tf32 ----------------
__global__ void round_kernel(const float4* __restrict__ src, float4* __restrict__ dst, int n4) {
    int i = blockIdx.x * blockDim.x + threadIdx.x;
    if (i < n4) {
        float4 v = src[i];
        dst[i] = make_float4(rtf(v.x), rtf(v.y), rtf(v.z), rtf(v.w));
    }
}

// ---------------- tf32 mma GEMM  C = A @ B^T  (pre-rounded inputs) ----------------
__global__ void __launch_bounds__(256, 2) gemm_tf32_kernel(
    const float* __restrict__ A, const float* __restrict__ Bm,
    float* __restrict__ C, int M, int N, int K)
{
    __shared__ uint32_t As[128 * 36];
    __shared__ uint32_t Bs[128 * 36];

    const int tid = threadIdx.x;
    const int w = tid >> 5, lane = tid & 31;
    const int g = lane >> 2, t = lane & 3;
    const int wm = w >> 2, wn = w & 3;
    const int bm = blockIdx.y, bn = blockIdx.x;

    const int r = tid >> 1, seg = (tid & 1) * 16;
    const uint4* gA = (const uint4*)(A + (size_t)(bm * 128 + r) * K + seg);
    const uint4* gB = (const uint4*)(Bm + (size_t)(bn * 128 + r) * K + seg);

    uint4 pa[4], pb[4];
#pragma unroll
    for (int i = 0; i < 4; i++) { pa[i] = gA[i]; pb[i] = gB[i]; }

    float acc[4][4][4];
#pragma unroll
    for (int mf = 0; mf < 4; mf++)
#pragma unroll
        for (int nf = 0; nf < 4; nf++)
#pragma unroll
            for (int c = 0; c < 4; c++) acc[mf][nf][c] = 0.0f;

    const int nch = K >> 5;
    for (int ch = 0; ch < nch; ch++) {
        if (ch) __syncthreads();
#pragma unroll
        for (int i = 0; i < 4; i++) {
            *(uint4*)&As[r * 36 + seg + 4 * i] = pa[i];
            *(uint4*)&Bs[r * 36 + seg + 4 * i] = pb[i];
        }
        __syncthreads();
        if (ch + 1 < nch) {
#pragma unroll
            for (int i = 0; i < 4; i++) {
                pa[i] = gA[(ch + 1) * 8 + i];
                pb[i] = gB[(ch + 1) * 8 + i];
            }
        }
#pragma unroll
        for (int k8 = 0; k8 < 4; k8++) {
            uint32_t a[4][4];
#pragma unroll
            for (int mf = 0; mf < 4; mf++) {
                int rm = wm * 64 + mf * 16;
                a[mf][0] = As[(rm + g) * 36 + k8 * 8 + t];
                a[mf][1] = As[(rm + g + 8) * 36 + k8 * 8 + t];
                a[mf][2] = As[(rm + g) * 36 + k8 * 8 + t + 4];
                a[mf][3] = As[(rm + g + 8) * 36 + k8 * 8 + t + 4];
            }
#pragma unroll
            for (int nf = 0; nf < 4; nf++) {
                int rn = wn * 32 + nf * 8;
                uint32_t b0 = Bs[(rn + g) * 36 + k8 * 8 + t];
                uint32_t b1 = Bs[(rn + g) * 36 + k8 * 8 + t + 4];
#pragma unroll
                for (int mf = 0; mf < 4; mf++)
                    mma_tf32(acc[mf][nf], a[mf][0], a[mf][1], a[mf][2], a[mf][3], b0, b1);
            }
        }
    }

#pragma unroll
    for (int mf = 0; mf < 4; mf++) {
        int row = bm * 128 + wm * 64 + mf * 16 + g;
#pragma unroll
        for (int nf = 0; nf < 4; nf++) {
            int col = bn * 128 + wn * 32 + nf * 8 + 2 * t;
            *(float2*)&C[(size_t)row * N + col]       = make_float2(acc[mf][nf][0], acc[mf][nf][1]);
            *(float2*)&C[(size_t)(row + 8) * N + col] = make_float2(acc[mf][nf][2], acc[mf][nf][3]);
        }
    }
}

// ---------------- rotation + tf32 rounding + permuted K/V emission ----------------
__global__ void __launch_bounds__(256) rotate_kernel(const float* __restrict__ rot)
{
    const int p = blockIdx.x, tid = threadIdx.x;
    const int b = p >> 11, s = p & 2047;
    float* row = &g_qkv[(size_t)p * ROWQ];
    const bool masked = (g_mask[p] != 0.0f);

    if (masked) {
        __shared__ float Rt[64 * 65];
        __shared__ float X[1024];
        const float* R = rot + (size_t)p * 4096;
#pragma unroll
        for (int t2 = 0; t2 < 16; t2++) {
            int idx = tid + 256 * t2;
            int i = idx >> 6, j = idx & 63;
            Rt[j * 65 + i] = R[idx];
        }
#pragma unroll
        for (int t2 = 0; t2 < 4; t2++) {
            int idx = tid + 256 * t2;
            X[idx] = row[idx];
        }
        __syncthreads();

        const int i  = tid & 63;
        const int vb = tid >> 6;
#pragma unroll
        for (int ii = 0; ii < 4; ii++) {
            int v = vb + 4 * ii;
            float acc = 0.0f;
#pragma unroll 8
            for (int j = 0; j < 64; j++)
                acc = fmaf(Rt[j * 65 + i], X[v * 64 + j], acc);
            float rv = rtf(acc);
            if (v < 8) row[v * 64 + i] = rv;            // q natural
            else       g_kf[kf_off(b, v - 8, s, i)] = rv;  // k permuted
        }
    } else {
#pragma unroll
        for (int t2 = 0; t2 < 4; t2++) {
            int idx = tid + 256 * t2;     // 0..1023
            float rv = rtf(row[idx]);
            if (idx < 512) row[idx] = rv;
            else g_kf[kf_off(b, (idx - 512) >> 6, s, idx & 63)] = rv;
        }
    }
    // v: round + permuted store (both branches)
#pragma unroll
    for (int t2 = 0; t2 < 2; t2++) {
        int idx = tid + 256 * t2;         // 0..511
        float rv = rtf(row[1024 + idx]);
        g_vf[vf_off(b, idx >> 6, s, idx & 63)] = rv;
    }
}

// ---------------- cp.async double-buffered mma.sync tf32 Taylor attention ------
// grid (16 qtiles, 16 bh), 256 threads = 8 warps, 2 CTAs/SM.
// 32 stages of 64 keys; K/V arrive via cp.async already in fragment order.

#define STG_K   (64 * 68)                 // words
#define STG_V   (64 * 68)
#define STG_WORDS (STG_K + STG_V + 64)    // + 64 mask floats = 8768
#define ATT_WORDS (2 * STG_WORDS)         // 17536 words = 70144 B

__global__ void __launch_bounds__(256, 2) attn_mma_kernel(float* __restrict__ outp)
{
    extern __shared__ uint32_t sm[];
    const uint32_t sbase = smem_u32(sm);

    const int tid = threadIdx.x;
    const int w = tid >> 5, lane = tid & 31;
    const int g = lane >> 2, t = lane & 3;
    const int qt = blockIdx.x, bh = blockIdx.y;
    const int b = bh >> 3, h = bh & 7;
    const int prow0 = b * SS;

    // ---- Q fragments in registers (pre-rounded, natural layout) ----
    uint32_t qa[8][4];
    {
        const float* qA = &g_qkv[(size_t)(prow0 + qt * 128 + w * 16 + g) * ROWQ + h * 64];
        const float* qB = qA + 8 * ROWQ;
#pragma unroll
        for (int k8 = 0; k8 < 8; k8++) {
            qa[k8][0] = __float_as_uint(qA[k8 * 8 + t]);
            qa[k8][1] = __float_as_uint(qB[k8 * 8 + t]);
            qa[k8][2] = __float_as_uint(qA[k8 * 8 + t + 4]);
            qa[k8][3] = __float_as_uint(qB[k8 * 8 + t + 4]);
        }
    }

    // stage copy: thread copies 4 K chunks + 4 V chunks (+ mask for tid<16)
    const float* kbase = &g_kf[(size_t)(bh * 32) * 4096];
    const float* vbase = &g_vf[(size_t)(bh * 32) * 4096];
    const float* mbase = &g_mask[b * SS];

    auto issue_stage = [&](int s) {
        const uint32_t dstb = sbase + (uint32_t)((s & 1) * STG_WORDS * 4);
        const char* ksrc = (const char*)(kbase + (size_t)s * 4096);
        const char* vsrc = (const char*)(vbase + (size_t)s * 4096);
#pragma unroll
        for (int c = 0; c < 4; c++) {
            int ch = tid * 4 + c;                 // 0..1023
            int ib = ch >> 4, off = ch & 15;
            uint32_t d = (uint32_t)(ib * 272 + off * 16);
            cp16(dstb + d, ksrc + ch * 16);
            cp16(dstb + (uint32_t)(STG_K * 4) + d, vsrc + ch * 16);
        }
        if (tid < 16)
            cp16(dstb + (uint32_t)((STG_K + STG_V) * 4 + tid * 16),
                 (const char*)(mbase + s * 64 + tid * 4));
        CP_COMMIT();
    };

    float outr[8][4];
#pragma unroll
    for (int n = 0; n < 8; n++)
#pragma unroll
        for (int j = 0; j < 4; j++) outr[n][j] = 0.0f;
    float den0 = 0.0f, den1 = 0.0f;

    const int srcL = (lane & ~3) | (t >> 1);
    const int srcH = srcL + 2;
    const bool odd = (t & 1);

    issue_stage(0);

    for (int s = 0; s < 32; s++) {
        CP_WAIT0();
        __syncthreads();          // stage s data visible; all warps done with stage s-1 buffer
        if (s + 1 < 32) issue_stage(s + 1);

        uint32_t* Kf = sm + (s & 1) * STG_WORDS;
        uint32_t* Vf = Kf + STG_K;
        const float* mk = (const float*)(Vf + STG_V);

        // ---- MMA1: S[16 q, 64 keys] = Q @ K^T ----
        float sc[8][4];
#pragma unroll
        for (int n = 0; n < 8; n++)
#pragma unroll
            for (int j = 0; j < 4; j++) sc[n][j] = 0.0f;

#pragma unroll
        for (int k8 = 0; k8 < 8; k8++) {
#pragma unroll
            for (int n = 0; n < 8; n++) {
                uint2 kf = *(const uint2*)&Kf[(n * 8 + k8) * 68 + 2 * lane];
                mma_tf32(sc[n], qa[k8][0], qa[k8][1], qa[k8][2], qa[k8][3], kf.x, kf.y);
            }
        }

        // ---- Taylor weights + mask + denominators ----
#pragma unroll
        for (int n = 0; n < 8; n++) {
            int kc = n * 8 + 2 * t;
            float m0 = mk[kc], m1 = mk[kc + 1];
            float s0 = sc[n][0] * 0.125f, s1 = sc[n][1] * 0.125f;
            float s2 = sc[n][2] * 0.125f, s3 = sc[n][3] * 0.125f;
            float w0 = fmaf(s0, fmaf(0.5f, s0, 1.0f), 1.0f) * m0;
            float w1 = fmaf(s1, fmaf(0.5f, s1, 1.0f), 1.0f) * m1;
            float w2 = fmaf(s2, fmaf(0.5f, s2, 1.0f), 1.0f) * m0;
            float w3 = fmaf(s3, fmaf(0.5f, s3, 1.0f), 1.0f) * m1;
            den0 += w0 + w1;
            den1 += w2 + w3;
            sc[n][0] = w0; sc[n][1] = w1; sc[n][2] = w2; sc[n][3] = w3;
        }

        // ---- MMA2: O += W @ V (A-frags via quad shfl) ----
#pragma unroll
        for (int n = 0; n < 8; n++) {
            float u0 = __shfl_sync(0xffffffffu, sc[n][0], srcL);
            float u1 = __shfl_sync(0xffffffffu, sc[n][1], srcL);
            float v0 = __shfl_sync(0xffffffffu, sc[n][2], srcL);
            float v1 = __shfl_sync(0xffffffffu, sc[n][3], srcL);
            float x0 = __shfl_sync(0xffffffffu, sc[n][0], srcH);
            float x1 = __shfl_sync(0xffffffffu, sc[n][1], srcH);
            float y0 = __shfl_sync(0xffffffffu, sc[n][2], srcH);
            float y1 = __shfl_sync(0xffffffffu, sc[n][3], srcH);
            uint32_t a0 = f2tf32(odd ? u1 : u0);
            uint32_t a1 = f2tf32(odd ? v1 : v0);
            uint32_t a2 = f2tf32(odd ? x1 : x0);
            uint32_t a3 = f2tf32(odd ? y1 : y0);
#pragma unroll
            for (int dn = 0; dn < 8; dn++) {
                uint2 vf = *(const uint2*)&Vf[(n * 8 + dn) * 68 + 2 * lane];
                mma_tf32(outr[dn], a0, a1, a2, a3, vf.x, vf.y);
            }
        }
    }

    // ---- quad-reduce denominators ----
    den0 += __shfl_xor_sync(0xffffffffu, den0, 1);
    den0 += __shfl_xor_sync(0xffffffffu, den0, 2);
    den1 += __shfl_xor_sync(0xffffffffu, den1, 1);
    den1 += __shfl_xor_sync(0xffffffffu, den1, 2);
    float inv0 = 1.0f / den0;
    float inv1 = 1.0f / den1;

    // ---- normalize + tf32-round + store ----
    {
        const int rowA = w * 16 + g;
        float* dA = &outp[(size_t)(prow0 + qt * 128 + rowA) * DIM + h * 64];
        float* dB = dA + 8 * DIM;
#pragma unroll
        for (int n = 0; n < 8; n++) {
            int c = n * 8 + 2 * t;
            *(float2*)(dA + c) = make_float2(rtf(outr[n][0] * inv0), rtf(outr[n][1] * inv0));
            *(float2*)(dB + c) = make_float2(rtf(outr[n][2] * inv1), rtf(outr[n][3] * inv1));
        }
    }
}

// ---------------- launch ----------------
extern "C" void kernel_launch(void* const* d_in, const int* in_sizes, int n_in,
                              void* d_out, int out_size)
{
    const float*         x    = (const float*)d_in[0];
    const unsigned char* mask = (const unsigned char*)d_in[1];
    const float*         rot  = (const float*)d_in[2];
    const float*         Wt   = (const float*)d_in[3];
    const float*         Wo   = (const float*)d_in[4];
    float*               out  = (float*)d_out;

    float *qkv_p, *att_p, *x_p, *wt_p, *wo_p;
    cudaGetSymbolAddress((void**)&qkv_p, g_qkv);
    cudaGetSymbolAddress((void**)&att_p, g_att);
    cudaGetSymbolAddress((void**)&x_p,  g_x);
    cudaGetSymbolAddress((void**)&wt_p, g_wt);
    cudaGetSymbolAddress((void**)&wo_p, g_wo);

    static const int ATT_SMEM = ATT_WORDS * (int)sizeof(uint32_t);  // 70,144 B
    cudaFuncSetAttribute(attn_mma_kernel, cudaFuncAttributeMaxDynamicSharedMemorySize, ATT_SMEM);

    convert_mask_kernel<<<1, 256>>>(mask);

    // pre-round inputs to tf32
    round_kernel<<<(NP * DIM / 4 + 255) / 256, 256>>>((const float4*)x, (float4*)x_p, NP * DIM / 4);
    round_kernel<<<(ROWQ * DIM / 4 + 255) / 256, 256>>>((const float4*)Wt, (float4*)wt_p, ROWQ * DIM / 4);
    round_kernel<<<(DIM * DIM / 4 + 255) / 256, 256>>>((const float4*)Wo, (float4*)wo_p, DIM * DIM / 4);

    // qkv = x @ W_trans^T
    gemm_tf32_kernel<<<dim3(ROWQ / 128, NP / 128), 256>>>(x_p, wt_p, qkv_p, NP, ROWQ, DIM);

    // rotate q,k where masked; round; emit fragment-ordered K/V
    rotate_kernel<<<NP, 256>>>(rot);

    // attention (cp.async pipelined mma.sync tf32) -> g_att
    attn_mma_kernel<<<dim3(SS / 128, BB * NH), 256, ATT_SMEM>>>(att_p);

    // out = att @ W_o^T
    gemm_tf32_kernel<<<dim3(DIM / 128, NP / 128), 256>>>(att_p, wo_p, out, NP, DIM, DIM);
}

// round 7
// speedup vs baseline: 3.1985x; 1.0517x over previous
#include <cuda_runtime.h>
#include <cuda_bf16.h>
#include <cstdint>

// Problem constants
#define BB   2
#define SS   2048
#define DIM  512
#define NH   8
#define HD   64
#define QK   512          // NH*HD
#define ROWQ 1536         // 2*QK + DIM
#define NP   4096         // B*S positions

// ---------------- scratch ----------------
__device__ float g_qkv[NP * ROWQ];     // natural layout (q part used by attn)
__device__ float g_attaf[NP * DIM];    // attention output, A-frag order
__device__ float g_mask[NP];
__device__ float g_xaf[NP * DIM];      // x, A-frag order, tf32-rounded
__device__ float g_wtbf[ROWQ * DIM];   // W_trans, B-frag order, rounded
__device__ float g_wobf[DIM * DIM];    // W_o, B-frag order, rounded
// fragment-ordered K/V for attention: [bh][stage][block 0..63][word 0..63]
__device__ float g_kf[16 * 32 * 64 * 64];
__device__ float g_vf[16 * 32 * 64 * 64];

// ---------------- helpers ----------------
__device__ __forceinline__ uint32_t f2tf32(float f) {
    uint32_t r; asm("cvt.rn.tf32.f32 %0, %1;" : "=r"(r) : "f"(f)); return r;
}
__device__ __forceinline__ float rtf(float f) { return __uint_as_float(f2tf32(f)); }

__device__ __forceinline__ uint32_t smem_u32(const void* p) {
    uint32_t a;
    asm("{ .reg .u64 t; cvta.to.shared.u64 t, %1; cvt.u32.u64 %0, t; }" : "=r"(a) : "l"(p));
    return a;
}
__device__ __forceinline__ void cp16(uint32_t dst, const void* src) {
    asm volatile("cp.async.ca.shared.global [%0], [%1], 16;" :: "r"(dst), "l"(src) : "memory");
}
#define CP_COMMIT() asm volatile("cp.async.commit_group;" ::: "memory")
#define CP_WAIT0()  asm volatile("cp.async.wait_group 0;" ::: "memory")

__device__ __forceinline__ void mma_tf32(float* c,
    uint32_t a0, uint32_t a1, uint32_t a2, uint32_t a3, uint32_t b0, uint32_t b1)
{
    asm volatile(
        "mma.sync.aligned.m16n8k8.row.col.f32.tf32.tf32.f32 "
        "{%0,%1,%2,%3}, {%4,%5,%6,%7}, {%8,%9}, {%0,%1,%2,%3};"
        : "+f"(c[0]), "+f"(c[1]), "+f"(c[2]), "+f"(c[3])
        : "r"(a0), "r"(a1), "r"(a2), "r"(a3), "r"(b0), "r"(b1));
}

// permuted K index (attention): element K[b,h][key][d]
__device__ __forceinline__ size_t kf_off(int b, int h, int key, int d) {
    int stage = key >> 6, n8 = (key >> 3) & 7, g = key & 7;
    return ((size_t)(((b * 8 + h) * 32 + stage) * 64 + n8 * 8 + (d >> 3))) * 64
           + 8 * g + 2 * (d & 3) + ((d & 7) >> 2);
}
// permuted V index (attention): element V[b,h][key][d]
__device__ __forceinline__ size_t vf_off(int b, int h, int key, int d) {
    int stage = key >> 6, kb = (key >> 3) & 7;
    return ((size_t)(((b * 8 + h) * 32 + stage) * 64 + kb * 8 + (d >> 3))) * 64
           + 8 * (d & 7) + 2 * (key & 3) + ((key & 7) >> 2);
}

// ---------------- mask sniff ----------------
__global__ void convert_mask_kernel(const unsigned char* __restrict__ raw) {
    __shared__ int typ_s;
    if (threadIdx.x == 0) {
        int t = 1;
        for (int i = 0; i < 512; i++) {
            unsigned char b = raw[i];
            if ((i & 3) != 0 && b != 0) { t = (b == 0x3f || b == 0x80) ? 2 : 0; break; }
        }
        typ_s = t;
    }
    __syncthreads();
    int t = typ_s;
    for (int i = threadIdx.x; i < NP; i += blockDim.x) {
        float m;
        if (t == 0)      m = raw[i] ? 1.0f : 0.0f;
        else if (t == 1) m = (((const int*)raw)[i] != 0) ? 1.0f : 0.0f;
        else             m = (((const float*)raw)[i] != 0.0f) ? 1.0f : 0.0f;
        g_mask[i] = m;
    }
}

// ---------------- round + emit A-frag order ----------------
// A[r][c] -> block (r>>4)*(K/8)+(c>>3), word 4*(4*(r&7)+(c&3)) + 2*((c>>2)&1) + ((r&15)>>3)
__global__ void round_af_kernel(const float4* __restrict__ src, float* __restrict__ dst,
                                int K4, int n4) {
    int i = blockIdx.x * blockDim.x + threadIdx.x;
    if (i >= n4) return;
    float4 v = src[i];
    int r = i / K4, c0 = (i - r * K4) * 4;
    int rm = r & 15;
    size_t block = (size_t)(r >> 4) * (K4 >> 1) + (c0 >> 3);
    int W0 = 16 * (rm & 7) + 2 * ((c0 >> 2) & 1) + (rm >> 3);
    float* bp = dst + block * 128;
    bp[W0]      = rtf(v.x);
    bp[W0 + 4]  = rtf(v.y);
    bp[W0 + 8]  = rtf(v.z);
    bp[W0 + 12] = rtf(v.w);
}

// ---------------- round + emit B-frag order ----------------
// B[n][c] -> block (n>>3)*(K/8)+(c>>3), word 2*(4*(n&7)+(c&3)) + ((c>>2)&1)
__global__ void round_bf_kernel(const float4* __restrict__ src, float* __restrict__ dst,
                                int K4, int n4) {
    int i = blockIdx.x * blockDim.x + threadIdx.x;
    if (i >= n4) return;
    float4 v = src[i];
    int r = i / K4, c0 = (i - r * K4) * 4;
    size_t block = (size_t)(r >> 3) * (K4 >> 1) + (c0 >> 3);
    int W0 = 8 * (r & 7) + ((c0 >> 2) & 1);
    float* bp = dst + block * 64;
    bp[W0]     = rtf(v.x);
    bp[W0 + 2] = rtf(v.y);
    bp[W0 + 4] = rtf(v.z);
    bp[W0 + 6] = rtf(v.w);
}

// ---------------- cp.async frag-ordered tf32 GEMM  C = A @ B^T ----------------
// Aaf: A-frag order [M/16][K/8][128w]; Bbf: B-frag order [N/8][K/8][64w].
// CTA 128x128, BK=32, 16 stages, double buffered. C natural row-major.
__global__ void __launch_bounds__(256, 2) gemm_af_kernel(
    const float* __restrict__ Aaf, const float* __restrict__ Bbf,
    float* __restrict__ C, int M, int N, int K)
{
    extern __shared__ uint32_t gsm[];
    const uint32_t sbase = smem_u32(gsm);

    const int tid = threadIdx.x;
    const int w = tid >> 5, lane = tid & 31;
    const int g = lane >> 2, t = lane & 3;
    const int wm = w >> 2, wn = w & 3;
    const int bm = blockIdx.y, bn = blockIdx.x;
    const int K8 = K >> 3;
    const int nst = K >> 5;

    const char* Ab = (const char*)Aaf;
    const char* Bb = (const char*)Bbf;

    auto issue = [&](int s) {
        uint32_t dstA = sbase + (uint32_t)((s & 1) * 32768);
        uint32_t dstB = dstA + 16384;
#pragma unroll
        for (int c = 0; c < 4; c++) {
            int ch = tid * 4 + c;                       // 0..1023
            cp16(dstA + (uint32_t)(ch * 16),
                 Ab + ((size_t)((bm * 8 + (ch >> 7)) * K8 + s * 4)) * 512 + (ch & 127) * 16);
            cp16(dstB + (uint32_t)(ch * 16),
                 Bb + ((size_t)((bn * 16 + (ch >> 6)) * K8 + s * 4)) * 256 + (ch & 63) * 16);
        }
        CP_COMMIT();
    };

    float acc[4][4][4];
#pragma unroll
    for (int mf = 0; mf < 4; mf++)
#pragma unroll
        for (int nf = 0; nf < 4; nf++)
#pragma unroll
            for (int c = 0; c < 4; c++) acc[mf][nf][c] = 0.0f;

    issue(0);

    for (int s = 0; s < nst; s++) {
        CP_WAIT0();
        __syncthreads();
        if (s + 1 < nst) issue(s + 1);

        uint32_t* As = gsm + (s & 1) * 8192;
        uint32_t* Bs = As + 4096;

#pragma unroll
        for (int kb = 0; kb < 4; kb++) {
            uint32_t a[4][4];
#pragma unroll
            for (int mf = 0; mf < 4; mf++) {
                uint4 av = *(const uint4*)&As[((wm * 4 + mf) * 4 + kb) * 128 + 4 * lane];
                a[mf][0] = av.x; a[mf][1] = av.y; a[mf][2] = av.z; a[mf][3] = av.w;
            }
#pragma unroll
            for (int nf = 0; nf < 4; nf++) {
                uint2 bv = *(const uint2*)&Bs[((wn * 4 + nf) * 4 + kb) * 64 + 2 * lane];
#pragma unroll
                for (int mf = 0; mf < 4; mf++)
                    mma_tf32(acc[mf][nf], a[mf][0], a[mf][1], a[mf][2], a[mf][3], bv.x, bv.y);
            }
        }
    }

#pragma unroll
    for (int mf = 0; mf < 4; mf++) {
        int row = bm * 128 + wm * 64 + mf * 16 + g;
#pragma unroll
        for (int nf = 0; nf < 4; nf++) {
            int col = bn * 128 + wn * 32 + nf * 8 + 2 * t;
            *(float2*)&C[(size_t)row * N + col]       = make_float2(acc[mf][nf][0], acc[mf][nf][1]);
            *(float2*)&C[(size_t)(row + 8) * N + col] = make_float2(acc[mf][nf][2], acc[mf][nf][3]);
        }
    }
}

// ---------------- rotation + tf32 rounding + permuted K/V emission ----------------
__global__ void __launch_bounds__(256) rotate_kernel(const float* __restrict__ rot)
{
    const int p = blockIdx.x, tid = threadIdx.x;
    const int b = p >> 11, s = p & 2047;
    float* row = &g_qkv[(size_t)p * ROWQ];
    const bool masked = (g_mask[p] != 0.0f);

    if (masked) {
        __shared__ float Rt[64 * 65];
        __shared__ float X[1024];
        const float* R = rot + (size_t)p * 4096;
#pragma unroll
        for (int t2 = 0; t2 < 16; t2++) {
            int idx = tid + 256 * t2;
            int i = idx >> 6, j = idx & 63;
            Rt[j * 65 + i] = R[idx];
        }
#pragma unroll
        for (int t2 = 0; t2 < 4; t2++) {
            int idx = tid + 256 * t2;
            X[idx] = row[idx];
        }
        __syncthreads();

        const int i  = tid & 63;
        const int vb = tid >> 6;
#pragma unroll
        for (int ii = 0; ii < 4; ii++) {
            int v = vb + 4 * ii;
            float acc = 0.0f;
#pragma unroll 8
            for (int j = 0; j < 64; j++)
                acc = fmaf(Rt[j * 65 + i], X[v * 64 + j], acc);
            float rv = rtf(acc);
            if (v < 8) row[v * 64 + i] = rv;               // q natural
            else       g_kf[kf_off(b, v - 8, s, i)] = rv;  // k permuted
        }
    } else {
#pragma unroll
        for (int t2 = 0; t2 < 4; t2++) {
            int idx = tid + 256 * t2;     // 0..1023
            float rv = rtf(row[idx]);
            if (idx < 512) row[idx] = rv;
            else g_kf[kf_off(b, (idx - 512) >> 6, s, idx & 63)] = rv;
        }
    }
    // v: round + permuted store (both branches)
#pragma unroll
    for (int t2 = 0; t2 < 2; t2++) {
        int idx = tid + 256 * t2;         // 0..511
        float rv = rtf(row[1024 + idx]);
        g_vf[vf_off(b, idx >> 6, s, idx & 63)] = rv;
    }
}

// ---------------- cp.async double-buffered mma.sync tf32 Taylor attention ------
#define STG_K   (64 * 68)
#define STG_V   (64 * 68)
#define STG_WORDS (STG_K + STG_V + 64)
#define ATT_WORDS (2 * STG_WORDS)

__global__ void __launch_bounds__(256, 2) attn_mma_kernel(float* __restrict__ outaf)
{
    extern __shared__ uint32_t sm[];
    const uint32_t sbase = smem_u32(sm);

    const int tid = threadIdx.x;
    const int w = tid >> 5, lane = tid & 31;
    const int g = lane >> 2, t = lane & 3;
    const int qt = blockIdx.x, bh = blockIdx.y;
    const int b = bh >> 3, h = bh & 7;
    const int prow0 = b * SS;

    // ---- Q fragments in registers ----
    uint32_t qa[8][4];
    {
        const float* qA = &g_qkv[(size_t)(prow0 + qt * 128 + w * 16 + g) * ROWQ + h * 64];
        const float* qB = qA + 8 * ROWQ;
#pragma unroll
        for (int k8 = 0; k8 < 8; k8++) {
            qa[k8][0] = __float_as_uint(qA[k8 * 8 + t]);
            qa[k8][1] = __float_as_uint(qB[k8 * 8 + t]);
            qa[k8][2] = __float_as_uint(qA[k8 * 8 + t + 4]);
            qa[k8][3] = __float_as_uint(qB[k8 * 8 + t + 4]);
        }
    }

    const float* kbase = &g_kf[(size_t)(bh * 32) * 4096];
    const float* vbase = &g_vf[(size_t)(bh * 32) * 4096];
    const float* mbase = &g_mask[b * SS];

    auto issue_stage = [&](int s) {
        const uint32_t dstb = sbase + (uint32_t)((s & 1) * STG_WORDS * 4);
        const char* ksrc = (const char*)(kbase + (size_t)s * 4096);
        const char* vsrc = (const char*)(vbase + (size_t)s * 4096);
#pragma unroll
        for (int c = 0; c < 4; c++) {
            int ch = tid * 4 + c;
            int ib = ch >> 4, off = ch & 15;
            uint32_t d = (uint32_t)(ib * 272 + off * 16);
            cp16(dstb + d, ksrc + ch * 16);
            cp16(dstb + (uint32_t)(STG_K * 4) + d, vsrc + ch * 16);
        }
        if (tid < 16)
            cp16(dstb + (uint32_t)((STG_K + STG_V) * 4 + tid * 16),
                 (const char*)(mbase + s * 64 + tid * 4));
        CP_COMMIT();
    };

    float outr[8][4];
#pragma unroll
    for (int n = 0; n < 8; n++)
#pragma unroll
        for (int j = 0; j < 4; j++) outr[n][j] = 0.0f;
    float den0 = 0.0f, den1 = 0.0f;

    const int srcL = (lane & ~3) | (t >> 1);
    const int srcH = srcL + 2;
    const bool odd = (t & 1);

    issue_stage(0);

    for (int s = 0; s < 32; s++) {
        CP_WAIT0();
        __syncthreads();
        if (s + 1 < 32) issue_stage(s + 1);

        uint32_t* Kf = sm + (s & 1) * STG_WORDS;
        uint32_t* Vf = Kf + STG_K;
        const float* mk = (const float*)(Vf + STG_V);

        // ---- MMA1: S[16 q, 64 keys] = Q @ K^T ----
        float sc[8][4];
#pragma unroll
        for (int n = 0; n < 8; n++)
#pragma unroll
            for (int j = 0; j < 4; j++) sc[n][j] = 0.0f;

#pragma unroll
        for (int k8 = 0; k8 < 8; k8++) {
#pragma unroll
            for (int n = 0; n < 8; n++) {
                uint2 kf = *(const uint2*)&Kf[(n * 8 + k8) * 68 + 2 * lane];
                mma_tf32(sc[n], qa[k8][0], qa[k8][1], qa[k8][2], qa[k8][3], kf.x, kf.y);
            }
        }

        // ---- Taylor weights + mask + denominators ----
#pragma unroll
        for (int n = 0; n < 8; n++) {
            int kc = n * 8 + 2 * t;
            float m0 = mk[kc], m1 = mk[kc + 1];
            float s0 = sc[n][0] * 0.125f, s1 = sc[n][1] * 0.125f;
            float s2 = sc[n][2] * 0.125f, s3 = sc[n][3] * 0.125f;
            float w0 = fmaf(s0, fmaf(0.5f, s0, 1.0f), 1.0f) * m0;
            float w1 = fmaf(s1, fmaf(0.5f, s1, 1.0f), 1.0f) * m1;
            float w2 = fmaf(s2, fmaf(0.5f, s2, 1.0f), 1.0f) * m0;
            float w3 = fmaf(s3, fmaf(0.5f, s3, 1.0f), 1.0f) * m1;
            den0 += w0 + w1;
            den1 += w2 + w3;
            sc[n][0] = w0; sc[n][1] = w1; sc[n][2] = w2; sc[n][3] = w3;
        }

        // ---- MMA2: O += W @ V (A-frags via quad shfl) ----
#pragma unroll
        for (int n = 0; n < 8; n++) {
            float u0 = __shfl_sync(0xffffffffu, sc[n][0], srcL);
            float u1 = __shfl_sync(0xffffffffu, sc[n][1], srcL);
            float v0 = __shfl_sync(0xffffffffu, sc[n][2], srcL);
            float v1 = __shfl_sync(0xffffffffu, sc[n][3], srcL);
            float x0 = __shfl_sync(0xffffffffu, sc[n][0], srcH);
            float x1 = __shfl_sync(0xffffffffu, sc[n][1], srcH);
            float y0 = __shfl_sync(0xffffffffu, sc[n][2], srcH);
            float y1 = __shfl_sync(0xffffffffu, sc[n][3], srcH);
            uint32_t a0 = f2tf32(odd ? u1 : u0);
            uint32_t a1 = f2tf32(odd ? v1 : v0);
            uint32_t a2 = f2tf32(odd ? x1 : x0);
            uint32_t a3 = f2tf32(odd ? y1 : y0);
#pragma unroll
            for (int dn = 0; dn < 8; dn++) {
                uint2 vf = *(const uint2*)&Vf[(n * 8 + dn) * 68 + 2 * lane];
                mma_tf32(outr[dn], a0, a1, a2, a3, vf.x, vf.y);
            }
        }
    }

    // ---- quad-reduce denominators ----
    den0 += __shfl_xor_sync(0xffffffffu, den0, 1);
    den0 += __shfl_xor_sync(0xffffffffu, den0, 2);
    den1 += __shfl_xor_sync(0xffffffffu, den1, 1);
    den1 += __shfl_xor_sync(0xffffffffu, den1, 2);
    float inv0 = 1.0f / den0;
    float inv1 = 1.0f / den1;

    // ---- normalize + tf32-round + store in A-frag order for gemm2 ----
    {
        // m16 block of this warp; col blocks h*8+n; words per af layout
        size_t blk0 = ((size_t)((prow0 + qt * 128 + w * 16) >> 4)) * 64 + h * 8;
        int w00 = 16 * g + 4 * ((2 * t) & 3) + 2 * (t >> 1);       // rowA, col 2t
        int w01 = 16 * g + 4 * ((2 * t + 1) & 3) + 2 * (t >> 1);   // rowA, col 2t+1
#pragma unroll
        for (int n = 0; n < 8; n++) {
            float* bp = outaf + (blk0 + n) * 128;
            bp[w00]     = rtf(outr[n][0] * inv0);
            bp[w01]     = rtf(outr[n][1] * inv0);
            bp[w00 + 1] = rtf(outr[n][2] * inv1);   // rowB = rowA+8 -> +1
            bp[w01 + 1] = rtf(outr[n][3] * inv1);
        }
    }
}

// ---------------- launch ----------------
extern "C" void kernel_launch(void* const* d_in, const int* in_sizes, int n_in,
                              void* d_out, int out_size)
{
    const float*         x    = (const float*)d_in[0];
    const unsigned char* mask = (const unsigned char*)d_in[1];
    const float*         rot  = (const float*)d_in[2];
    const float*         Wt   = (const float*)d_in[3];
    const float*         Wo   = (const float*)d_in[4];
    float*               out  = (float*)d_out;

    float *qkv_p, *attaf_p, *xaf_p, *wtbf_p, *wobf_p;
    cudaGetSymbolAddress((void**)&qkv_p,  g_qkv);
    cudaGetSymbolAddress((void**)&attaf_p, g_attaf);
    cudaGetSymbolAddress((void**)&xaf_p,  g_xaf);
    cudaGetSymbolAddress((void**)&wtbf_p, g_wtbf);
    cudaGetSymbolAddress((void**)&wobf_p, g_wobf);

    static const int ATT_SMEM  = ATT_WORDS * (int)sizeof(uint32_t);  // 70,144 B
    static const int GEMM_SMEM = 65536;
    cudaFuncSetAttribute(attn_mma_kernel, cudaFuncAttributeMaxDynamicSharedMemorySize, ATT_SMEM);
    cudaFuncSetAttribute(gemm_af_kernel, cudaFuncAttributeMaxDynamicSharedMemorySize, GEMM_SMEM);

    convert_mask_kernel<<<1, 256>>>(mask);

    // round + reorder inputs (K4 = DIM/4 = 128 for all three)
    round_af_kernel<<<(NP * DIM / 4 + 255) / 256, 256>>>((const float4*)x, xaf_p, DIM / 4, NP * DIM / 4);
    round_bf_kernel<<<(ROWQ * DIM / 4 + 255) / 256, 256>>>((const float4*)Wt, wtbf_p, DIM / 4, ROWQ * DIM / 4);
    round_bf_kernel<<<(DIM * DIM / 4 + 255) / 256, 256>>>((const float4*)Wo, wobf_p, DIM / 4, DIM * DIM / 4);

    // qkv = x @ W_trans^T  (frag-ordered operands, natural output)
    gemm_af_kernel<<<dim3(ROWQ / 128, NP / 128), 256, GEMM_SMEM>>>(xaf_p, wtbf_p, qkv_p, NP, ROWQ, DIM);

    // rotate q,k where masked; round; emit fragment-ordered K/V
    rotate_kernel<<<NP, 256>>>(rot);

    // attention -> g_attaf (A-frag order, tf32-rounded)
    attn_mma_kernel<<<dim3(SS / 128, BB * NH), 256, ATT_SMEM>>>(attaf_p);

    // out = att @ W_o^T
    gemm_af_kernel<<<dim3(DIM / 128, NP / 128), 256, GEMM_SMEM>>>(attaf_p, wobf_p, out, NP, DIM, DIM);
}

// round 8
// speedup vs baseline: 5.5540x; 1.7365x over previous
#include <cuda_runtime.h>
#include <cuda_fp16.h>
#include <cstdint>

// Problem constants
#define BB   2
#define SS   2048
#define DIM  512
#define NH   8
#define HD   64
#define QK   512          // NH*HD
#define ROWQ 1536         // 2*QK + DIM
#define NP   4096         // B*S positions

// ---------------- scratch ----------------
__device__ float    g_qkv[NP * ROWQ];        // gemm1 output, natural f32
__device__ unsigned short g_qh[NP * QK];     // Q fp16, A-frag order per (b,h)
__device__ unsigned short g_kh[NP * QK];     // K fp16, B-frag order (MMA1)
__device__ unsigned short g_vh[NP * QK];     // V fp16, B-frag order (MMA2)
__device__ uint32_t g_xaf[NP * DIM / 2];     // x fp16 A-frag words
__device__ uint32_t g_wtbf[ROWQ * DIM / 2];  // W_trans fp16 B-frag words
__device__ uint32_t g_wobf[DIM * DIM / 2];   // W_o fp16 B-frag words
__device__ uint32_t g_attaf[NP * DIM / 2];   // attention out fp16 A-frag words
__device__ float    g_mask[NP];

// ---------------- helpers ----------------
__device__ __forceinline__ uint32_t pack_h2(float lo, float hi) {
    uint32_t r;
    asm("cvt.rn.f16x2.f32 %0, %1, %2;" : "=r"(r) : "f"(hi), "f"(lo));
    return r;
}
__device__ __forceinline__ unsigned short f2h(float f) {
    return __half_as_ushort(__float2half_rn(f));
}
__device__ __forceinline__ uint32_t smem_u32(const void* p) {
    uint32_t a;
    asm("{ .reg .u64 t; cvta.to.shared.u64 t, %1; cvt.u32.u64 %0, t; }" : "=r"(a) : "l"(p));
    return a;
}
__device__ __forceinline__ void cp16(uint32_t dst, const void* src) {
    asm volatile("cp.async.ca.shared.global [%0], [%1], 16;" :: "r"(dst), "l"(src) : "memory");
}
#define CP_COMMIT() asm volatile("cp.async.commit_group;" ::: "memory")
#define CP_WAIT0()  asm volatile("cp.async.wait_group 0;" ::: "memory")
#define CP_WAIT1()  asm volatile("cp.async.wait_group 1;" ::: "memory")

__device__ __forceinline__ void mma_f16(float* c,
    uint32_t a0, uint32_t a1, uint32_t a2, uint32_t a3, uint32_t b0, uint32_t b1)
{
    asm volatile(
        "mma.sync.aligned.m16n8k16.row.col.f32.f16.f16.f32 "
        "{%0,%1,%2,%3}, {%4,%5,%6,%7}, {%8,%9}, {%0,%1,%2,%3};"
        : "+f"(c[0]), "+f"(c[1]), "+f"(c[2]), "+f"(c[3])
        : "r"(a0), "r"(a1), "r"(a2), "r"(a3), "r"(b0), "r"(b1));
}

// half-index helpers for attention operand layouts
__device__ __forceinline__ size_t qh_off(int bh, int s, int d) {
    int lane = 4 * (s & 7) + ((d & 7) >> 1);
    int j = ((s >> 3) & 1) + 2 * ((d >> 3) & 1);
    return (((size_t)bh * 128 + (s >> 4)) * 4 + (d >> 4)) * 256 + lane * 8 + j * 2 + (d & 1);
}
__device__ __forceinline__ size_t kh_off(int bh, int key, int d) {
    return ((((size_t)bh * 32 + (key >> 6)) * 8 + ((key >> 3) & 7)) * 4 + (d >> 4)) * 128
           + (4 * (key & 7) + ((d & 7) >> 1)) * 4 + ((d >> 3) & 1) * 2 + (d & 1);
}
__device__ __forceinline__ size_t vh_off(int bh, int key, int d) {
    int kr = key & 63, kb = kr >> 4, kk = kr & 15;
    return ((((size_t)bh * 32 + (key >> 6)) * 8 + (d >> 3)) * 4 + kb) * 128
           + (4 * (d & 7) + ((kk & 7) >> 1)) * 4 + ((kk >> 3) & 1) * 2 + (kk & 1);
}

// ---------------- mask sniff ----------------
__global__ void convert_mask_kernel(const unsigned char* __restrict__ raw) {
    __shared__ int typ_s;
    if (threadIdx.x == 0) {
        int t = 1;
        for (int i = 0; i < 512; i++) {
            unsigned char b = raw[i];
            if ((i & 3) != 0 && b != 0) { t = (b == 0x3f || b == 0x80) ? 2 : 0; break; }
        }
        typ_s = t;
    }
    __syncthreads();
    int t = typ_s;
    for (int i = threadIdx.x; i < NP; i += blockDim.x) {
        float m;
        if (t == 0)      m = raw[i] ? 1.0f : 0.0f;
        else if (t == 1) m = (((const int*)raw)[i] != 0) ? 1.0f : 0.0f;
        else             m = (((const float*)raw)[i] != 0.0f) ? 1.0f : 0.0f;
        g_mask[i] = m;
    }
}

// ---------------- round f32 -> fp16, emit A-frag order ----------------
__global__ void round_af_kernel(const float4* __restrict__ src, uint32_t* __restrict__ dst,
                                int K4, int n4) {
    int i = blockIdx.x * blockDim.x + threadIdx.x;
    if (i >= n4) return;
    float4 v = src[i];
    int r = i / K4, c0 = (i - r * K4) * 4;
    int rm = r & 15;
    size_t block = (size_t)(r >> 4) * (K4 >> 2) + (c0 >> 4);
    int lane = 4 * (rm & 7) + ((c0 & 7) >> 1);
    int j = (rm >> 3) + 2 * ((c0 >> 3) & 1);
    dst[block * 128 + lane * 4 + j]       = pack_h2(v.x, v.y);
    dst[block * 128 + (lane + 1) * 4 + j] = pack_h2(v.z, v.w);
}

// ---------------- round f32 -> fp16, emit B-frag order ----------------
__global__ void round_bf_kernel(const float4* __restrict__ src, uint32_t* __restrict__ dst,
                                int K4, int n4) {
    int i = blockIdx.x * blockDim.x + threadIdx.x;
    if (i >= n4) return;
    float4 v = src[i];
    int r = i / K4, c0 = (i - r * K4) * 4;
    size_t block = (size_t)(r >> 3) * (K4 >> 2) + (c0 >> 4);
    int lane = 4 * (r & 7) + ((c0 & 7) >> 1);
    int br = (c0 >> 3) & 1;
    dst[block * 64 + lane * 2 + br]       = pack_h2(v.x, v.y);
    dst[block * 64 + (lane + 1) * 2 + br] = pack_h2(v.z, v.w);
}

// ---------------- fp16 frag-ordered GEMM  C = A @ B^T (3-stage cp.async) ----
// Aaf: [M/16][K/16][256 halves]; Bbf: [N/8][K/16][128 halves]; C f32 natural.
__global__ void __launch_bounds__(256, 2) gemm_af_kernel(
    const uint32_t* __restrict__ Aaf, const uint32_t* __restrict__ Bbf,
    float* __restrict__ C, int M, int N, int K)
{
    extern __shared__ uint32_t gsm[];
    const uint32_t sbase = smem_u32(gsm);

    const int tid = threadIdx.x;
    const int w = tid >> 5, lane = tid & 31;
    const int g = lane >> 2, t = lane & 3;
    const int wm = w >> 2, wn = w & 3;
    const int bm = blockIdx.y, bn = blockIdx.x;
    const int K16 = K >> 4;
    const int nst = K >> 5;

    const char* Ab = (const char*)Aaf;
    const char* Bb = (const char*)Bbf;

    auto issue = [&](int s) {
        uint32_t base = sbase + (uint32_t)((s % 3) * 16384);
#pragma unroll
        for (int c = 0; c < 2; c++) {
            int ch = tid * 2 + c;                 // 0..511
            int ablk = ch >> 5;                   // mb*2+kb
            cp16(base + (uint32_t)(ch * 16),
                 Ab + ((size_t)((bm * 8 + (ablk >> 1)) * K16 + s * 2 + (ablk & 1))) * 512 + (ch & 31) * 16);
            int bblk = ch >> 4;                   // nb*2+kb
            cp16(base + 8192u + (uint32_t)(ch * 16),
                 Bb + ((size_t)((bn * 16 + (bblk >> 1)) * K16 + s * 2 + (bblk & 1))) * 256 + (ch & 15) * 16);
        }
        CP_COMMIT();
    };

    float acc[4][4][4];
#pragma unroll
    for (int mf = 0; mf < 4; mf++)
#pragma unroll
        for (int nf = 0; nf < 4; nf++)
#pragma unroll
            for (int c = 0; c < 4; c++) acc[mf][nf][c] = 0.0f;

    issue(0);
    issue(1);

    for (int s = 0; s < nst; s++) {
        if (s + 1 == nst) { CP_WAIT0(); } else { CP_WAIT1(); }
        __syncthreads();
        if (s + 2 < nst) issue(s + 2);

        uint32_t* As = gsm + (s % 3) * 4096;
        uint32_t* Bs = As + 2048;

#pragma unroll
        for (int kb = 0; kb < 2; kb++) {
            uint32_t a[4][4];
#pragma unroll
            for (int mf = 0; mf < 4; mf++) {
                uint4 av = *(const uint4*)&As[((wm * 4 + mf) * 2 + kb) * 128 + 4 * lane];
                a[mf][0] = av.x; a[mf][1] = av.y; a[mf][2] = av.z; a[mf][3] = av.w;
            }
#pragma unroll
            for (int nf = 0; nf < 4; nf++) {
                uint2 bv = *(const uint2*)&Bs[((wn * 4 + nf) * 2 + kb) * 64 + 2 * lane];
#pragma unroll
                for (int mf = 0; mf < 4; mf++)
                    mma_f16(acc[mf][nf], a[mf][0], a[mf][1], a[mf][2], a[mf][3], bv.x, bv.y);
            }
        }
        __syncthreads();
    }

#pragma unroll
    for (int mf = 0; mf < 4; mf++) {
        int row = bm * 128 + wm * 64 + mf * 16 + g;
#pragma unroll
        for (int nf = 0; nf < 4; nf++) {
            int col = bn * 128 + wn * 32 + nf * 8 + 2 * t;
            *(float2*)&C[(size_t)row * N + col]       = make_float2(acc[mf][nf][0], acc[mf][nf][1]);
            *(float2*)&C[(size_t)(row + 8) * N + col] = make_float2(acc[mf][nf][2], acc[mf][nf][3]);
        }
    }
}

// ---------------- rotation + fp16 rounding + frag-ordered q/k/v emission ------
__global__ void __launch_bounds__(256) rotate_kernel(const float* __restrict__ rot)
{
    const int p = blockIdx.x, tid = threadIdx.x;
    const int b = p >> 11, s = p & 2047;
    float* row = &g_qkv[(size_t)p * ROWQ];
    const bool masked = (g_mask[p] != 0.0f);

    if (masked) {
        __shared__ float Rt[64 * 65];
        __shared__ float X[1024];
        const float* R = rot + (size_t)p * 4096;
#pragma unroll
        for (int t2 = 0; t2 < 16; t2++) {
            int idx = tid + 256 * t2;
            int i = idx >> 6, j = idx & 63;
            Rt[j * 65 + i] = R[idx];
        }
#pragma unroll
        for (int t2 = 0; t2 < 4; t2++) {
            int idx = tid + 256 * t2;
            X[idx] = row[idx];
        }
        __syncthreads();

        const int i  = tid & 63;
        const int vb = tid >> 6;
#pragma unroll
        for (int ii = 0; ii < 4; ii++) {
            int vv = vb + 4 * ii;
            float acc = 0.0f;
#pragma unroll 8
            for (int j = 0; j < 64; j++)
                acc = fmaf(Rt[j * 65 + i], X[vv * 64 + j], acc);
            unsigned short hv = f2h(acc);
            if (vv < 8) g_qh[qh_off(b * 8 + vv, s, i)] = hv;
            else        g_kh[kh_off(b * 8 + vv - 8, s, i)] = hv;
        }
    } else {
#pragma unroll
        for (int t2 = 0; t2 < 4; t2++) {
            int idx = tid + 256 * t2;     // 0..1023
            unsigned short hv = f2h(row[idx]);
            if (idx < 512) g_qh[qh_off(b * 8 + (idx >> 6), s, idx & 63)] = hv;
            else           g_kh[kh_off(b * 8 + ((idx - 512) >> 6), s, idx & 63)] = hv;
        }
    }
    // v: round + frag-ordered store
#pragma unroll
    for (int t2 = 0; t2 < 2; t2++) {
        int idx = tid + 256 * t2;         // 0..511
        g_vh[vh_off(b * 8 + (idx >> 6), s, idx & 63)] = f2h(row[1024 + idx]);
    }
}

// ---------------- fp16 mma.sync Taylor attention (cp.async double-buffered) ----
// grid (16 qtiles, 16 bh), 256 thr, 2 CTA/SM. 32 stages of 64 keys.
// Stage smem: K 8KB | V 8KB | mask 256B = 16640B; x2 buffers = 33280B.
#define STGW 4160   // stage words

__global__ void __launch_bounds__(256, 2) attn_mma_kernel(uint32_t* __restrict__ outaf)
{
    extern __shared__ uint32_t sm[];
    const uint32_t sbase = smem_u32(sm);

    const int tid = threadIdx.x;
    const int w = tid >> 5, lane = tid & 31;
    const int g = lane >> 2, t = lane & 3;
    const int qt = blockIdx.x, bh = blockIdx.y;
    const int b = bh >> 3, h = bh & 7;

    // ---- Q fragments in registers: 4 k16 blocks, one LDG.128 each ----
    uint32_t qa[4][4];
    {
        int qblk = qt * 8 + w;
        const uint4* qp = reinterpret_cast<const uint4*>(g_qh)
                          + (((size_t)bh * 128 + qblk) * 4) * 32 + lane;
#pragma unroll
        for (int k16 = 0; k16 < 4; k16++) {
            uint4 v = qp[k16 * 32];
            qa[k16][0] = v.x; qa[k16][1] = v.y; qa[k16][2] = v.z; qa[k16][3] = v.w;
        }
    }

    const char* kbase = (const char*)(g_kh + (size_t)bh * 32 * 4096);
    const char* vbase = (const char*)(g_vh + (size_t)bh * 32 * 4096);
    const float* mbase = &g_mask[b * SS];

    auto issue_stage = [&](int s) {
        const uint32_t dstb = sbase + (uint32_t)((s & 1) * STGW * 4);
        const char* ks = kbase + (size_t)s * 8192;
        const char* vs = vbase + (size_t)s * 8192;
#pragma unroll
        for (int c = 0; c < 2; c++) {
            int ch = tid * 2 + c;               // 0..511
            cp16(dstb + (uint32_t)(ch * 16), ks + ch * 16);
            cp16(dstb + 8192u + (uint32_t)(ch * 16), vs + ch * 16);
        }
        if (tid < 16)
            cp16(dstb + 16384u + (uint32_t)(tid * 16), (const char*)(mbase + s * 64 + tid * 4));
        CP_COMMIT();
    };

    float outr[8][4];
#pragma unroll
    for (int n = 0; n < 8; n++)
#pragma unroll
        for (int j = 0; j < 4; j++) outr[n][j] = 0.0f;
    float den0 = 0.0f, den1 = 0.0f;

    issue_stage(0);

    for (int s = 0; s < 32; s++) {
        CP_WAIT0();
        __syncthreads();
        if (s + 1 < 32) issue_stage(s + 1);

        uint32_t* Kf = sm + (s & 1) * STGW;
        uint32_t* Vf = Kf + 2048;
        const float* mk = (const float*)(Kf + 4096);

        // ---- MMA1: S[16 q, 64 keys] = Q @ K^T ----
        float sc[8][4];
#pragma unroll
        for (int n = 0; n < 8; n++)
#pragma unroll
            for (int j = 0; j < 4; j++) sc[n][j] = 0.0f;

#pragma unroll
        for (int k16 = 0; k16 < 4; k16++) {
#pragma unroll
            for (int n = 0; n < 8; n++) {
                uint2 kf = *(const uint2*)&Kf[(n * 4 + k16) * 64 + 2 * lane];
                mma_f16(sc[n], qa[k16][0], qa[k16][1], qa[k16][2], qa[k16][3], kf.x, kf.y);
            }
        }

        // ---- Taylor weights + mask + denominators ----
#pragma unroll
        for (int n = 0; n < 8; n++) {
            int kc = n * 8 + 2 * t;
            float m0 = mk[kc], m1 = mk[kc + 1];
            float s0 = sc[n][0] * 0.125f, s1 = sc[n][1] * 0.125f;
            float s2 = sc[n][2] * 0.125f, s3 = sc[n][3] * 0.125f;
            float w0 = fmaf(s0, fmaf(0.5f, s0, 1.0f), 1.0f) * m0;
            float w1 = fmaf(s1, fmaf(0.5f, s1, 1.0f), 1.0f) * m1;
            float w2 = fmaf(s2, fmaf(0.5f, s2, 1.0f), 1.0f) * m0;
            float w3 = fmaf(s3, fmaf(0.5f, s3, 1.0f), 1.0f) * m1;
            den0 += w0 + w1;
            den1 += w2 + w3;
            sc[n][0] = w0; sc[n][1] = w1; sc[n][2] = w2; sc[n][3] = w3;
        }

        // ---- MMA2: O += W @ V ; C->A frag mapping is identity (just pack) ----
#pragma unroll
        for (int j2 = 0; j2 < 4; j2++) {
            uint32_t a0 = pack_h2(sc[2 * j2][0],     sc[2 * j2][1]);
            uint32_t a1 = pack_h2(sc[2 * j2][2],     sc[2 * j2][3]);
            uint32_t a2 = pack_h2(sc[2 * j2 + 1][0], sc[2 * j2 + 1][1]);
            uint32_t a3 = pack_h2(sc[2 * j2 + 1][2], sc[2 * j2 + 1][3]);
#pragma unroll
            for (int dn = 0; dn < 8; dn++) {
                uint2 vf = *(const uint2*)&Vf[(dn * 4 + j2) * 64 + 2 * lane];
                mma_f16(outr[dn], a0, a1, a2, a3, vf.x, vf.y);
            }
        }
    }

    // ---- quad-reduce denominators ----
    den0 += __shfl_xor_sync(0xffffffffu, den0, 1);
    den0 += __shfl_xor_sync(0xffffffffu, den0, 2);
    den1 += __shfl_xor_sync(0xffffffffu, den1, 1);
    den1 += __shfl_xor_sync(0xffffffffu, den1, 2);
    float inv0 = 1.0f / den0;
    float inv1 = 1.0f / den1;

    // ---- normalize + store fp16 A-frag words for gemm2 ----
    {
        size_t qb = (size_t)((b * SS + qt * 128 + w * 16) >> 4);
#pragma unroll
        for (int dn = 0; dn < 8; dn++) {
            size_t block = qb * 32 + h * 4 + (dn >> 1);
            int jA = 2 * (dn & 1);
            outaf[block * 128 + lane * 4 + jA]     = pack_h2(outr[dn][0] * inv0, outr[dn][1] * inv0);
            outaf[block * 128 + lane * 4 + jA + 1] = pack_h2(outr[dn][2] * inv1, outr[dn][3] * inv1);
        }
    }
}

// ---------------- launch ----------------
extern "C" void kernel_launch(void* const* d_in, const int* in_sizes, int n_in,
                              void* d_out, int out_size)
{
    const float*         x    = (const float*)d_in[0];
    const unsigned char* mask = (const unsigned char*)d_in[1];
    const float*         rot  = (const float*)d_in[2];
    const float*         Wt   = (const float*)d_in[3];
    const float*         Wo   = (const float*)d_in[4];
    float*               out  = (float*)d_out;

    float *qkv_p;
    uint32_t *attaf_p, *xaf_p, *wtbf_p, *wobf_p;
    cudaGetSymbolAddress((void**)&qkv_p,   g_qkv);
    cudaGetSymbolAddress((void**)&attaf_p, g_attaf);
    cudaGetSymbolAddress((void**)&xaf_p,   g_xaf);
    cudaGetSymbolAddress((void**)&wtbf_p,  g_wtbf);
    cudaGetSymbolAddress((void**)&wobf_p,  g_wobf);

    static const int ATT_SMEM  = 2 * STGW * 4;   // 33,280 B
    static const int GEMM_SMEM = 49152;          // 3 x 16 KB
    cudaFuncSetAttribute(attn_mma_kernel, cudaFuncAttributeMaxDynamicSharedMemorySize, ATT_SMEM);
    cudaFuncSetAttribute(gemm_af_kernel, cudaFuncAttributeMaxDynamicSharedMemorySize, GEMM_SMEM);

    convert_mask_kernel<<<1, 256>>>(mask);

    // round + reorder inputs to fp16 frag layouts (K4 = DIM/4 = 128)
    round_af_kernel<<<(NP * DIM / 4 + 255) / 256, 256>>>((const float4*)x, xaf_p, DIM / 4, NP * DIM / 4);
    round_bf_kernel<<<(ROWQ * DIM / 4 + 255) / 256, 256>>>((const float4*)Wt, wtbf_p, DIM / 4, ROWQ * DIM / 4);
    round_bf_kernel<<<(DIM * DIM / 4 + 255) / 256, 256>>>((const float4*)Wo, wobf_p, DIM / 4, DIM * DIM / 4);

    // qkv = x @ W_trans^T  (fp16 operands, f32 natural output)
    gemm_af_kernel<<<dim3(ROWQ / 128, NP / 128), 256, GEMM_SMEM>>>(xaf_p, wtbf_p, qkv_p, NP, ROWQ, DIM);

    // rotate q,k where masked; round to fp16; emit frag-ordered q/k/v
    rotate_kernel<<<NP, 256>>>(rot);

    // attention -> g_attaf (fp16 A-frag order)
    attn_mma_kernel<<<dim3(SS / 128, BB * NH), 256, ATT_SMEM>>>(attaf_p);

    // out = att @ W_o^T
    gemm_af_kernel<<<dim3(DIM / 128, NP / 128), 256, GEMM_SMEM>>>(attaf_p, wobf_p, out, NP, DIM, DIM);
}

// round 9
// speedup vs baseline: 5.7277x; 1.0313x over previous
#include <cuda_runtime.h>
#include <cuda_fp16.h>
#include <cstdint>

// Problem constants
#define BB   2
#define SS   2048
#define DIM  512
#define NH   8
#define HD   64
#define QK   512          // NH*HD
#define ROWQ 1536         // 2*QK + DIM
#define NP   4096         // B*S positions

// ---------------- scratch ----------------
__device__ float    g_qkv[NP * ROWQ];        // gemm1 output, natural f32
__device__ unsigned short g_qh[NP * QK];     // Q fp16, A-frag order per (b,h)
__device__ unsigned short g_kh[NP * QK];     // K fp16, B-frag order (MMA1)
__device__ unsigned short g_vh[NP * QK];     // V fp16, B-frag order (MMA2)
__device__ uint32_t g_xaf[NP * DIM / 2];     // x fp16 A-frag words
__device__ uint32_t g_wtbf[ROWQ * DIM / 2];  // W_trans fp16 B-frag words
__device__ uint32_t g_wobf[DIM * DIM / 2];   // W_o fp16 B-frag words
__device__ uint32_t g_attaf[NP * DIM / 2];   // attention out fp16 A-frag words
__device__ float    g_mask[NP];              // f32 mask (rotate)
__device__ uint32_t g_mh[BB * SS / 2];       // half2 mask pairs, chunk-frag order

// half2 constants
#define H2_ONE  0x3C003C00u
#define H2_C8   0x30003000u   // 1/8
#define H2_C128 0x20002000u   // 1/128

// ---------------- helpers ----------------
__device__ __forceinline__ uint32_t pack_h2(float lo, float hi) {
    uint32_t r;
    asm("cvt.rn.f16x2.f32 %0, %1, %2;" : "=r"(r) : "f"(hi), "f"(lo));
    return r;
}
__device__ __forceinline__ unsigned short f2h(float f) {
    return __half_as_ushort(__float2half_rn(f));
}
__device__ __forceinline__ uint32_t hfma2(uint32_t a, uint32_t b, uint32_t c) {
    uint32_t d;
    asm("fma.rn.f16x2 %0, %1, %2, %3;" : "=r"(d) : "r"(a), "r"(b), "r"(c));
    return d;
}
__device__ __forceinline__ uint32_t hmul2(uint32_t a, uint32_t b) {
    uint32_t d;
    asm("mul.rn.f16x2 %0, %1, %2;" : "=r"(d) : "r"(a), "r"(b));
    return d;
}
__device__ __forceinline__ uint32_t smem_u32(const void* p) {
    uint32_t a;
    asm("{ .reg .u64 t; cvta.to.shared.u64 t, %1; cvt.u32.u64 %0, t; }" : "=r"(a) : "l"(p));
    return a;
}
__device__ __forceinline__ void cp16(uint32_t dst, const void* src) {
    asm volatile("cp.async.ca.shared.global [%0], [%1], 16;" :: "r"(dst), "l"(src) : "memory");
}
#define CP_COMMIT() asm volatile("cp.async.commit_group;" ::: "memory")
#define CP_WAIT0()  asm volatile("cp.async.wait_group 0;" ::: "memory")
#define CP_WAIT1()  asm volatile("cp.async.wait_group 1;" ::: "memory")

__device__ __forceinline__ void mma_f16(float* c,
    uint32_t a0, uint32_t a1, uint32_t a2, uint32_t a3, uint32_t b0, uint32_t b1)
{
    asm volatile(
        "mma.sync.aligned.m16n8k16.row.col.f32.f16.f16.f32 "
        "{%0,%1,%2,%3}, {%4,%5,%6,%7}, {%8,%9}, {%0,%1,%2,%3};"
        : "+f"(c[0]), "+f"(c[1]), "+f"(c[2]), "+f"(c[3])
        : "r"(a0), "r"(a1), "r"(a2), "r"(a3), "r"(b0), "r"(b1));
}

// half-index helpers for attention operand layouts
__device__ __forceinline__ size_t qh_off(int bh, int s, int d) {
    int lane = 4 * (s & 7) + ((d & 7) >> 1);
    int j = ((s >> 3) & 1) + 2 * ((d >> 3) & 1);
    return (((size_t)bh * 128 + (s >> 4)) * 4 + (d >> 4)) * 256 + lane * 8 + j * 2 + (d & 1);
}
__device__ __forceinline__ size_t kh_off(int bh, int key, int d) {
    return ((((size_t)bh * 32 + (key >> 6)) * 8 + ((key >> 3) & 7)) * 4 + (d >> 4)) * 128
           + (4 * (key & 7) + ((d & 7) >> 1)) * 4 + ((d >> 3) & 1) * 2 + (d & 1);
}
__device__ __forceinline__ size_t vh_off(int bh, int key, int d) {
    int kr = key & 63, kb = kr >> 4, kk = kr & 15;
    return ((((size_t)bh * 32 + (key >> 6)) * 8 + (d >> 3)) * 4 + kb) * 128
           + (4 * (d & 7) + ((kk & 7) >> 1)) * 4 + ((kk >> 3) & 1) * 2 + (kk & 1);
}

// ---------------- fused prep: round/reorder x, Wt, Wo + mask ----------------
__device__ __forceinline__ void emit_af(const float4* __restrict__ src,
                                        uint32_t* __restrict__ dst, int i) {
    float4 v = src[i];
    int r = i >> 7, c0 = (i & 127) * 4;          // K4 = 128
    int rm = r & 15;
    size_t block = (size_t)(r >> 4) * 32 + (c0 >> 4);
    int lane = 4 * (rm & 7) + ((c0 & 7) >> 1);
    int j = (rm >> 3) + 2 * ((c0 >> 3) & 1);
    dst[block * 128 + lane * 4 + j]       = pack_h2(v.x, v.y);
    dst[block * 128 + (lane + 1) * 4 + j] = pack_h2(v.z, v.w);
}
__device__ __forceinline__ void emit_bf(const float4* __restrict__ src,
                                        uint32_t* __restrict__ dst, int i) {
    float4 v = src[i];
    int r = i >> 7, c0 = (i & 127) * 4;
    size_t block = (size_t)(r >> 3) * 32 + (c0 >> 4);
    int lane = 4 * (r & 7) + ((c0 & 7) >> 1);
    int br = (c0 >> 3) & 1;
    dst[block * 64 + lane * 2 + br]       = pack_h2(v.x, v.y);
    dst[block * 64 + (lane + 1) * 2 + br] = pack_h2(v.z, v.w);
}

__global__ void prep_kernel(const float4* __restrict__ x,
                            const unsigned char* __restrict__ mraw,
                            const float4* __restrict__ Wt,
                            const float4* __restrict__ Wo)
{
    const int blk = blockIdx.x, tid = threadIdx.x;
    if (blk < 2048) {                 // x -> A-frag
        emit_af(x, g_xaf, blk * 256 + tid);
    } else if (blk < 2816) {          // Wt -> B-frag
        emit_bf(Wt, g_wtbf, (blk - 2048) * 256 + tid);
    } else if (blk < 3072) {          // Wo -> B-frag
        emit_bf(Wo, g_wobf, (blk - 2816) * 256 + tid);
    } else {                          // mask: f32 + half2-pair frag order
        __shared__ int typ_s;
        if (tid == 0) {
            int t = 1;
            for (int i = 0; i < 512; i++) {
                unsigned char bb = mraw[i];
                if ((i & 3) != 0 && bb != 0) { t = (bb == 0x3f || bb == 0x80) ? 2 : 0; break; }
            }
            typ_s = t;
        }
        __syncthreads();
        int t = typ_s;
        int idx = (blk - 3072) * 256 + tid;      // pair index 0..2047
        int p0 = 2 * idx;
        float m0, m1;
        if (t == 0) {
            m0 = mraw[p0] ? 1.0f : 0.0f; m1 = mraw[p0 + 1] ? 1.0f : 0.0f;
        } else if (t == 1) {
            m0 = (((const int*)mraw)[p0] != 0) ? 1.0f : 0.0f;
            m1 = (((const int*)mraw)[p0 + 1] != 0) ? 1.0f : 0.0f;
        } else {
            m0 = (((const float*)mraw)[p0] != 0.0f) ? 1.0f : 0.0f;
            m1 = (((const float*)mraw)[p0 + 1] != 0.0f) ? 1.0f : 0.0f;
        }
        g_mask[p0] = m0; g_mask[p0 + 1] = m1;
        int b = p0 >> 11, kb = p0 & 2047;
        g_mh[b * 1024 + (kb >> 6) * 32 + ((kb >> 3) & 7) * 4 + ((kb >> 1) & 3)] = pack_h2(m0, m1);
    }
}

// ---------------- fp16 frag-ordered GEMM  C = A @ B^T (3-stage cp.async) ----
__global__ void __launch_bounds__(256, 2) gemm_af_kernel(
    const uint32_t* __restrict__ Aaf, const uint32_t* __restrict__ Bbf,
    float* __restrict__ C, int M, int N, int K)
{
    extern __shared__ uint32_t gsm[];
    const uint32_t sbase = smem_u32(gsm);

    const int tid = threadIdx.x;
    const int w = tid >> 5, lane = tid & 31;
    const int g = lane >> 2, t = lane & 3;
    const int wm = w >> 2, wn = w & 3;
    const int bm = blockIdx.y, bn = blockIdx.x;
    const int K16 = K >> 4;
    const int nst = K >> 5;

    const char* Ab = (const char*)Aaf;
    const char* Bb = (const char*)Bbf;

    auto issue = [&](int s) {
        uint32_t base = sbase + (uint32_t)((s % 3) * 16384);
#pragma unroll
        for (int c = 0; c < 2; c++) {
            int ch = tid * 2 + c;
            int ablk = ch >> 5;
            cp16(base + (uint32_t)(ch * 16),
                 Ab + ((size_t)((bm * 8 + (ablk >> 1)) * K16 + s * 2 + (ablk & 1))) * 512 + (ch & 31) * 16);
            int bblk = ch >> 4;
            cp16(base + 8192u + (uint32_t)(ch * 16),
                 Bb + ((size_t)((bn * 16 + (bblk >> 1)) * K16 + s * 2 + (bblk & 1))) * 256 + (ch & 15) * 16);
        }
        CP_COMMIT();
    };

    float acc[4][4][4];
#pragma unroll
    for (int mf = 0; mf < 4; mf++)
#pragma unroll
        for (int nf = 0; nf < 4; nf++)
#pragma unroll
            for (int c = 0; c < 4; c++) acc[mf][nf][c] = 0.0f;

    issue(0);
    issue(1);

    for (int s = 0; s < nst; s++) {
        if (s + 1 == nst) { CP_WAIT0(); } else { CP_WAIT1(); }
        __syncthreads();
        if (s + 2 < nst) issue(s + 2);

        uint32_t* As = gsm + (s % 3) * 4096;
        uint32_t* Bs = As + 2048;

#pragma unroll
        for (int kb = 0; kb < 2; kb++) {
            uint32_t a[4][4];
#pragma unroll
            for (int mf = 0; mf < 4; mf++) {
                uint4 av = *(const uint4*)&As[((wm * 4 + mf) * 2 + kb) * 128 + 4 * lane];
                a[mf][0] = av.x; a[mf][1] = av.y; a[mf][2] = av.z; a[mf][3] = av.w;
            }
#pragma unroll
            for (int nf = 0; nf < 4; nf++) {
                uint2 bv = *(const uint2*)&Bs[((wn * 4 + nf) * 2 + kb) * 64 + 2 * lane];
#pragma unroll
                for (int mf = 0; mf < 4; mf++)
                    mma_f16(acc[mf][nf], a[mf][0], a[mf][1], a[mf][2], a[mf][3], bv.x, bv.y);
            }
        }
        __syncthreads();
    }

#pragma unroll
    for (int mf = 0; mf < 4; mf++) {
        int row = bm * 128 + wm * 64 + mf * 16 + g;
#pragma unroll
        for (int nf = 0; nf < 4; nf++) {
            int col = bn * 128 + wn * 32 + nf * 8 + 2 * t;
            *(float2*)&C[(size_t)row * N + col]       = make_float2(acc[mf][nf][0], acc[mf][nf][1]);
            *(float2*)&C[(size_t)(row + 8) * N + col] = make_float2(acc[mf][nf][2], acc[mf][nf][3]);
        }
    }
}

// ---------------- rotation + fp16 rounding + frag-ordered q/k/v emission ------
__global__ void __launch_bounds__(256) rotate_kernel(const float* __restrict__ rot)
{
    const int p = blockIdx.x, tid = threadIdx.x;
    const int b = p >> 11, s = p & 2047;
    float* row = &g_qkv[(size_t)p * ROWQ];
    const bool masked = (g_mask[p] != 0.0f);

    if (masked) {
        __shared__ float Rt[64 * 65];
        __shared__ float X[1024];
        const float* R = rot + (size_t)p * 4096;
#pragma unroll
        for (int t2 = 0; t2 < 16; t2++) {
            int idx = tid + 256 * t2;
            int i = idx >> 6, j = idx & 63;
            Rt[j * 65 + i] = R[idx];
        }
#pragma unroll
        for (int t2 = 0; t2 < 4; t2++) {
            int idx = tid + 256 * t2;
            X[idx] = row[idx];
        }
        __syncthreads();

        const int i  = tid & 63;
        const int vb = tid >> 6;
#pragma unroll
        for (int ii = 0; ii < 4; ii++) {
            int vv = vb + 4 * ii;
            float acc = 0.0f;
#pragma unroll 8
            for (int j = 0; j < 64; j++)
                acc = fmaf(Rt[j * 65 + i], X[vv * 64 + j], acc);
            unsigned short hv = f2h(acc);
            if (vv < 8) g_qh[qh_off(b * 8 + vv, s, i)] = hv;
            else        g_kh[kh_off(b * 8 + vv - 8, s, i)] = hv;
        }
    } else {
#pragma unroll
        for (int t2 = 0; t2 < 4; t2++) {
            int idx = tid + 256 * t2;
            unsigned short hv = f2h(row[idx]);
            if (idx < 512) g_qh[qh_off(b * 8 + (idx >> 6), s, idx & 63)] = hv;
            else           g_kh[kh_off(b * 8 + ((idx - 512) >> 6), s, idx & 63)] = hv;
        }
    }
#pragma unroll
    for (int t2 = 0; t2 < 2; t2++) {
        int idx = tid + 256 * t2;
        g_vh[vh_off(b * 8 + (idx >> 6), s, idx & 63)] = f2h(row[1024 + idx]);
    }
}

// ---------------- fp16 mma.sync Taylor attention ----------------
// grid (16 qtiles, 16 bh), 256 thr, 2 CTA/SM. 16 stages of 128 keys.
// Stage smem: K 16KB | V 16KB | mask 256B = 33024B; x2 = 66048B.
#define STGW 8256   // stage words

__global__ void __launch_bounds__(256, 2) attn_mma_kernel(uint32_t* __restrict__ outaf)
{
    extern __shared__ uint32_t sm[];
    const uint32_t sbase = smem_u32(sm);

    const int tid = threadIdx.x;
    const int w = tid >> 5, lane = tid & 31;
    const int t = lane & 3;
    const int qt = blockIdx.x, bh = blockIdx.y;
    const int b = bh >> 3, h = bh & 7;

    // ---- Q fragments in registers ----
    uint32_t qa[4][4];
    {
        int qblk = qt * 8 + w;
        const uint4* qp = reinterpret_cast<const uint4*>(g_qh)
                          + (((size_t)bh * 128 + qblk) * 4) * 32 + lane;
#pragma unroll
        for (int k16 = 0; k16 < 4; k16++) {
            uint4 v = qp[k16 * 32];
            qa[k16][0] = v.x; qa[k16][1] = v.y; qa[k16][2] = v.z; qa[k16][3] = v.w;
        }
    }

    const char* kbase = (const char*)(g_kh + (size_t)bh * 32 * 4096);
    const char* vbase = (const char*)(g_vh + (size_t)bh * 32 * 4096);
    const char* mbase = (const char*)(g_mh + b * 1024);

    auto issue_stage = [&](int s) {
        const uint32_t dstb = sbase + (uint32_t)((s & 1) * STGW * 4);
        const char* ks = kbase + (size_t)s * 16384;
        const char* vs = vbase + (size_t)s * 16384;
#pragma unroll
        for (int c = 0; c < 4; c++) {
            int ch = tid * 4 + c;               // 0..1023
            cp16(dstb + (uint32_t)(ch * 16), ks + ch * 16);
            cp16(dstb + 16384u + (uint32_t)(ch * 16), vs + ch * 16);
        }
        if (tid < 16)
            cp16(dstb + 32768u + (uint32_t)(tid * 16), mbase + s * 256 + tid * 16);
        CP_COMMIT();
    };

    float outr[8][4];
#pragma unroll
    for (int n = 0; n < 8; n++)
#pragma unroll
        for (int j = 0; j < 4; j++) outr[n][j] = 0.0f;
    float dacc[4] = {0.0f, 0.0f, 0.0f, 0.0f};

    issue_stage(0);

    for (int s = 0; s < 16; s++) {
        CP_WAIT0();
        __syncthreads();
        if (s + 1 < 16) issue_stage(s + 1);

        uint32_t* base = sm + (s & 1) * STGW;

#pragma unroll
        for (int h2 = 0; h2 < 2; h2++) {
            uint32_t* Kf = base + h2 * 2048;
            uint32_t* Vf = base + 4096 + h2 * 2048;
            const uint32_t* mh = base + 8192 + h2 * 32;

            // ---- MMA1: S[16 q, 64 keys] = Q @ K^T ----
            float sc[8][4];
#pragma unroll
            for (int n = 0; n < 8; n++)
#pragma unroll
                for (int j = 0; j < 4; j++) sc[n][j] = 0.0f;

#pragma unroll
            for (int k16 = 0; k16 < 4; k16++) {
#pragma unroll
                for (int n = 0; n < 8; n++) {
                    uint2 kf = *(const uint2*)&Kf[(n * 4 + k16) * 64 + 2 * lane];
                    mma_f16(sc[n], qa[k16][0], qa[k16][1], qa[k16][2], qa[k16][3], kf.x, kf.y);
                }
            }

            // ---- Taylor weights in half2: w = fma(s, fma(s,1/128,1/8), 1) * m ----
            uint32_t wpA[8], wpB[8];
#pragma unroll
            for (int n = 0; n < 8; n++) {
                uint32_t m2 = mh[n * 4 + t];
                uint32_t sA = pack_h2(sc[n][0], sc[n][1]);
                uint32_t sB = pack_h2(sc[n][2], sc[n][3]);
                wpA[n] = hmul2(hfma2(sA, hfma2(sA, H2_C128, H2_C8), H2_ONE), m2);
                wpB[n] = hmul2(hfma2(sB, hfma2(sB, H2_C128, H2_C8), H2_ONE), m2);
            }

            // ---- MMA2: O += W @ V ; den += W @ ones (constant B-frag) ----
#pragma unroll
            for (int j2 = 0; j2 < 4; j2++) {
                uint32_t a0 = wpA[2 * j2], a1 = wpB[2 * j2];
                uint32_t a2 = wpA[2 * j2 + 1], a3 = wpB[2 * j2 + 1];
                mma_f16(dacc, a0, a1, a2, a3, H2_ONE, H2_ONE);
#pragma unroll
                for (int dn = 0; dn < 8; dn++) {
                    uint2 vf = *(const uint2*)&Vf[(dn * 4 + j2) * 64 + 2 * lane];
                    mma_f16(outr[dn], a0, a1, a2, a3, vf.x, vf.y);
                }
            }
        }
    }

    // den per lane: dacc[0] = rowA sum, dacc[2] = rowB sum (all n-cols identical)
    float inv0 = 1.0f / dacc[0];
    float inv1 = 1.0f / dacc[2];

    // ---- normalize + store fp16 A-frag words for gemm2 ----
    {
        size_t qb = (size_t)((b * SS + qt * 128 + w * 16) >> 4);
#pragma unroll
        for (int dn = 0; dn < 8; dn++) {
            size_t block = qb * 32 + h * 4 + (dn >> 1);
            int jA = 2 * (dn & 1);
            outaf[block * 128 + lane * 4 + jA]     = pack_h2(outr[dn][0] * inv0, outr[dn][1] * inv0);
            outaf[block * 128 + lane * 4 + jA + 1] = pack_h2(outr[dn][2] * inv1, outr[dn][3] * inv1);
        }
    }
}

// ---------------- launch ----------------
extern "C" void kernel_launch(void* const* d_in, const int* in_sizes, int n_in,
                              void* d_out, int out_size)
{
    const float*         x    = (const float*)d_in[0];
    const unsigned char* mask = (const unsigned char*)d_in[1];
    const float*         rot  = (const float*)d_in[2];
    const float*         Wt   = (const float*)d_in[3];
    const float*         Wo   = (const float*)d_in[4];
    float*               out  = (float*)d_out;

    float *qkv_p;
    uint32_t *attaf_p, *xaf_p, *wtbf_p, *wobf_p;
    cudaGetSymbolAddress((void**)&qkv_p,   g_qkv);
    cudaGetSymbolAddress((void**)&attaf_p, g_attaf);
    cudaGetSymbolAddress((void**)&xaf_p,   g_xaf);
    cudaGetSymbolAddress((void**)&wtbf_p,  g_wtbf);
    cudaGetSymbolAddress((void**)&wobf_p,  g_wobf);

    static const int ATT_SMEM  = 2 * STGW * 4;   // 66,048 B
    static const int GEMM_SMEM = 49152;
    cudaFuncSetAttribute(attn_mma_kernel, cudaFuncAttributeMaxDynamicSharedMemorySize, ATT_SMEM);
    cudaFuncSetAttribute(gemm_af_kernel, cudaFuncAttributeMaxDynamicSharedMemorySize, GEMM_SMEM);

    // fused prep: x->af, Wt->bf, Wo->bf, mask (f32 + half2 frag order)
    prep_kernel<<<3080, 256>>>((const float4*)x, mask, (const float4*)Wt, (const float4*)Wo);

    // qkv = x @ W_trans^T
    gemm_af_kernel<<<dim3(ROWQ / 128, NP / 128), 256, GEMM_SMEM>>>(xaf_p, wtbf_p, qkv_p, NP, ROWQ, DIM);

    // rotate q,k where masked; round to fp16; emit frag-ordered q/k/v
    rotate_kernel<<<NP, 256>>>(rot);

    // attention -> g_attaf (fp16 A-frag order)
    attn_mma_kernel<<<dim3(SS / 128, BB * NH), 256, ATT_SMEM>>>(attaf_p);

    // out = att @ W_o^T
    gemm_af_kernel<<<dim3(DIM / 128, NP / 128), 256, GEMM_SMEM>>>(attaf_p, wobf_p, out, NP, DIM, DIM);
}

// round 10
// speedup vs baseline: 6.8750x; 1.2003x over previous
#include <cuda_runtime.h>
#include <cuda_fp16.h>
#include <cstdint>

// Problem constants
#define BB   2
#define SS   2048
#define DIM  512
#define NH   8
#define HD   64
#define QK   512          // NH*HD
#define ROWQ 1536         // 2*QK + DIM
#define NP   4096         // B*S positions

// ---------------- scratch ----------------
__device__ float    g_qkv[NP * ROWQ];        // gemm1 output, natural f32
__device__ unsigned short g_qh[NP * QK];     // Q fp16, A-frag order per (b,h)
__device__ unsigned short g_kh[NP * QK];     // K fp16, B-frag order, COMPACTED keys
__device__ unsigned short g_vh[NP * QK];     // V fp16, B-frag order, COMPACTED keys
__device__ uint32_t g_xaf[NP * DIM / 2];     // x fp16 A-frag words
__device__ uint32_t g_wtbf[ROWQ * DIM / 2];  // W_trans fp16 B-frag words
__device__ uint32_t g_wobf[DIM * DIM / 2];   // W_o fp16 B-frag words
__device__ uint32_t g_attaf[NP * DIM / 2];   // attention out fp16 A-frag words
__device__ float    g_mask[NP];              // f32 mask (rotate branch)
__device__ int      g_cidx[NP];              // compacted key index (valid where mask!=0)
__device__ int      g_nkeys[BB];             // live keys per batch

// half2 constants
#define H2_ONE  0x3C003C00u
#define H2_C8   0x30003000u   // 1/8
#define H2_C128 0x20002000u   // 1/128

// ---------------- helpers ----------------
__device__ __forceinline__ uint32_t pack_h2(float lo, float hi) {
    uint32_t r;
    asm("cvt.rn.f16x2.f32 %0, %1, %2;" : "=r"(r) : "f"(hi), "f"(lo));
    return r;
}
__device__ __forceinline__ unsigned short f2h(float f) {
    return __half_as_ushort(__float2half_rn(f));
}
__device__ __forceinline__ uint32_t hfma2(uint32_t a, uint32_t b, uint32_t c) {
    uint32_t d;
    asm("fma.rn.f16x2 %0, %1, %2, %3;" : "=r"(d) : "r"(a), "r"(b), "r"(c));
    return d;
}
__device__ __forceinline__ uint32_t smem_u32(const void* p) {
    uint32_t a;
    asm("{ .reg .u64 t; cvta.to.shared.u64 t, %1; cvt.u32.u64 %0, t; }" : "=r"(a) : "l"(p));
    return a;
}
__device__ __forceinline__ void cp16(uint32_t dst, const void* src) {
    asm volatile("cp.async.ca.shared.global [%0], [%1], 16;" :: "r"(dst), "l"(src) : "memory");
}
#define CP_COMMIT() asm volatile("cp.async.commit_group;" ::: "memory")
#define CP_WAIT0()  asm volatile("cp.async.wait_group 0;" ::: "memory")
#define CP_WAIT1()  asm volatile("cp.async.wait_group 1;" ::: "memory")

__device__ __forceinline__ void mma_f16(float* c,
    uint32_t a0, uint32_t a1, uint32_t a2, uint32_t a3, uint32_t b0, uint32_t b1)
{
    asm volatile(
        "mma.sync.aligned.m16n8k16.row.col.f32.f16.f16.f32 "
        "{%0,%1,%2,%3}, {%4,%5,%6,%7}, {%8,%9}, {%0,%1,%2,%3};"
        : "+f"(c[0]), "+f"(c[1]), "+f"(c[2]), "+f"(c[3])
        : "r"(a0), "r"(a1), "r"(a2), "r"(a3), "r"(b0), "r"(b1));
}

// half-index helpers for attention operand layouts
__device__ __forceinline__ size_t qh_off(int bh, int s, int d) {
    int lane = 4 * (s & 7) + ((d & 7) >> 1);
    int j = ((s >> 3) & 1) + 2 * ((d >> 3) & 1);
    return (((size_t)bh * 128 + (s >> 4)) * 4 + (d >> 4)) * 256 + lane * 8 + j * 2 + (d & 1);
}
__device__ __forceinline__ size_t kh_off(int bh, int key, int d) {
    return ((((size_t)bh * 32 + (key >> 6)) * 8 + ((key >> 3) & 7)) * 4 + (d >> 4)) * 128
           + (4 * (key & 7) + ((d & 7) >> 1)) * 4 + ((d >> 3) & 1) * 2 + (d & 1);
}
__device__ __forceinline__ size_t vh_off(int bh, int key, int d) {
    int kr = key & 63, kb = kr >> 4, kk = kr & 15;
    return ((((size_t)bh * 32 + (key >> 6)) * 8 + (d >> 3)) * 4 + kb) * 128
           + (4 * (d & 7) + ((kk & 7) >> 1)) * 4 + ((kk >> 3) & 1) * 2 + (kk & 1);
}

// ---------------- fused prep: round/reorder x, Wt, Wo + mask scan ----------------
__device__ __forceinline__ void emit_af(const float4* __restrict__ src,
                                        uint32_t* __restrict__ dst, int i) {
    float4 v = src[i];
    int r = i >> 7, c0 = (i & 127) * 4;          // K4 = 128
    int rm = r & 15;
    size_t block = (size_t)(r >> 4) * 32 + (c0 >> 4);
    int lane = 4 * (rm & 7) + ((c0 & 7) >> 1);
    int j = (rm >> 3) + 2 * ((c0 >> 3) & 1);
    dst[block * 128 + lane * 4 + j]       = pack_h2(v.x, v.y);
    dst[block * 128 + (lane + 1) * 4 + j] = pack_h2(v.z, v.w);
}
__device__ __forceinline__ void emit_bf(const float4* __restrict__ src,
                                        uint32_t* __restrict__ dst, int i) {
    float4 v = src[i];
    int r = i >> 7, c0 = (i & 127) * 4;
    size_t block = (size_t)(r >> 3) * 32 + (c0 >> 4);
    int lane = 4 * (r & 7) + ((c0 & 7) >> 1);
    int br = (c0 >> 3) & 1;
    dst[block * 64 + lane * 2 + br]       = pack_h2(v.x, v.y);
    dst[block * 64 + (lane + 1) * 2 + br] = pack_h2(v.z, v.w);
}

__global__ void prep_kernel(const float4* __restrict__ x,
                            const unsigned char* __restrict__ mraw,
                            const float4* __restrict__ Wt,
                            const float4* __restrict__ Wo)
{
    const int blk = blockIdx.x, tid = threadIdx.x;
    if (blk < 2048) {                 // x -> A-frag
        emit_af(x, g_xaf, blk * 256 + tid);
    } else if (blk < 2816) {          // Wt -> B-frag
        emit_bf(Wt, g_wtbf, (blk - 2048) * 256 + tid);
    } else if (blk < 3072) {          // Wo -> B-frag
        emit_bf(Wo, g_wobf, (blk - 2816) * 256 + tid);
    } else {                          // mask sniff + per-batch compaction scan
        const int bb = blk - 3072;    // batch 0/1
        __shared__ int typ_s;
        __shared__ int wsum[8];
        if (tid == 0) {
            int t = 1;
            for (int i = 0; i < 512; i++) {
                unsigned char c = mraw[i];
                if ((i & 3) != 0 && c != 0) { t = (c == 0x3f || c == 0x80) ? 2 : 0; break; }
            }
            typ_s = t;
        }
        __syncthreads();
        const int t = typ_s;
        const int base = bb * SS;
        const int p0 = tid * 8;
        float mv[8];
        int cnt = 0;
#pragma unroll
        for (int i = 0; i < 8; i++) {
            int p = base + p0 + i;
            float m;
            if (t == 0)      m = mraw[p] ? 1.0f : 0.0f;
            else if (t == 1) m = (((const int*)mraw)[p] != 0) ? 1.0f : 0.0f;
            else             m = (((const float*)mraw)[p] != 0.0f) ? 1.0f : 0.0f;
            mv[i] = m;
            cnt += (m != 0.0f);
        }
        // inclusive warp scan of cnt
        const int lane = tid & 31, wid = tid >> 5;
        int xs = cnt;
#pragma unroll
        for (int o = 1; o < 32; o <<= 1) {
            int y = __shfl_up_sync(0xffffffffu, xs, o);
            if (lane >= o) xs += y;
        }
        if (lane == 31) wsum[wid] = xs;
        __syncthreads();
        if (tid == 0) {
            int a = 0;
#pragma unroll
            for (int ww = 0; ww < 8; ww++) { int tt = wsum[ww]; wsum[ww] = a; a += tt; }
            g_nkeys[bb] = a;
        }
        __syncthreads();
        int c = xs - cnt + wsum[wid];   // exclusive prefix for this thread
#pragma unroll
        for (int i = 0; i < 8; i++) {
            int p = base + p0 + i;
            g_mask[p] = mv[i];
            if (mv[i] != 0.0f) g_cidx[p] = c++;
        }
    }
}

// ---------------- fp16 frag-ordered GEMM  C = A @ B^T (3-stage cp.async) ----
__global__ void __launch_bounds__(256, 2) gemm_af_kernel(
    const uint32_t* __restrict__ Aaf, const uint32_t* __restrict__ Bbf,
    float* __restrict__ C, int M, int N, int K)
{
    extern __shared__ uint32_t gsm[];
    const uint32_t sbase = smem_u32(gsm);

    const int tid = threadIdx.x;
    const int w = tid >> 5, lane = tid & 31;
    const int g = lane >> 2, t = lane & 3;
    const int wm = w >> 2, wn = w & 3;
    const int bm = blockIdx.y, bn = blockIdx.x;
    const int K16 = K >> 4;
    const int nst = K >> 5;

    const char* Ab = (const char*)Aaf;
    const char* Bb = (const char*)Bbf;

    auto issue = [&](int s) {
        uint32_t base = sbase + (uint32_t)((s % 3) * 16384);
#pragma unroll
        for (int c = 0; c < 2; c++) {
            int ch = tid * 2 + c;
            int ablk = ch >> 5;
            cp16(base + (uint32_t)(ch * 16),
                 Ab + ((size_t)((bm * 8 + (ablk >> 1)) * K16 + s * 2 + (ablk & 1))) * 512 + (ch & 31) * 16);
            int bblk = ch >> 4;
            cp16(base + 8192u + (uint32_t)(ch * 16),
                 Bb + ((size_t)((bn * 16 + (bblk >> 1)) * K16 + s * 2 + (bblk & 1))) * 256 + (ch & 15) * 16);
        }
        CP_COMMIT();
    };

    float acc[4][4][4];
#pragma unroll
    for (int mf = 0; mf < 4; mf++)
#pragma unroll
        for (int nf = 0; nf < 4; nf++)
#pragma unroll
            for (int c = 0; c < 4; c++) acc[mf][nf][c] = 0.0f;

    issue(0);
    issue(1);

    for (int s = 0; s < nst; s++) {
        if (s + 1 == nst) { CP_WAIT0(); } else { CP_WAIT1(); }
        __syncthreads();
        if (s + 2 < nst) issue(s + 2);

        uint32_t* As = gsm + (s % 3) * 4096;
        uint32_t* Bs = As + 2048;

#pragma unroll
        for (int kb = 0; kb < 2; kb++) {
            uint32_t a[4][4];
#pragma unroll
            for (int mf = 0; mf < 4; mf++) {
                uint4 av = *(const uint4*)&As[((wm * 4 + mf) * 2 + kb) * 128 + 4 * lane];
                a[mf][0] = av.x; a[mf][1] = av.y; a[mf][2] = av.z; a[mf][3] = av.w;
            }
#pragma unroll
            for (int nf = 0; nf < 4; nf++) {
                uint2 bv = *(const uint2*)&Bs[((wn * 4 + nf) * 2 + kb) * 64 + 2 * lane];
#pragma unroll
                for (int mf = 0; mf < 4; mf++)
                    mma_f16(acc[mf][nf], a[mf][0], a[mf][1], a[mf][2], a[mf][3], bv.x, bv.y);
            }
        }
        __syncthreads();
    }

#pragma unroll
    for (int mf = 0; mf < 4; mf++) {
        int row = bm * 128 + wm * 64 + mf * 16 + g;
#pragma unroll
        for (int nf = 0; nf < 4; nf++) {
            int col = bn * 128 + wn * 32 + nf * 8 + 2 * t;
            *(float2*)&C[(size_t)row * N + col]       = make_float2(acc[mf][nf][0], acc[mf][nf][1]);
            *(float2*)&C[(size_t)(row + 8) * N + col] = make_float2(acc[mf][nf][2], acc[mf][nf][3]);
        }
    }
}

// ---------------- rotation + fp16 rounding + COMPACTED frag-ordered k/v ------
__global__ void __launch_bounds__(256) rotate_kernel(const float* __restrict__ rot)
{
    const int p = blockIdx.x, tid = threadIdx.x;
    const int b = p >> 11, s = p & 2047;
    float* row = &g_qkv[(size_t)p * ROWQ];
    const bool masked = (g_mask[p] != 0.0f);

    if (masked) {
        const int c = g_cidx[p];
        __shared__ float Rt[64 * 65];
        __shared__ float X[1024];
        const float* R = rot + (size_t)p * 4096;
#pragma unroll
        for (int t2 = 0; t2 < 16; t2++) {
            int idx = tid + 256 * t2;
            int i = idx >> 6, j = idx & 63;
            Rt[j * 65 + i] = R[idx];
        }
#pragma unroll
        for (int t2 = 0; t2 < 4; t2++) {
            int idx = tid + 256 * t2;
            X[idx] = row[idx];
        }
        __syncthreads();

        const int i  = tid & 63;
        const int vb = tid >> 6;
#pragma unroll
        for (int ii = 0; ii < 4; ii++) {
            int vv = vb + 4 * ii;
            float acc = 0.0f;
#pragma unroll 8
            for (int j = 0; j < 64; j++)
                acc = fmaf(Rt[j * 65 + i], X[vv * 64 + j], acc);
            unsigned short hv = f2h(acc);
            if (vv < 8) g_qh[qh_off(b * 8 + vv, s, i)] = hv;
            else        g_kh[kh_off(b * 8 + vv - 8, c, i)] = hv;
        }
        // v: only live keys matter
#pragma unroll
        for (int t2 = 0; t2 < 2; t2++) {
            int idx = tid + 256 * t2;
            g_vh[vh_off(b * 8 + (idx >> 6), c, idx & 63)] = f2h(row[1024 + idx]);
        }
    } else {
        // only q survives; k/v dropped (weight would be 0)
#pragma unroll
        for (int t2 = 0; t2 < 2; t2++) {
            int idx = tid + 256 * t2;     // 0..511
            g_qh[qh_off(b * 8 + (idx >> 6), s, idx & 63)] = f2h(row[idx]);
        }
    }
}

// ---------------- fp16 mma.sync Taylor attention over compacted keys ----------
// grid (16 qtiles, 16 bh), 256 thr, 2 CTA/SM. ceil(N/128) stages of 128 keys.
#define STGW 8192   // stage words: K 16KB | V 16KB

__global__ void __launch_bounds__(256, 2) attn_mma_kernel(uint32_t* __restrict__ outaf)
{
    extern __shared__ uint32_t sm[];
    const uint32_t sbase = smem_u32(sm);

    const int tid = threadIdx.x;
    const int w = tid >> 5, lane = tid & 31;
    const int t = lane & 3;
    const int qt = blockIdx.x, bh = blockIdx.y;
    const int b = bh >> 3, h = bh & 7;
    const int N = g_nkeys[b];
    const int nst = (N + 127) >> 7;

    // ---- Q fragments in registers ----
    uint32_t qa[4][4];
    {
        int qblk = qt * 8 + w;
        const uint4* qp = reinterpret_cast<const uint4*>(g_qh)
                          + (((size_t)bh * 128 + qblk) * 4) * 32 + lane;
#pragma unroll
        for (int k16 = 0; k16 < 4; k16++) {
            uint4 v = qp[k16 * 32];
            qa[k16][0] = v.x; qa[k16][1] = v.y; qa[k16][2] = v.z; qa[k16][3] = v.w;
        }
    }

    const char* kbase = (const char*)(g_kh + (size_t)bh * 32 * 4096);
    const char* vbase = (const char*)(g_vh + (size_t)bh * 32 * 4096);

    auto issue_stage = [&](int s) {
        const uint32_t dstb = sbase + (uint32_t)((s & 1) * STGW * 4);
        const char* ks = kbase + (size_t)s * 16384;
        const char* vs = vbase + (size_t)s * 16384;
#pragma unroll
        for (int c = 0; c < 4; c++) {
            int ch = tid * 4 + c;               // 0..1023
            cp16(dstb + (uint32_t)(ch * 16), ks + ch * 16);
            cp16(dstb + 16384u + (uint32_t)(ch * 16), vs + ch * 16);
        }
        CP_COMMIT();
    };

    float outr[8][4];
#pragma unroll
    for (int n = 0; n < 8; n++)
#pragma unroll
        for (int j = 0; j < 4; j++) outr[n][j] = 0.0f;
    float dacc[4] = {0.0f, 0.0f, 0.0f, 0.0f};

    issue_stage(0);

    for (int s = 0; s < nst; s++) {
        CP_WAIT0();
        __syncthreads();
        if (s + 1 < nst) issue_stage(s + 1);

        uint32_t* base = sm + (s & 1) * STGW;
        const bool needmask = ((s + 1) * 128 > N);

#pragma unroll
        for (int h2 = 0; h2 < 2; h2++) {
            uint32_t* Kf = base + h2 * 2048;
            uint32_t* Vf = base + 4096 + h2 * 2048;

            // ---- MMA1: S[16 q, 64 keys] = Q @ K^T ----
            float sc[8][4];
#pragma unroll
            for (int n = 0; n < 8; n++)
#pragma unroll
                for (int j = 0; j < 4; j++) sc[n][j] = 0.0f;

#pragma unroll
            for (int k16 = 0; k16 < 4; k16++) {
#pragma unroll
                for (int n = 0; n < 8; n++) {
                    uint2 kf = *(const uint2*)&Kf[(n * 4 + k16) * 64 + 2 * lane];
                    mma_f16(sc[n], qa[k16][0], qa[k16][1], qa[k16][2], qa[k16][3], kf.x, kf.y);
                }
            }

            // ---- Taylor weights in half2: w = fma(s, fma(s,1/128,1/8), 1) ----
            uint32_t wpA[8], wpB[8];
#pragma unroll
            for (int n = 0; n < 8; n++) {
                uint32_t sA = pack_h2(sc[n][0], sc[n][1]);
                uint32_t sB = pack_h2(sc[n][2], sc[n][3]);
                wpA[n] = hfma2(sA, hfma2(sA, H2_C128, H2_C8), H2_ONE);
                wpB[n] = hfma2(sB, hfma2(sB, H2_C128, H2_C8), H2_ONE);
                if (needmask) {
                    int k0 = s * 128 + h2 * 64 + n * 8 + 2 * t;
                    uint32_t mm = (k0 < N ? 0x0000FFFFu : 0u) | (k0 + 1 < N ? 0xFFFF0000u : 0u);
                    wpA[n] &= mm;
                    wpB[n] &= mm;
                }
            }

            // ---- MMA2: O += W @ V ; den += W @ ones ----
#pragma unroll
            for (int j2 = 0; j2 < 4; j2++) {
                uint32_t a0 = wpA[2 * j2], a1 = wpB[2 * j2];
                uint32_t a2 = wpA[2 * j2 + 1], a3 = wpB[2 * j2 + 1];
                mma_f16(dacc, a0, a1, a2, a3, H2_ONE, H2_ONE);
#pragma unroll
                for (int dn = 0; dn < 8; dn++) {
                    uint2 vf = *(const uint2*)&Vf[(dn * 4 + j2) * 64 + 2 * lane];
                    mma_f16(outr[dn], a0, a1, a2, a3, vf.x, vf.y);
                }
            }
        }
    }

    float inv0 = 1.0f / dacc[0];
    float inv1 = 1.0f / dacc[2];

    // ---- normalize + store fp16 A-frag words for gemm2 ----
    {
        size_t qb = (size_t)((b * SS + qt * 128 + w * 16) >> 4);
#pragma unroll
        for (int dn = 0; dn < 8; dn++) {
            size_t block = qb * 32 + h * 4 + (dn >> 1);
            int jA = 2 * (dn & 1);
            outaf[block * 128 + lane * 4 + jA]     = pack_h2(outr[dn][0] * inv0, outr[dn][1] * inv0);
            outaf[block * 128 + lane * 4 + jA + 1] = pack_h2(outr[dn][2] * inv1, outr[dn][3] * inv1);
        }
    }
}

// ---------------- launch ----------------
extern "C" void kernel_launch(void* const* d_in, const int* in_sizes, int n_in,
                              void* d_out, int out_size)
{
    const float*         x    = (const float*)d_in[0];
    const unsigned char* mask = (const unsigned char*)d_in[1];
    const float*         rot  = (const float*)d_in[2];
    const float*         Wt   = (const float*)d_in[3];
    const float*         Wo   = (const float*)d_in[4];
    float*               out  = (float*)d_out;

    float *qkv_p;
    uint32_t *attaf_p, *xaf_p, *wtbf_p, *wobf_p;
    cudaGetSymbolAddress((void**)&qkv_p,   g_qkv);
    cudaGetSymbolAddress((void**)&attaf_p, g_attaf);
    cudaGetSymbolAddress((void**)&xaf_p,   g_xaf);
    cudaGetSymbolAddress((void**)&wtbf_p,  g_wtbf);
    cudaGetSymbolAddress((void**)&wobf_p,  g_wobf);

    static const int ATT_SMEM  = 2 * STGW * 4;   // 65,536 B
    static const int GEMM_SMEM = 49152;
    cudaFuncSetAttribute(attn_mma_kernel, cudaFuncAttributeMaxDynamicSharedMemorySize, ATT_SMEM);
    cudaFuncSetAttribute(gemm_af_kernel, cudaFuncAttributeMaxDynamicSharedMemorySize, GEMM_SMEM);

    // fused prep: x->af, Wt->bf, Wo->bf, mask sniff + compaction scan
    prep_kernel<<<3074, 256>>>((const float4*)x, mask, (const float4*)Wt, (const float4*)Wo);

    // qkv = x @ W_trans^T
    gemm_af_kernel<<<dim3(ROWQ / 128, NP / 128), 256, GEMM_SMEM>>>(xaf_p, wtbf_p, qkv_p, NP, ROWQ, DIM);

    // rotate q,k where masked; emit frag-ordered q + COMPACTED k/v
    rotate_kernel<<<NP, 256>>>(rot);

    // attention over compacted keys -> g_attaf
    attn_mma_kernel<<<dim3(SS / 128, BB * NH), 256, ATT_SMEM>>>(attaf_p);

    // out = att @ W_o^T
    gemm_af_kernel<<<dim3(DIM / 128, NP / 128), 256, GEMM_SMEM>>>(attaf_p, wobf_p, out, NP, DIM, DIM);
}

// round 11
// speedup vs baseline: 7.7980x; 1.1343x over previous
#include <cuda_runtime.h>
#include <cuda_fp16.h>
#include <cstdint>

// Problem constants
#define BB   2
#define SS   2048
#define DIM  512
#define NH   8
#define HD   64
#define QK   512          // NH*HD
#define ROWQ 1536         // 2*QK + DIM
#define NP   4096         // B*S positions

// ---------------- scratch ----------------
__device__ float    g_qkv[NP * ROWQ];        // gemm1 output, natural f32
__device__ unsigned short g_qh[NP * QK];     // Q fp16, A-frag order per (b,h)
__device__ unsigned short g_kh[NP * QK];     // K fp16, B-frag order, COMPACTED keys
__device__ unsigned short g_vh[NP * QK];     // V fp16, B-frag order, COMPACTED keys
__device__ uint32_t g_xaf[NP * DIM / 2];     // x fp16 A-frag words
__device__ uint32_t g_wtbf[ROWQ * DIM / 2];  // W_trans fp16 B-frag words
__device__ uint32_t g_wobf[DIM * DIM / 2];   // W_o fp16 B-frag words
__device__ uint32_t g_attaf[NP * DIM / 2];   // attention out fp16 A-frag words
__device__ float    g_mask[NP];              // f32 mask (rotate branch)
__device__ int      g_cidx[NP];              // compacted key index (valid where mask!=0)
__device__ int      g_nkeys[BB];             // live keys per batch

// half2 constants
#define H2_ONE  0x3C003C00u
#define H2_C8   0x30003000u   // 1/8
#define H2_C128 0x20002000u   // 1/128

// ---------------- helpers ----------------
__device__ __forceinline__ uint32_t pack_h2(float lo, float hi) {
    uint32_t r;
    asm("cvt.rn.f16x2.f32 %0, %1, %2;" : "=r"(r) : "f"(hi), "f"(lo));
    return r;
}
__device__ __forceinline__ unsigned short f2h(float f) {
    return __half_as_ushort(__float2half_rn(f));
}
__device__ __forceinline__ uint32_t hfma2(uint32_t a, uint32_t b, uint32_t c) {
    uint32_t d;
    asm("fma.rn.f16x2 %0, %1, %2, %3;" : "=r"(d) : "r"(a), "r"(b), "r"(c));
    return d;
}
__device__ __forceinline__ uint32_t smem_u32(const void* p) {
    uint32_t a;
    asm("{ .reg .u64 t; cvta.to.shared.u64 t, %1; cvt.u32.u64 %0, t; }" : "=r"(a) : "l"(p));
    return a;
}
__device__ __forceinline__ void cp16(uint32_t dst, const void* src) {
    asm volatile("cp.async.ca.shared.global [%0], [%1], 16;" :: "r"(dst), "l"(src) : "memory");
}
#define CP_COMMIT() asm volatile("cp.async.commit_group;" ::: "memory")
#define CP_WAIT0()  asm volatile("cp.async.wait_group 0;" ::: "memory")
#define CP_WAIT1()  asm volatile("cp.async.wait_group 1;" ::: "memory")

__device__ __forceinline__ void mma_f16(float* c,
    uint32_t a0, uint32_t a1, uint32_t a2, uint32_t a3, uint32_t b0, uint32_t b1)
{
    asm volatile(
        "mma.sync.aligned.m16n8k16.row.col.f32.f16.f16.f32 "
        "{%0,%1,%2,%3}, {%4,%5,%6,%7}, {%8,%9}, {%0,%1,%2,%3};"
        : "+f"(c[0]), "+f"(c[1]), "+f"(c[2]), "+f"(c[3])
        : "r"(a0), "r"(a1), "r"(a2), "r"(a3), "r"(b0), "r"(b1));
}

// half-index helpers for attention operand layouts
__device__ __forceinline__ size_t qh_off(int bh, int s, int d) {
    int lane = 4 * (s & 7) + ((d & 7) >> 1);
    int j = ((s >> 3) & 1) + 2 * ((d >> 3) & 1);
    return (((size_t)bh * 128 + (s >> 4)) * 4 + (d >> 4)) * 256 + lane * 8 + j * 2 + (d & 1);
}
__device__ __forceinline__ size_t kh_off(int bh, int key, int d) {
    return ((((size_t)bh * 32 + (key >> 6)) * 8 + ((key >> 3) & 7)) * 4 + (d >> 4)) * 128
           + (4 * (key & 7) + ((d & 7) >> 1)) * 4 + ((d >> 3) & 1) * 2 + (d & 1);
}
__device__ __forceinline__ size_t vh_off(int bh, int key, int d) {
    int kr = key & 63, kb = kr >> 4, kk = kr & 15;
    return ((((size_t)bh * 32 + (key >> 6)) * 8 + (d >> 3)) * 4 + kb) * 128
           + (4 * (d & 7) + ((kk & 7) >> 1)) * 4 + ((kk >> 3) & 1) * 2 + (kk & 1);
}

// ---------------- fused prep: round/reorder x, Wt, Wo + mask scan ----------------
__device__ __forceinline__ void emit_af(const float4* __restrict__ src,
                                        uint32_t* __restrict__ dst, int i) {
    float4 v = src[i];
    int r = i >> 7, c0 = (i & 127) * 4;          // K4 = 128
    int rm = r & 15;
    size_t block = (size_t)(r >> 4) * 32 + (c0 >> 4);
    int lane = 4 * (rm & 7) + ((c0 & 7) >> 1);
    int j = (rm >> 3) + 2 * ((c0 >> 3) & 1);
    dst[block * 128 + lane * 4 + j]       = pack_h2(v.x, v.y);
    dst[block * 128 + (lane + 1) * 4 + j] = pack_h2(v.z, v.w);
}
__device__ __forceinline__ void emit_bf(const float4* __restrict__ src,
                                        uint32_t* __restrict__ dst, int i) {
    float4 v = src[i];
    int r = i >> 7, c0 = (i & 127) * 4;
    size_t block = (size_t)(r >> 3) * 32 + (c0 >> 4);
    int lane = 4 * (r & 7) + ((c0 & 7) >> 1);
    int br = (c0 >> 3) & 1;
    dst[block * 64 + lane * 2 + br]       = pack_h2(v.x, v.y);
    dst[block * 64 + (lane + 1) * 2 + br] = pack_h2(v.z, v.w);
}

__global__ void prep_kernel(const float4* __restrict__ x,
                            const unsigned char* __restrict__ mraw,
                            const float4* __restrict__ Wt,
                            const float4* __restrict__ Wo)
{
    const int blk = blockIdx.x, tid = threadIdx.x;
    if (blk < 2048) {                 // x -> A-frag
        emit_af(x, g_xaf, blk * 256 + tid);
    } else if (blk < 2816) {          // Wt -> B-frag
        emit_bf(Wt, g_wtbf, (blk - 2048) * 256 + tid);
    } else if (blk < 3072) {          // Wo -> B-frag
        emit_bf(Wo, g_wobf, (blk - 2816) * 256 + tid);
    } else {                          // mask sniff + per-batch compaction scan
        const int bb = blk - 3072;    // batch 0/1
        __shared__ int typ_s;
        __shared__ int wsum[8];
        if (tid == 0) {
            int t = 1;
            for (int i = 0; i < 512; i++) {
                unsigned char c = mraw[i];
                if ((i & 3) != 0 && c != 0) { t = (c == 0x3f || c == 0x80) ? 2 : 0; break; }
            }
            typ_s = t;
        }
        __syncthreads();
        const int t = typ_s;
        const int base = bb * SS;
        const int p0 = tid * 8;
        float mv[8];
        int cnt = 0;
#pragma unroll
        for (int i = 0; i < 8; i++) {
            int p = base + p0 + i;
            float m;
            if (t == 0)      m = mraw[p] ? 1.0f : 0.0f;
            else if (t == 1) m = (((const int*)mraw)[p] != 0) ? 1.0f : 0.0f;
            else             m = (((const float*)mraw)[p] != 0.0f) ? 1.0f : 0.0f;
            mv[i] = m;
            cnt += (m != 0.0f);
        }
        const int lane = tid & 31, wid = tid >> 5;
        int xs = cnt;
#pragma unroll
        for (int o = 1; o < 32; o <<= 1) {
            int y = __shfl_up_sync(0xffffffffu, xs, o);
            if (lane >= o) xs += y;
        }
        if (lane == 31) wsum[wid] = xs;
        __syncthreads();
        if (tid == 0) {
            int a = 0;
#pragma unroll
            for (int ww = 0; ww < 8; ww++) { int tt = wsum[ww]; wsum[ww] = a; a += tt; }
            g_nkeys[bb] = a;
        }
        __syncthreads();
        int c = xs - cnt + wsum[wid];
#pragma unroll
        for (int i = 0; i < 8; i++) {
            int p = base + p0 + i;
            g_mask[p] = mv[i];
            if (mv[i] != 0.0f) g_cidx[p] = c++;
        }
    }
}

// ---------------- fp16 frag-ordered GEMM  C = A @ B^T (3-stage cp.async) ----
// Single barrier per stage: with a 3-buffer ring, issue(s+2) after barrier(s)
// cannot race reads of stage s-1 (same buffer) because every warp passes
// barrier(s) only after finishing its s-1 reads.
__global__ void __launch_bounds__(256, 2) gemm_af_kernel(
    const uint32_t* __restrict__ Aaf, const uint32_t* __restrict__ Bbf,
    float* __restrict__ C, int M, int N, int K)
{
    extern __shared__ uint32_t gsm[];
    const uint32_t sbase = smem_u32(gsm);

    const int tid = threadIdx.x;
    const int w = tid >> 5, lane = tid & 31;
    const int g = lane >> 2, t = lane & 3;
    const int wm = w >> 2, wn = w & 3;
    const int bm = blockIdx.y, bn = blockIdx.x;
    const int K16 = K >> 4;
    const int nst = K >> 5;

    const char* Ab = (const char*)Aaf;
    const char* Bb = (const char*)Bbf;

    auto issue = [&](int s) {
        uint32_t base = sbase + (uint32_t)((s % 3) * 16384);
#pragma unroll
        for (int c = 0; c < 2; c++) {
            int ch = tid * 2 + c;
            int ablk = ch >> 5;
            cp16(base + (uint32_t)(ch * 16),
                 Ab + ((size_t)((bm * 8 + (ablk >> 1)) * K16 + s * 2 + (ablk & 1))) * 512 + (ch & 31) * 16);
            int bblk = ch >> 4;
            cp16(base + 8192u + (uint32_t)(ch * 16),
                 Bb + ((size_t)((bn * 16 + (bblk >> 1)) * K16 + s * 2 + (bblk & 1))) * 256 + (ch & 15) * 16);
        }
        CP_COMMIT();
    };

    float acc[4][4][4];
#pragma unroll
    for (int mf = 0; mf < 4; mf++)
#pragma unroll
        for (int nf = 0; nf < 4; nf++)
#pragma unroll
            for (int c = 0; c < 4; c++) acc[mf][nf][c] = 0.0f;

    issue(0);
    issue(1);

    for (int s = 0; s < nst; s++) {
        if (s + 1 == nst) { CP_WAIT0(); } else { CP_WAIT1(); }
        __syncthreads();
        if (s + 2 < nst) issue(s + 2);

        uint32_t* As = gsm + (s % 3) * 4096;
        uint32_t* Bs = As + 2048;

#pragma unroll
        for (int kb = 0; kb < 2; kb++) {
            uint32_t a[4][4];
#pragma unroll
            for (int mf = 0; mf < 4; mf++) {
                uint4 av = *(const uint4*)&As[((wm * 4 + mf) * 2 + kb) * 128 + 4 * lane];
                a[mf][0] = av.x; a[mf][1] = av.y; a[mf][2] = av.z; a[mf][3] = av.w;
            }
#pragma unroll
            for (int nf = 0; nf < 4; nf++) {
                uint2 bv = *(const uint2*)&Bs[((wn * 4 + nf) * 2 + kb) * 64 + 2 * lane];
#pragma unroll
                for (int mf = 0; mf < 4; mf++)
                    mma_f16(acc[mf][nf], a[mf][0], a[mf][1], a[mf][2], a[mf][3], bv.x, bv.y);
            }
        }
    }

#pragma unroll
    for (int mf = 0; mf < 4; mf++) {
        int row = bm * 128 + wm * 64 + mf * 16 + g;
#pragma unroll
        for (int nf = 0; nf < 4; nf++) {
            int col = bn * 128 + wn * 32 + nf * 8 + 2 * t;
            *(float2*)&C[(size_t)row * N + col]       = make_float2(acc[mf][nf][0], acc[mf][nf][1]);
            *(float2*)&C[(size_t)(row + 8) * N + col] = make_float2(acc[mf][nf][2], acc[mf][nf][3]);
        }
    }
}

// ---------------- rotation (row-major R, vector loads) + compacted k/v ------
__global__ void __launch_bounds__(256) rotate_kernel(const float* __restrict__ rot)
{
    const int p = blockIdx.x, tid = threadIdx.x;
    const int b = p >> 11, s = p & 2047;
    float* row = &g_qkv[(size_t)p * ROWQ];
    const bool masked = (g_mask[p] != 0.0f);

    if (masked) {
        const int c = g_cidx[p];
        __shared__ float4 Rr[64 * 17];   // row i at Rr[i*17 + j4]
        __shared__ float4 X4[256];       // 16 vectors x 16 float4

        const float4* R4 = (const float4*)(rot + (size_t)p * 4096);
#pragma unroll
        for (int t2 = 0; t2 < 4; t2++) {
            int idx4 = tid + 256 * t2;           // 0..1023
            Rr[(idx4 >> 4) * 17 + (idx4 & 15)] = R4[idx4];
        }
        X4[tid] = ((const float4*)row)[tid];
        __syncthreads();

        const int i  = tid & 63;
        const int vb = tid >> 6;
        float acc[4] = {0.0f, 0.0f, 0.0f, 0.0f};
#pragma unroll
        for (int j4 = 0; j4 < 16; j4++) {
            float4 r = Rr[i * 17 + j4];
#pragma unroll
            for (int ii = 0; ii < 4; ii++) {
                float4 xv = X4[(vb + 4 * ii) * 16 + j4];
                acc[ii] = fmaf(r.x, xv.x, acc[ii]);
                acc[ii] = fmaf(r.y, xv.y, acc[ii]);
                acc[ii] = fmaf(r.z, xv.z, acc[ii]);
                acc[ii] = fmaf(r.w, xv.w, acc[ii]);
            }
        }
#pragma unroll
        for (int ii = 0; ii < 4; ii++) {
            int vv = vb + 4 * ii;
            unsigned short hv = f2h(acc[ii]);
            if (vv < 8) g_qh[qh_off(b * 8 + vv, s, i)] = hv;
            else        g_kh[kh_off(b * 8 + vv - 8, c, i)] = hv;
        }
        // v: only live keys matter
#pragma unroll
        for (int t2 = 0; t2 < 2; t2++) {
            int idx = tid + 256 * t2;
            g_vh[vh_off(b * 8 + (idx >> 6), c, idx & 63)] = f2h(row[1024 + idx]);
        }
    } else {
        // only q survives; k/v dropped (weight would be 0)
#pragma unroll
        for (int t2 = 0; t2 < 2; t2++) {
            int idx = tid + 256 * t2;     // 0..511
            g_qh[qh_off(b * 8 + (idx >> 6), s, idx & 63)] = f2h(row[idx]);
        }
    }
}

// ---------------- fp16 mma.sync Taylor attention, m32 warp tiles --------------
// grid (16 qtiles, 16 bh), 128 thr = 4 warps (each 2 m16 blocks), 2 CTA/SM.
// ceil(N/128) stages of 128 compacted keys; every K/V B-frag feeds 2 MMAs.
#define STGW 8192   // stage words: K 16KB | V 16KB

__global__ void __launch_bounds__(128, 2) attn_mma_kernel(uint32_t* __restrict__ outaf)
{
    extern __shared__ uint32_t sm[];
    const uint32_t sbase = smem_u32(sm);

    const int tid = threadIdx.x;
    const int w = tid >> 5, lane = tid & 31;
    const int t = lane & 3;
    const int qt = blockIdx.x, bh = blockIdx.y;
    const int b = bh >> 3, h = bh & 7;
    const int N = g_nkeys[b];
    const int nst = (N + 127) >> 7;

    // ---- Q fragments in registers: 2 m16 blocks x 4 k16 ----
    uint32_t qa[2][4][4];
#pragma unroll
    for (int mb = 0; mb < 2; mb++) {
        int qblk = qt * 8 + w * 2 + mb;
        const uint4* qp = reinterpret_cast<const uint4*>(g_qh)
                          + (((size_t)bh * 128 + qblk) * 4) * 32 + lane;
#pragma unroll
        for (int k16 = 0; k16 < 4; k16++) {
            uint4 v = qp[k16 * 32];
            qa[mb][k16][0] = v.x; qa[mb][k16][1] = v.y;
            qa[mb][k16][2] = v.z; qa[mb][k16][3] = v.w;
        }
    }

    const char* kbase = (const char*)(g_kh + (size_t)bh * 32 * 4096);
    const char* vbase = (const char*)(g_vh + (size_t)bh * 32 * 4096);

    auto issue_stage = [&](int s) {
        const uint32_t dstb = sbase + (uint32_t)((s & 1) * STGW * 4);
        const char* ks = kbase + (size_t)s * 16384;
        const char* vs = vbase + (size_t)s * 16384;
#pragma unroll
        for (int c = 0; c < 8; c++) {
            int ch = tid * 8 + c;               // 0..1023
            cp16(dstb + (uint32_t)(ch * 16), ks + ch * 16);
            cp16(dstb + 16384u + (uint32_t)(ch * 16), vs + ch * 16);
        }
        CP_COMMIT();
    };

    float outr[2][8][4];
#pragma unroll
    for (int mb = 0; mb < 2; mb++)
#pragma unroll
        for (int n = 0; n < 8; n++)
#pragma unroll
            for (int j = 0; j < 4; j++) outr[mb][n][j] = 0.0f;
    float dacc[2][4] = {{0.0f,0.0f,0.0f,0.0f},{0.0f,0.0f,0.0f,0.0f}};

    issue_stage(0);

    for (int s = 0; s < nst; s++) {
        CP_WAIT0();
        __syncthreads();
        if (s + 1 < nst) issue_stage(s + 1);

        uint32_t* base = sm + (s & 1) * STGW;
        const bool needmask = ((s + 1) * 128 > N);

#pragma unroll
        for (int h2 = 0; h2 < 2; h2++) {
            uint32_t* Kf = base + h2 * 2048;
            uint32_t* Vf = base + 4096 + h2 * 2048;

            // ---- MMA1: S[32 q, 64 keys] = Q @ K^T (each kf feeds 2 MMAs) ----
            float sc[2][8][4];
#pragma unroll
            for (int mb = 0; mb < 2; mb++)
#pragma unroll
                for (int n = 0; n < 8; n++)
#pragma unroll
                    for (int j = 0; j < 4; j++) sc[mb][n][j] = 0.0f;

#pragma unroll
            for (int k16 = 0; k16 < 4; k16++) {
#pragma unroll
                for (int n = 0; n < 8; n++) {
                    uint2 kf = *(const uint2*)&Kf[(n * 4 + k16) * 64 + 2 * lane];
                    mma_f16(sc[0][n], qa[0][k16][0], qa[0][k16][1], qa[0][k16][2], qa[0][k16][3], kf.x, kf.y);
                    mma_f16(sc[1][n], qa[1][k16][0], qa[1][k16][1], qa[1][k16][2], qa[1][k16][3], kf.x, kf.y);
                }
            }

            // ---- Taylor weights in half2 ----
            uint32_t wpA[2][8], wpB[2][8];
#pragma unroll
            for (int n = 0; n < 8; n++) {
                uint32_t mm = 0xFFFFFFFFu;
                if (needmask) {
                    int k0 = s * 128 + h2 * 64 + n * 8 + 2 * t;
                    mm = (k0 < N ? 0x0000FFFFu : 0u) | (k0 + 1 < N ? 0xFFFF0000u : 0u);
                }
#pragma unroll
                for (int mb = 0; mb < 2; mb++) {
                    uint32_t sA = pack_h2(sc[mb][n][0], sc[mb][n][1]);
                    uint32_t sB = pack_h2(sc[mb][n][2], sc[mb][n][3]);
                    uint32_t wa = hfma2(sA, hfma2(sA, H2_C128, H2_C8), H2_ONE);
                    uint32_t wb = hfma2(sB, hfma2(sB, H2_C128, H2_C8), H2_ONE);
                    wpA[mb][n] = wa & mm;
                    wpB[mb][n] = wb & mm;
                }
            }

            // ---- MMA2: O += W @ V ; den += W @ ones (vf feeds 2 MMAs) ----
#pragma unroll
            for (int j2 = 0; j2 < 4; j2++) {
                mma_f16(dacc[0], wpA[0][2*j2], wpB[0][2*j2], wpA[0][2*j2+1], wpB[0][2*j2+1], H2_ONE, H2_ONE);
                mma_f16(dacc[1], wpA[1][2*j2], wpB[1][2*j2], wpA[1][2*j2+1], wpB[1][2*j2+1], H2_ONE, H2_ONE);
#pragma unroll
                for (int dn = 0; dn < 8; dn++) {
                    uint2 vf = *(const uint2*)&Vf[(dn * 4 + j2) * 64 + 2 * lane];
                    mma_f16(outr[0][dn], wpA[0][2*j2], wpB[0][2*j2], wpA[0][2*j2+1], wpB[0][2*j2+1], vf.x, vf.y);
                    mma_f16(outr[1][dn], wpA[1][2*j2], wpB[1][2*j2], wpA[1][2*j2+1], wpB[1][2*j2+1], vf.x, vf.y);
                }
            }
        }
    }

    // ---- normalize + store fp16 A-frag words for gemm2 ----
#pragma unroll
    for (int mb = 0; mb < 2; mb++) {
        float inv0 = 1.0f / dacc[mb][0];
        float inv1 = 1.0f / dacc[mb][2];
        size_t qb = (size_t)((b * SS + qt * 128 + w * 32 + mb * 16) >> 4);
#pragma unroll
        for (int dn = 0; dn < 8; dn++) {
            size_t block = qb * 32 + h * 4 + (dn >> 1);
            int jA = 2 * (dn & 1);
            outaf[block * 128 + lane * 4 + jA]     = pack_h2(outr[mb][dn][0] * inv0, outr[mb][dn][1] * inv0);
            outaf[block * 128 + lane * 4 + jA + 1] = pack_h2(outr[mb][dn][2] * inv1, outr[mb][dn][3] * inv1);
        }
    }
}

// ---------------- launch ----------------
extern "C" void kernel_launch(void* const* d_in, const int* in_sizes, int n_in,
                              void* d_out, int out_size)
{
    const float*         x    = (const float*)d_in[0];
    const unsigned char* mask = (const unsigned char*)d_in[1];
    const float*         rot  = (const float*)d_in[2];
    const float*         Wt   = (const float*)d_in[3];
    const float*         Wo   = (const float*)d_in[4];
    float*               out  = (float*)d_out;

    float *qkv_p;
    uint32_t *attaf_p, *xaf_p, *wtbf_p, *wobf_p;
    cudaGetSymbolAddress((void**)&qkv_p,   g_qkv);
    cudaGetSymbolAddress((void**)&attaf_p, g_attaf);
    cudaGetSymbolAddress((void**)&xaf_p,   g_xaf);
    cudaGetSymbolAddress((void**)&wtbf_p,  g_wtbf);
    cudaGetSymbolAddress((void**)&wobf_p,  g_wobf);

    static const int ATT_SMEM  = 2 * STGW * 4;   // 65,536 B
    static const int GEMM_SMEM = 49152;
    cudaFuncSetAttribute(attn_mma_kernel, cudaFuncAttributeMaxDynamicSharedMemorySize, ATT_SMEM);
    cudaFuncSetAttribute(gemm_af_kernel, cudaFuncAttributeMaxDynamicSharedMemorySize, GEMM_SMEM);

    // fused prep: x->af, Wt->bf, Wo->bf, mask sniff + compaction scan
    prep_kernel<<<3074, 256>>>((const float4*)x, mask, (const float4*)Wt, (const float4*)Wo);

    // qkv = x @ W_trans^T
    gemm_af_kernel<<<dim3(ROWQ / 128, NP / 128), 256, GEMM_SMEM>>>(xaf_p, wtbf_p, qkv_p, NP, ROWQ, DIM);

    // rotate q,k where masked; emit frag-ordered q + COMPACTED k/v
    rotate_kernel<<<NP, 256>>>(rot);

    // attention over compacted keys -> g_attaf (m32 warp tiles)
    attn_mma_kernel<<<dim3(SS / 128, BB * NH), 128, ATT_SMEM>>>(attaf_p);

    // out = att @ W_o^T
    gemm_af_kernel<<<dim3(DIM / 128, NP / 128), 256, GEMM_SMEM>>>(attaf_p, wobf_p, out, NP, DIM, DIM);
}

// round 12
// speedup vs baseline: 8.1106x; 1.0401x over previous
#include <cuda_runtime.h>
#include <cuda_fp16.h>
#include <cstdint>

// Problem constants
#define BB   2
#define SS   2048
#define DIM  512
#define NH   8
#define HD   64
#define QK   512          // NH*HD
#define ROWQ 1536         // 2*QK + DIM
#define NP   4096         // B*S positions

// ---------------- scratch ----------------
__device__ float    g_qkv[NP * ROWQ];        // gemm1 output, natural f32
__device__ unsigned short g_qh[NP * QK];     // Q fp16, A-frag order per (b,h)
__device__ unsigned short g_kh[NP * QK];     // K fp16, paired-B-frag order, COMPACTED
__device__ unsigned short g_vh[NP * QK];     // V fp16, paired-B-frag order, COMPACTED
__device__ uint32_t g_xaf[NP * DIM / 2];     // x fp16 A-frag words
__device__ uint32_t g_wtbf[ROWQ * DIM / 2];  // W_trans fp16 paired-B-frag words
__device__ uint32_t g_wobf[DIM * DIM / 2];   // W_o fp16 paired-B-frag words
__device__ uint32_t g_attaf[NP * DIM / 2];   // attention out fp16 A-frag words
__device__ float    g_mask[NP];              // f32 mask (rotate branch)
__device__ int      g_cidx[NP];              // compacted key index (valid where mask!=0)
__device__ int      g_nkeys[BB];             // live keys per batch

// half2 constants
#define H2_ONE  0x3C003C00u
#define H2_C8   0x30003000u   // 1/8
#define H2_C128 0x20002000u   // 1/128

// ---------------- helpers ----------------
__device__ __forceinline__ uint32_t pack_h2(float lo, float hi) {
    uint32_t r;
    asm("cvt.rn.f16x2.f32 %0, %1, %2;" : "=r"(r) : "f"(hi), "f"(lo));
    return r;
}
__device__ __forceinline__ unsigned short f2h(float f) {
    return __half_as_ushort(__float2half_rn(f));
}
__device__ __forceinline__ uint32_t hfma2(uint32_t a, uint32_t b, uint32_t c) {
    uint32_t d;
    asm("fma.rn.f16x2 %0, %1, %2, %3;" : "=r"(d) : "r"(a), "r"(b), "r"(c));
    return d;
}
__device__ __forceinline__ uint32_t smem_u32(const void* p) {
    uint32_t a;
    asm("{ .reg .u64 t; cvta.to.shared.u64 t, %1; cvt.u32.u64 %0, t; }" : "=r"(a) : "l"(p));
    return a;
}
__device__ __forceinline__ void cp16(uint32_t dst, const void* src) {
    asm volatile("cp.async.ca.shared.global [%0], [%1], 16;" :: "r"(dst), "l"(src) : "memory");
}
#define CP_COMMIT() asm volatile("cp.async.commit_group;" ::: "memory")
#define CP_WAIT0()  asm volatile("cp.async.wait_group 0;" ::: "memory")
#define CP_WAIT1()  asm volatile("cp.async.wait_group 1;" ::: "memory")

__device__ __forceinline__ void mma_f16(float* c,
    uint32_t a0, uint32_t a1, uint32_t a2, uint32_t a3, uint32_t b0, uint32_t b1)
{
    asm volatile(
        "mma.sync.aligned.m16n8k16.row.col.f32.f16.f16.f32 "
        "{%0,%1,%2,%3}, {%4,%5,%6,%7}, {%8,%9}, {%0,%1,%2,%3};"
        : "+f"(c[0]), "+f"(c[1]), "+f"(c[2]), "+f"(c[3])
        : "r"(a0), "r"(a1), "r"(a2), "r"(a3), "r"(b0), "r"(b1));
}

// half-index helpers (paired-B layouts)
__device__ __forceinline__ size_t qh_off(int bh, int s, int d) {
    int lane = 4 * (s & 7) + ((d & 7) >> 1);
    int j = ((s >> 3) & 1) + 2 * ((d >> 3) & 1);
    return (((size_t)bh * 128 + (s >> 4)) * 4 + (d >> 4)) * 256 + lane * 8 + j * 2 + (d & 1);
}
// K: block ((bh,g64),pair,k16) of 256 halves; half = lane*8 + po*4 + br*2 + lo
__device__ __forceinline__ size_t kh_off(int bh, int key, int d) {
    int g64 = key >> 6, n8 = (key >> 3) & 7;
    int lane = 4 * (key & 7) + ((d & 7) >> 1);
    return ((((size_t)bh * 32 + g64) * 4 + (n8 >> 1)) * 4 + (d >> 4)) * 256
           + lane * 8 + (n8 & 1) * 4 + ((d >> 3) & 1) * 2 + (d & 1);
}
// V: block ((bh,g64),dpair,kb) of 256 halves
__device__ __forceinline__ size_t vh_off(int bh, int key, int d) {
    int g64 = key >> 6, kk = key & 15, kb = (key >> 4) & 3;
    int lane = 4 * (d & 7) + ((kk & 7) >> 1);
    return ((((size_t)bh * 32 + g64) * 4 + (d >> 4)) * 4 + kb) * 256
           + lane * 8 + ((d >> 3) & 1) * 4 + ((kk >> 3) & 1) * 2 + (kk & 1);
}

// ---------------- fused prep: round/reorder x, Wt, Wo + mask scan ----------------
__device__ __forceinline__ void emit_af(const float4* __restrict__ src,
                                        uint32_t* __restrict__ dst, int i) {
    float4 v = src[i];
    int r = i >> 7, c0 = (i & 127) * 4;          // K4 = 128
    int rm = r & 15;
    size_t block = (size_t)(r >> 4) * 32 + (c0 >> 4);
    int lane = 4 * (rm & 7) + ((c0 & 7) >> 1);
    int j = (rm >> 3) + 2 * ((c0 >> 3) & 1);
    dst[block * 128 + lane * 4 + j]       = pack_h2(v.x, v.y);
    dst[block * 128 + (lane + 1) * 4 + j] = pack_h2(v.z, v.w);
}
// paired-B: block (pair, k16) of 128 words; word = lane*4 + po*2 + br
__device__ __forceinline__ void emit_bf2(const float4* __restrict__ src,
                                         uint32_t* __restrict__ dst, int i) {
    float4 v = src[i];
    int r = i >> 7, c0 = (i & 127) * 4;          // K = 512, K16 = 32
    size_t block = (size_t)(r >> 4) * 32 + (c0 >> 4);
    int lane = 4 * (r & 7) + ((c0 & 7) >> 1);
    int w0 = ((r >> 3) & 1) * 2 + ((c0 >> 3) & 1);
    dst[block * 128 + lane * 4 + w0]       = pack_h2(v.x, v.y);
    dst[block * 128 + (lane + 1) * 4 + w0] = pack_h2(v.z, v.w);
}

__global__ void prep_kernel(const float4* __restrict__ x,
                            const unsigned char* __restrict__ mraw,
                            const float4* __restrict__ Wt,
                            const float4* __restrict__ Wo)
{
    const int blk = blockIdx.x, tid = threadIdx.x;
    if (blk < 2048) {                 // x -> A-frag
        emit_af(x, g_xaf, blk * 256 + tid);
    } else if (blk < 2816) {          // Wt -> paired B-frag
        emit_bf2(Wt, g_wtbf, (blk - 2048) * 256 + tid);
    } else if (blk < 3072) {          // Wo -> paired B-frag
        emit_bf2(Wo, g_wobf, (blk - 2816) * 256 + tid);
    } else {                          // mask sniff + per-batch compaction scan
        const int bb = blk - 3072;
        __shared__ int typ_s;
        __shared__ int wsum[8];
        if (tid == 0) {
            int t = 1;
            for (int i = 0; i < 512; i++) {
                unsigned char c = mraw[i];
                if ((i & 3) != 0 && c != 0) { t = (c == 0x3f || c == 0x80) ? 2 : 0; break; }
            }
            typ_s = t;
        }
        __syncthreads();
        const int t = typ_s;
        const int base = bb * SS;
        const int p0 = tid * 8;
        float mv[8];
        int cnt = 0;
#pragma unroll
        for (int i = 0; i < 8; i++) {
            int p = base + p0 + i;
            float m;
            if (t == 0)      m = mraw[p] ? 1.0f : 0.0f;
            else if (t == 1) m = (((const int*)mraw)[p] != 0) ? 1.0f : 0.0f;
            else             m = (((const float*)mraw)[p] != 0.0f) ? 1.0f : 0.0f;
            mv[i] = m;
            cnt += (m != 0.0f);
        }
        const int lane = tid & 31, wid = tid >> 5;
        int xs = cnt;
#pragma unroll
        for (int o = 1; o < 32; o <<= 1) {
            int y = __shfl_up_sync(0xffffffffu, xs, o);
            if (lane >= o) xs += y;
        }
        if (lane == 31) wsum[wid] = xs;
        __syncthreads();
        if (tid == 0) {
            int a = 0;
#pragma unroll
            for (int ww = 0; ww < 8; ww++) { int tt = wsum[ww]; wsum[ww] = a; a += tt; }
            g_nkeys[bb] = a;
        }
        __syncthreads();
        int c = xs - cnt + wsum[wid];
#pragma unroll
        for (int i = 0; i < 8; i++) {
            int p = base + p0 + i;
            g_mask[p] = mv[i];
            if (mv[i] != 0.0f) g_cidx[p] = c++;
        }
    }
}

// ---------------- fp16 frag-ordered GEMM (paired-B, 3-stage, 1 barrier) ------
__global__ void __launch_bounds__(256, 2) gemm_af_kernel(
    const uint32_t* __restrict__ Aaf, const uint32_t* __restrict__ Bbf,
    float* __restrict__ C, int M, int N, int K)
{
    extern __shared__ uint32_t gsm[];
    const uint32_t sbase = smem_u32(gsm);

    const int tid = threadIdx.x;
    const int w = tid >> 5, lane = tid & 31;
    const int g = lane >> 2, t = lane & 3;
    const int wm = w >> 2, wn = w & 3;
    const int bm = blockIdx.y, bn = blockIdx.x;
    const int K16 = K >> 4;
    const int nst = K >> 5;

    const char* Ab = (const char*)Aaf;
    const char* Bb = (const char*)Bbf;

    auto issue = [&](int s) {
        uint32_t base = sbase + (uint32_t)((s % 3) * 16384);
#pragma unroll
        for (int c = 0; c < 2; c++) {
            int ch = tid * 2 + c;                 // 0..511
            int ablk = ch >> 5;                   // mb*2+kb
            cp16(base + (uint32_t)(ch * 16),
                 Ab + ((size_t)((bm * 8 + (ablk >> 1)) * K16 + s * 2 + (ablk & 1))) * 512 + (ch & 31) * 16);
            int bblk = ch >> 5;                   // pairLocal*2+kb (8 pairs x 2 kb = 16 x 512B)
            cp16(base + 8192u + (uint32_t)(ch * 16),
                 Bb + ((size_t)((bn * 8 + (bblk >> 1)) * K16 + s * 2 + (bblk & 1))) * 512 + (ch & 31) * 16);
        }
        CP_COMMIT();
    };

    float acc[4][4][4];
#pragma unroll
    for (int mf = 0; mf < 4; mf++)
#pragma unroll
        for (int nf = 0; nf < 4; nf++)
#pragma unroll
            for (int c = 0; c < 4; c++) acc[mf][nf][c] = 0.0f;

    issue(0);
    issue(1);

    for (int s = 0; s < nst; s++) {
        if (s + 1 == nst) { CP_WAIT0(); } else { CP_WAIT1(); }
        __syncthreads();
        if (s + 2 < nst) issue(s + 2);

        uint32_t* As = gsm + (s % 3) * 4096;
        uint32_t* Bs = As + 2048;

#pragma unroll
        for (int kb = 0; kb < 2; kb++) {
            uint32_t a[4][4];
#pragma unroll
            for (int mf = 0; mf < 4; mf++) {
                uint4 av = *(const uint4*)&As[((wm * 4 + mf) * 2 + kb) * 128 + 4 * lane];
                a[mf][0] = av.x; a[mf][1] = av.y; a[mf][2] = av.z; a[mf][3] = av.w;
            }
#pragma unroll
            for (int nfp = 0; nfp < 2; nfp++) {
                uint4 bv = *(const uint4*)&Bs[((wn * 2 + nfp) * 2 + kb) * 128 + 4 * lane];
#pragma unroll
                for (int mf = 0; mf < 4; mf++) {
                    mma_f16(acc[mf][2 * nfp],     a[mf][0], a[mf][1], a[mf][2], a[mf][3], bv.x, bv.y);
                    mma_f16(acc[mf][2 * nfp + 1], a[mf][0], a[mf][1], a[mf][2], a[mf][3], bv.z, bv.w);
                }
            }
        }
    }

#pragma unroll
    for (int mf = 0; mf < 4; mf++) {
        int row = bm * 128 + wm * 64 + mf * 16 + g;
#pragma unroll
        for (int nf = 0; nf < 4; nf++) {
            int col = bn * 128 + wn * 32 + nf * 8 + 2 * t;
            *(float2*)&C[(size_t)row * N + col]       = make_float2(acc[mf][nf][0], acc[mf][nf][1]);
            *(float2*)&C[(size_t)(row + 8) * N + col] = make_float2(acc[mf][nf][2], acc[mf][nf][3]);
        }
    }
}

// ---------------- rotation (row-major R, vector loads) + compacted k/v ------
__global__ void __launch_bounds__(256) rotate_kernel(const float* __restrict__ rot)
{
    const int p = blockIdx.x, tid = threadIdx.x;
    const int b = p >> 11, s = p & 2047;
    float* row = &g_qkv[(size_t)p * ROWQ];
    const bool masked = (g_mask[p] != 0.0f);

    if (masked) {
        const int c = g_cidx[p];
        __shared__ float4 Rr[64 * 17];
        __shared__ float4 X4[256];

        const float4* R4 = (const float4*)(rot + (size_t)p * 4096);
#pragma unroll
        for (int t2 = 0; t2 < 4; t2++) {
            int idx4 = tid + 256 * t2;
            Rr[(idx4 >> 4) * 17 + (idx4 & 15)] = R4[idx4];
        }
        X4[tid] = ((const float4*)row)[tid];
        __syncthreads();

        const int i  = tid & 63;
        const int vb = tid >> 6;
        float acc[4] = {0.0f, 0.0f, 0.0f, 0.0f};
#pragma unroll
        for (int j4 = 0; j4 < 16; j4++) {
            float4 r = Rr[i * 17 + j4];
#pragma unroll
            for (int ii = 0; ii < 4; ii++) {
                float4 xv = X4[(vb + 4 * ii) * 16 + j4];
                acc[ii] = fmaf(r.x, xv.x, acc[ii]);
                acc[ii] = fmaf(r.y, xv.y, acc[ii]);
                acc[ii] = fmaf(r.z, xv.z, acc[ii]);
                acc[ii] = fmaf(r.w, xv.w, acc[ii]);
            }
        }
#pragma unroll
        for (int ii = 0; ii < 4; ii++) {
            int vv = vb + 4 * ii;
            unsigned short hv = f2h(acc[ii]);
            if (vv < 8) g_qh[qh_off(b * 8 + vv, s, i)] = hv;
            else        g_kh[kh_off(b * 8 + vv - 8, c, i)] = hv;
        }
#pragma unroll
        for (int t2 = 0; t2 < 2; t2++) {
            int idx = tid + 256 * t2;
            g_vh[vh_off(b * 8 + (idx >> 6), c, idx & 63)] = f2h(row[1024 + idx]);
        }
    } else {
#pragma unroll
        for (int t2 = 0; t2 < 2; t2++) {
            int idx = tid + 256 * t2;
            g_qh[qh_off(b * 8 + (idx >> 6), s, idx & 63)] = f2h(row[idx]);
        }
    }
}

// ---------------- fp16 mma.sync Taylor attention (paired-B K/V) --------------
// grid (16 qtiles, 16 bh), 256 thr = 8 warps m16, 2 CTA/SM.
// ceil(N/128) stages of 128 compacted keys; one LDS.128 feeds 2 B-frags.
#define STGW 8192   // stage words: K 16KB | V 16KB

__global__ void __launch_bounds__(256, 2) attn_mma_kernel(uint32_t* __restrict__ outaf)
{
    extern __shared__ uint32_t sm[];
    const uint32_t sbase = smem_u32(sm);

    const int tid = threadIdx.x;
    const int w = tid >> 5, lane = tid & 31;
    const int t = lane & 3;
    const int qt = blockIdx.x, bh = blockIdx.y;
    const int b = bh >> 3, h = bh & 7;
    const int N = g_nkeys[b];
    const int nst = (N + 127) >> 7;

    // ---- Q fragments in registers ----
    uint32_t qa[4][4];
    {
        int qblk = qt * 8 + w;
        const uint4* qp = reinterpret_cast<const uint4*>(g_qh)
                          + (((size_t)bh * 128 + qblk) * 4) * 32 + lane;
#pragma unroll
        for (int k16 = 0; k16 < 4; k16++) {
            uint4 v = qp[k16 * 32];
            qa[k16][0] = v.x; qa[k16][1] = v.y; qa[k16][2] = v.z; qa[k16][3] = v.w;
        }
    }

    const char* kbase = (const char*)(g_kh + (size_t)bh * 32 * 4096);
    const char* vbase = (const char*)(g_vh + (size_t)bh * 32 * 4096);

    auto issue_stage = [&](int s) {
        const uint32_t dstb = sbase + (uint32_t)((s & 1) * STGW * 4);
        const char* ks = kbase + (size_t)s * 16384;
        const char* vs = vbase + (size_t)s * 16384;
#pragma unroll
        for (int c = 0; c < 4; c++) {
            int ch = tid * 4 + c;               // 0..1023
            cp16(dstb + (uint32_t)(ch * 16), ks + ch * 16);
            cp16(dstb + 16384u + (uint32_t)(ch * 16), vs + ch * 16);
        }
        CP_COMMIT();
    };

    float outr[8][4];
#pragma unroll
    for (int n = 0; n < 8; n++)
#pragma unroll
        for (int j = 0; j < 4; j++) outr[n][j] = 0.0f;
    float dacc[4] = {0.0f, 0.0f, 0.0f, 0.0f};

    issue_stage(0);

    for (int s = 0; s < nst; s++) {
        CP_WAIT0();
        __syncthreads();
        if (s + 1 < nst) issue_stage(s + 1);

        uint32_t* base = sm + (s & 1) * STGW;
        const bool needmask = ((s + 1) * 128 > N);

#pragma unroll
        for (int h2 = 0; h2 < 2; h2++) {
            uint32_t* Kf = base + h2 * 2048;
            uint32_t* Vf = base + 4096 + h2 * 2048;

            // ---- MMA1: S[16 q, 64 keys] = Q @ K^T (paired kf: 1 LDS.128 -> 2 MMAs) ----
            float sc[8][4];
#pragma unroll
            for (int n = 0; n < 8; n++)
#pragma unroll
                for (int j = 0; j < 4; j++) sc[n][j] = 0.0f;

#pragma unroll
            for (int k16 = 0; k16 < 4; k16++) {
#pragma unroll
                for (int pr = 0; pr < 4; pr++) {
                    uint4 kf = *(const uint4*)&Kf[(pr * 4 + k16) * 128 + 4 * lane];
                    mma_f16(sc[2 * pr],     qa[k16][0], qa[k16][1], qa[k16][2], qa[k16][3], kf.x, kf.y);
                    mma_f16(sc[2 * pr + 1], qa[k16][0], qa[k16][1], qa[k16][2], qa[k16][3], kf.z, kf.w);
                }
            }

            // ---- Taylor weights in half2 ----
            uint32_t wpA[8], wpB[8];
#pragma unroll
            for (int n = 0; n < 8; n++) {
                uint32_t sA = pack_h2(sc[n][0], sc[n][1]);
                uint32_t sB = pack_h2(sc[n][2], sc[n][3]);
                wpA[n] = hfma2(sA, hfma2(sA, H2_C128, H2_C8), H2_ONE);
                wpB[n] = hfma2(sB, hfma2(sB, H2_C128, H2_C8), H2_ONE);
                if (needmask) {
                    int k0 = s * 128 + h2 * 64 + n * 8 + 2 * t;
                    uint32_t mm = (k0 < N ? 0x0000FFFFu : 0u) | (k0 + 1 < N ? 0xFFFF0000u : 0u);
                    wpA[n] &= mm;
                    wpB[n] &= mm;
                }
            }

            // ---- MMA2: O += W @ V ; den += W @ ones (paired vf) ----
#pragma unroll
            for (int j2 = 0; j2 < 4; j2++) {
                uint32_t a0 = wpA[2 * j2], a1 = wpB[2 * j2];
                uint32_t a2 = wpA[2 * j2 + 1], a3 = wpB[2 * j2 + 1];
                mma_f16(dacc, a0, a1, a2, a3, H2_ONE, H2_ONE);
#pragma unroll
                for (int dp = 0; dp < 4; dp++) {
                    uint4 vf = *(const uint4*)&Vf[(dp * 4 + j2) * 128 + 4 * lane];
                    mma_f16(outr[2 * dp],     a0, a1, a2, a3, vf.x, vf.y);
                    mma_f16(outr[2 * dp + 1], a0, a1, a2, a3, vf.z, vf.w);
                }
            }
        }
    }

    float inv0 = 1.0f / dacc[0];
    float inv1 = 1.0f / dacc[2];

    // ---- normalize + store fp16 A-frag words for gemm2 ----
    {
        size_t qb = (size_t)((b * SS + qt * 128 + w * 16) >> 4);
#pragma unroll
        for (int dn = 0; dn < 8; dn++) {
            size_t block = qb * 32 + h * 4 + (dn >> 1);
            int jA = 2 * (dn & 1);
            outaf[block * 128 + lane * 4 + jA]     = pack_h2(outr[dn][0] * inv0, outr[dn][1] * inv0);
            outaf[block * 128 + lane * 4 + jA + 1] = pack_h2(outr[dn][2] * inv1, outr[dn][3] * inv1);
        }
    }
}

// ---------------- launch ----------------
extern "C" void kernel_launch(void* const* d_in, const int* in_sizes, int n_in,
                              void* d_out, int out_size)
{
    const float*         x    = (const float*)d_in[0];
    const unsigned char* mask = (const unsigned char*)d_in[1];
    const float*         rot  = (const float*)d_in[2];
    const float*         Wt   = (const float*)d_in[3];
    const float*         Wo   = (const float*)d_in[4];
    float*               out  = (float*)d_out;

    float *qkv_p;
    uint32_t *attaf_p, *xaf_p, *wtbf_p, *wobf_p;
    cudaGetSymbolAddress((void**)&qkv_p,   g_qkv);
    cudaGetSymbolAddress((void**)&attaf_p, g_attaf);
    cudaGetSymbolAddress((void**)&xaf_p,   g_xaf);
    cudaGetSymbolAddress((void**)&wtbf_p,  g_wtbf);
    cudaGetSymbolAddress((void**)&wobf_p,  g_wobf);

    static const int ATT_SMEM  = 2 * STGW * 4;   // 65,536 B
    static const int GEMM_SMEM = 49152;
    cudaFuncSetAttribute(attn_mma_kernel, cudaFuncAttributeMaxDynamicSharedMemorySize, ATT_SMEM);
    cudaFuncSetAttribute(gemm_af_kernel, cudaFuncAttributeMaxDynamicSharedMemorySize, GEMM_SMEM);

    // fused prep: x->af, Wt->bf2, Wo->bf2, mask sniff + compaction scan
    prep_kernel<<<3074, 256>>>((const float4*)x, mask, (const float4*)Wt, (const float4*)Wo);

    // qkv = x @ W_trans^T
    gemm_af_kernel<<<dim3(ROWQ / 128, NP / 128), 256, GEMM_SMEM>>>(xaf_p, wtbf_p, qkv_p, NP, ROWQ, DIM);

    // rotate q,k where masked; emit frag-ordered q + COMPACTED paired k/v
    rotate_kernel<<<NP, 256>>>(rot);

    // attention over compacted keys -> g_attaf
    attn_mma_kernel<<<dim3(SS / 128, BB * NH), 256, ATT_SMEM>>>(attaf_p);

    // out = att @ W_o^T
    gemm_af_kernel<<<dim3(DIM / 128, NP / 128), 256, GEMM_SMEM>>>(attaf_p, wobf_p, out, NP, DIM, DIM);
}

// round 13
// speedup vs baseline: 8.4331x; 1.0398x over previous
#include <cuda_runtime.h>
#include <cuda_fp16.h>
#include <cstdint>

// Problem constants
#define BB   2
#define SS   2048
#define DIM  512
#define NH   8
#define HD   64
#define QK   512          // NH*HD
#define ROWQ 1536         // 2*QK + DIM
#define NP   4096         // B*S positions

// ---------------- scratch ----------------
__device__ float    g_qkv[NP * ROWQ];        // gemm1 output, natural f32
__device__ unsigned short g_qh[NP * QK];     // Q fp16, A-frag order per (b,h)
__device__ unsigned short g_kh[NP * QK];     // K fp16, paired-B-frag order, COMPACTED
__device__ unsigned short g_vh[NP * QK];     // V fp16, paired-B-frag order, COMPACTED
__device__ uint32_t g_xaf[NP * DIM / 2];     // x fp16 A-frag words
__device__ uint32_t g_wtbf[ROWQ * DIM / 2];  // W_trans fp16 paired-B-frag words
__device__ uint32_t g_wobf[DIM * DIM / 2];   // W_o fp16 paired-B-frag words
__device__ uint32_t g_attaf[NP * DIM / 2];   // attention out fp16 A-frag words
__device__ float    g_mask[NP];              // f32 mask (rotate branch)
__device__ int      g_cidx[NP];              // compacted key index (valid where mask!=0)
__device__ int      g_nkeys[BB];             // live keys per batch

// half2 constants
#define H2_ONE  0x3C003C00u
#define H2_C8   0x30003000u   // 1/8
#define H2_C128 0x20002000u   // 1/128

// ---------------- helpers ----------------
__device__ __forceinline__ uint32_t pack_h2(float lo, float hi) {
    uint32_t r;
    asm("cvt.rn.f16x2.f32 %0, %1, %2;" : "=r"(r) : "f"(hi), "f"(lo));
    return r;
}
__device__ __forceinline__ unsigned short f2h(float f) {
    return __half_as_ushort(__float2half_rn(f));
}
__device__ __forceinline__ uint32_t hfma2(uint32_t a, uint32_t b, uint32_t c) {
    uint32_t d;
    asm("fma.rn.f16x2 %0, %1, %2, %3;" : "=r"(d) : "r"(a), "r"(b), "r"(c));
    return d;
}
__device__ __forceinline__ uint32_t smem_u32(const void* p) {
    uint32_t a;
    asm("{ .reg .u64 t; cvta.to.shared.u64 t, %1; cvt.u32.u64 %0, t; }" : "=r"(a) : "l"(p));
    return a;
}
__device__ __forceinline__ void cp16(uint32_t dst, const void* src) {
    asm volatile("cp.async.ca.shared.global [%0], [%1], 16;" :: "r"(dst), "l"(src) : "memory");
}
#define CP_COMMIT() asm volatile("cp.async.commit_group;" ::: "memory")
#define CP_WAIT0()  asm volatile("cp.async.wait_group 0;" ::: "memory")
#define CP_WAIT1()  asm volatile("cp.async.wait_group 1;" ::: "memory")

__device__ __forceinline__ void mma_f16(float* c,
    uint32_t a0, uint32_t a1, uint32_t a2, uint32_t a3, uint32_t b0, uint32_t b1)
{
    asm volatile(
        "mma.sync.aligned.m16n8k16.row.col.f32.f16.f16.f32 "
        "{%0,%1,%2,%3}, {%4,%5,%6,%7}, {%8,%9}, {%0,%1,%2,%3};"
        : "+f"(c[0]), "+f"(c[1]), "+f"(c[2]), "+f"(c[3])
        : "r"(a0), "r"(a1), "r"(a2), "r"(a3), "r"(b0), "r"(b1));
}

// half-index helpers (paired-B layouts)
__device__ __forceinline__ size_t qh_off(int bh, int s, int d) {
    int lane = 4 * (s & 7) + ((d & 7) >> 1);
    int j = ((s >> 3) & 1) + 2 * ((d >> 3) & 1);
    return (((size_t)bh * 128 + (s >> 4)) * 4 + (d >> 4)) * 256 + lane * 8 + j * 2 + (d & 1);
}
__device__ __forceinline__ size_t kh_off(int bh, int key, int d) {
    int g64 = key >> 6, n8 = (key >> 3) & 7;
    int lane = 4 * (key & 7) + ((d & 7) >> 1);
    return ((((size_t)bh * 32 + g64) * 4 + (n8 >> 1)) * 4 + (d >> 4)) * 256
           + lane * 8 + (n8 & 1) * 4 + ((d >> 3) & 1) * 2 + (d & 1);
}
__device__ __forceinline__ size_t vh_off(int bh, int key, int d) {
    int g64 = key >> 6, kk = key & 15, kb = (key >> 4) & 3;
    int lane = 4 * (d & 7) + ((kk & 7) >> 1);
    return ((((size_t)bh * 32 + g64) * 4 + (d >> 4)) * 4 + kb) * 256
           + lane * 8 + ((d >> 3) & 1) * 4 + ((kk >> 3) & 1) * 2 + (kk & 1);
}

// ---------------- fused prep ----------------
__device__ __forceinline__ void emit_af(const float4* __restrict__ src,
                                        uint32_t* __restrict__ dst, int i) {
    float4 v = src[i];
    int r = i >> 7, c0 = (i & 127) * 4;
    int rm = r & 15;
    size_t block = (size_t)(r >> 4) * 32 + (c0 >> 4);
    int lane = 4 * (rm & 7) + ((c0 & 7) >> 1);
    int j = (rm >> 3) + 2 * ((c0 >> 3) & 1);
    dst[block * 128 + lane * 4 + j]       = pack_h2(v.x, v.y);
    dst[block * 128 + (lane + 1) * 4 + j] = pack_h2(v.z, v.w);
}
__device__ __forceinline__ void emit_bf2(const float4* __restrict__ src,
                                         uint32_t* __restrict__ dst, int i) {
    float4 v = src[i];
    int r = i >> 7, c0 = (i & 127) * 4;
    size_t block = (size_t)(r >> 4) * 32 + (c0 >> 4);
    int lane = 4 * (r & 7) + ((c0 & 7) >> 1);
    int w0 = ((r >> 3) & 1) * 2 + ((c0 >> 3) & 1);
    dst[block * 128 + lane * 4 + w0]       = pack_h2(v.x, v.y);
    dst[block * 128 + (lane + 1) * 4 + w0] = pack_h2(v.z, v.w);
}

__global__ void prep_kernel(const float4* __restrict__ x,
                            const unsigned char* __restrict__ mraw,
                            const float4* __restrict__ Wt,
                            const float4* __restrict__ Wo)
{
    const int blk = blockIdx.x, tid = threadIdx.x;
    if (blk < 2048) {
        emit_af(x, g_xaf, blk * 256 + tid);
    } else if (blk < 2816) {
        emit_bf2(Wt, g_wtbf, (blk - 2048) * 256 + tid);
    } else if (blk < 3072) {
        emit_bf2(Wo, g_wobf, (blk - 2816) * 256 + tid);
    } else {
        const int bb = blk - 3072;
        __shared__ int typ_s;
        __shared__ int wsum[8];
        if (tid == 0) {
            int t = 1;
            for (int i = 0; i < 512; i++) {
                unsigned char c = mraw[i];
                if ((i & 3) != 0 && c != 0) { t = (c == 0x3f || c == 0x80) ? 2 : 0; break; }
            }
            typ_s = t;
        }
        __syncthreads();
        const int t = typ_s;
        const int base = bb * SS;
        const int p0 = tid * 8;
        float mv[8];
        int cnt = 0;
#pragma unroll
        for (int i = 0; i < 8; i++) {
            int p = base + p0 + i;
            float m;
            if (t == 0)      m = mraw[p] ? 1.0f : 0.0f;
            else if (t == 1) m = (((const int*)mraw)[p] != 0) ? 1.0f : 0.0f;
            else             m = (((const float*)mraw)[p] != 0.0f) ? 1.0f : 0.0f;
            mv[i] = m;
            cnt += (m != 0.0f);
        }
        const int lane = tid & 31, wid = tid >> 5;
        int xs = cnt;
#pragma unroll
        for (int o = 1; o < 32; o <<= 1) {
            int y = __shfl_up_sync(0xffffffffu, xs, o);
            if (lane >= o) xs += y;
        }
        if (lane == 31) wsum[wid] = xs;
        __syncthreads();
        if (tid == 0) {
            int a = 0;
#pragma unroll
            for (int ww = 0; ww < 8; ww++) { int tt = wsum[ww]; wsum[ww] = a; a += tt; }
            g_nkeys[bb] = a;
        }
        __syncthreads();
        int c = xs - cnt + wsum[wid];
#pragma unroll
        for (int i = 0; i < 8; i++) {
            int p = base + p0 + i;
            g_mask[p] = mv[i];
            if (mv[i] != 0.0f) g_cidx[p] = c++;
        }
    }
}

// ---------------- fp16 frag GEMM, BK=64 stages, templated M-tile -------------
// MB = m16 blocks per CTA tile (8 -> 128 rows, 4 -> 64 rows). N tile = 128.
// A chunks/stage = MB*128 (16B each); B chunks = 1024.
template<int MB>
__global__ void __launch_bounds__(256, 2) gemm_af_kernel(
    const uint32_t* __restrict__ Aaf, const uint32_t* __restrict__ Bbf,
    float* __restrict__ C, int M, int N, int K)
{
    constexpr int MF  = MB / 2;             // m16 blocks per warp
    constexpr int ACH = MB * 128;           // A chunks per stage
    constexpr int TCH = ACH + 1024;         // total chunks per stage
    constexpr int SWORDS = TCH * 4;         // stage words

    extern __shared__ uint32_t gsm[];
    const uint32_t sbase = smem_u32(gsm);

    const int tid = threadIdx.x;
    const int w = tid >> 5, lane = tid & 31;
    const int g = lane >> 2, t = lane & 3;
    const int wm = w >> 2, wn = w & 3;
    const int bm = blockIdx.y, bn = blockIdx.x;
    const int K16 = K >> 4;
    const int nst = K >> 6;                 // BK = 64

    const char* Ab = (const char*)Aaf;
    const char* Bb = (const char*)Bbf;

    auto issue = [&](int s) {
        uint32_t base = sbase + (uint32_t)((s % 3) * (SWORDS * 4));
#pragma unroll
        for (int c = 0; c < TCH / 256; c++) {
            int ch = tid + 256 * c;
            if (ch < ACH) {
                int ablk = ch >> 5;                  // mb*4 + kb
                cp16(base + (uint32_t)(ch * 16),
                     Ab + ((size_t)((bm * MB + (ablk >> 2)) * K16 + s * 4 + (ablk & 3))) * 512 + (ch & 31) * 16);
            } else {
                int ch2 = ch - ACH;
                int bblk = ch2 >> 5;                 // pair*4 + kb
                cp16(base + (uint32_t)(ch * 16),
                     Bb + ((size_t)((bn * 8 + (bblk >> 2)) * K16 + s * 4 + (bblk & 3))) * 512 + (ch2 & 31) * 16);
            }
        }
        CP_COMMIT();
    };

    float acc[MF][4][4];
#pragma unroll
    for (int mf = 0; mf < MF; mf++)
#pragma unroll
        for (int nf = 0; nf < 4; nf++)
#pragma unroll
            for (int c = 0; c < 4; c++) acc[mf][nf][c] = 0.0f;

    issue(0);
    issue(1);

    for (int s = 0; s < nst; s++) {
        if (s + 1 == nst) { CP_WAIT0(); } else { CP_WAIT1(); }
        __syncthreads();
        if (s + 2 < nst) issue(s + 2);

        uint32_t* As = gsm + (s % 3) * SWORDS;
        uint32_t* Bs = As + ACH * 4;

#pragma unroll
        for (int kb = 0; kb < 4; kb++) {
            uint32_t a[MF][4];
#pragma unroll
            for (int mf = 0; mf < MF; mf++) {
                int mb = wm * MF + mf;
                uint4 av = *(const uint4*)&As[(mb * 4 + kb) * 128 + 4 * lane];
                a[mf][0] = av.x; a[mf][1] = av.y; a[mf][2] = av.z; a[mf][3] = av.w;
            }
#pragma unroll
            for (int nfp = 0; nfp < 2; nfp++) {
                uint4 bv = *(const uint4*)&Bs[((wn * 2 + nfp) * 4 + kb) * 128 + 4 * lane];
#pragma unroll
                for (int mf = 0; mf < MF; mf++) {
                    mma_f16(acc[mf][2 * nfp],     a[mf][0], a[mf][1], a[mf][2], a[mf][3], bv.x, bv.y);
                    mma_f16(acc[mf][2 * nfp + 1], a[mf][0], a[mf][1], a[mf][2], a[mf][3], bv.z, bv.w);
                }
            }
        }
    }

#pragma unroll
    for (int mf = 0; mf < MF; mf++) {
        int row = bm * (MB * 16) + wm * (MF * 16) + mf * 16 + g;
#pragma unroll
        for (int nf = 0; nf < 4; nf++) {
            int col = bn * 128 + wn * 32 + nf * 8 + 2 * t;
            *(float2*)&C[(size_t)row * N + col]       = make_float2(acc[mf][nf][0], acc[mf][nf][1]);
            *(float2*)&C[(size_t)(row + 8) * N + col] = make_float2(acc[mf][nf][2], acc[mf][nf][3]);
        }
    }
}

// ---------------- rotation (cp.async staging) + compacted k/v ---------------
__global__ void __launch_bounds__(256) rotate_kernel(const float* __restrict__ rot)
{
    const int p = blockIdx.x, tid = threadIdx.x;
    const int b = p >> 11, s = p & 2047;
    float* row = &g_qkv[(size_t)p * ROWQ];
    const bool masked = (g_mask[p] != 0.0f);

    if (masked) {
        const int c = g_cidx[p];
        __shared__ float4 Rr[64 * 17];   // row i at Rr[i*17 + j4]
        __shared__ float4 X4[256];

        const uint32_t rbase = smem_u32(Rr);
        const uint32_t xbase = smem_u32(X4);
        const float4* R4 = (const float4*)(rot + (size_t)p * 4096);
#pragma unroll
        for (int t2 = 0; t2 < 4; t2++) {
            int idx4 = tid + 256 * t2;
            cp16(rbase + (uint32_t)(((idx4 >> 4) * 17 + (idx4 & 15)) * 16), R4 + idx4);
        }
        cp16(xbase + (uint32_t)(tid * 16), ((const float4*)row) + tid);
        CP_COMMIT();

        // v processing overlaps the cp.async latency
#pragma unroll
        for (int t2 = 0; t2 < 2; t2++) {
            int idx = tid + 256 * t2;
            g_vh[vh_off(b * 8 + (idx >> 6), c, idx & 63)] = f2h(row[1024 + idx]);
        }

        CP_WAIT0();
        __syncthreads();

        const int i  = tid & 63;
        const int vb = tid >> 6;
        float acc[4] = {0.0f, 0.0f, 0.0f, 0.0f};
#pragma unroll
        for (int j4 = 0; j4 < 16; j4++) {
            float4 r = Rr[i * 17 + j4];
#pragma unroll
            for (int ii = 0; ii < 4; ii++) {
                float4 xv = X4[(vb + 4 * ii) * 16 + j4];
                acc[ii] = fmaf(r.x, xv.x, acc[ii]);
                acc[ii] = fmaf(r.y, xv.y, acc[ii]);
                acc[ii] = fmaf(r.z, xv.z, acc[ii]);
                acc[ii] = fmaf(r.w, xv.w, acc[ii]);
            }
        }
#pragma unroll
        for (int ii = 0; ii < 4; ii++) {
            int vv = vb + 4 * ii;
            unsigned short hv = f2h(acc[ii]);
            if (vv < 8) g_qh[qh_off(b * 8 + vv, s, i)] = hv;
            else        g_kh[kh_off(b * 8 + vv - 8, c, i)] = hv;
        }
    } else {
#pragma unroll
        for (int t2 = 0; t2 < 2; t2++) {
            int idx = tid + 256 * t2;
            g_qh[qh_off(b * 8 + (idx >> 6), s, idx & 63)] = f2h(row[idx]);
        }
    }
}

// ---------------- fp16 mma.sync Taylor attention (paired-B K/V) --------------
#define STGW 8192   // stage words: K 16KB | V 16KB

__global__ void __launch_bounds__(256, 2) attn_mma_kernel(uint32_t* __restrict__ outaf)
{
    extern __shared__ uint32_t sm[];
    const uint32_t sbase = smem_u32(sm);

    const int tid = threadIdx.x;
    const int w = tid >> 5, lane = tid & 31;
    const int t = lane & 3;
    const int qt = blockIdx.x, bh = blockIdx.y;
    const int b = bh >> 3, h = bh & 7;
    const int N = g_nkeys[b];
    const int nst = (N + 127) >> 7;

    uint32_t qa[4][4];
    {
        int qblk = qt * 8 + w;
        const uint4* qp = reinterpret_cast<const uint4*>(g_qh)
                          + (((size_t)bh * 128 + qblk) * 4) * 32 + lane;
#pragma unroll
        for (int k16 = 0; k16 < 4; k16++) {
            uint4 v = qp[k16 * 32];
            qa[k16][0] = v.x; qa[k16][1] = v.y; qa[k16][2] = v.z; qa[k16][3] = v.w;
        }
    }

    const char* kbase = (const char*)(g_kh + (size_t)bh * 32 * 4096);
    const char* vbase = (const char*)(g_vh + (size_t)bh * 32 * 4096);

    auto issue_stage = [&](int s) {
        const uint32_t dstb = sbase + (uint32_t)((s & 1) * STGW * 4);
        const char* ks = kbase + (size_t)s * 16384;
        const char* vs = vbase + (size_t)s * 16384;
#pragma unroll
        for (int c = 0; c < 4; c++) {
            int ch = tid * 4 + c;
            cp16(dstb + (uint32_t)(ch * 16), ks + ch * 16);
            cp16(dstb + 16384u + (uint32_t)(ch * 16), vs + ch * 16);
        }
        CP_COMMIT();
    };

    float outr[8][4];
#pragma unroll
    for (int n = 0; n < 8; n++)
#pragma unroll
        for (int j = 0; j < 4; j++) outr[n][j] = 0.0f;
    float dacc[4] = {0.0f, 0.0f, 0.0f, 0.0f};

    issue_stage(0);

    for (int s = 0; s < nst; s++) {
        CP_WAIT0();
        __syncthreads();
        if (s + 1 < nst) issue_stage(s + 1);

        uint32_t* base = sm + (s & 1) * STGW;
        const bool needmask = ((s + 1) * 128 > N);

#pragma unroll
        for (int h2 = 0; h2 < 2; h2++) {
            uint32_t* Kf = base + h2 * 2048;
            uint32_t* Vf = base + 4096 + h2 * 2048;

            float sc[8][4];
#pragma unroll
            for (int n = 0; n < 8; n++)
#pragma unroll
                for (int j = 0; j < 4; j++) sc[n][j] = 0.0f;

#pragma unroll
            for (int k16 = 0; k16 < 4; k16++) {
#pragma unroll
                for (int pr = 0; pr < 4; pr++) {
                    uint4 kf = *(const uint4*)&Kf[(pr * 4 + k16) * 128 + 4 * lane];
                    mma_f16(sc[2 * pr],     qa[k16][0], qa[k16][1], qa[k16][2], qa[k16][3], kf.x, kf.y);
                    mma_f16(sc[2 * pr + 1], qa[k16][0], qa[k16][1], qa[k16][2], qa[k16][3], kf.z, kf.w);
                }
            }

            uint32_t wpA[8], wpB[8];
#pragma unroll
            for (int n = 0; n < 8; n++) {
                uint32_t sA = pack_h2(sc[n][0], sc[n][1]);
                uint32_t sB = pack_h2(sc[n][2], sc[n][3]);
                wpA[n] = hfma2(sA, hfma2(sA, H2_C128, H2_C8), H2_ONE);
                wpB[n] = hfma2(sB, hfma2(sB, H2_C128, H2_C8), H2_ONE);
                if (needmask) {
                    int k0 = s * 128 + h2 * 64 + n * 8 + 2 * t;
                    uint32_t mm = (k0 < N ? 0x0000FFFFu : 0u) | (k0 + 1 < N ? 0xFFFF0000u : 0u);
                    wpA[n] &= mm;
                    wpB[n] &= mm;
                }
            }

#pragma unroll
            for (int j2 = 0; j2 < 4; j2++) {
                uint32_t a0 = wpA[2 * j2], a1 = wpB[2 * j2];
                uint32_t a2 = wpA[2 * j2 + 1], a3 = wpB[2 * j2 + 1];
                mma_f16(dacc, a0, a1, a2, a3, H2_ONE, H2_ONE);
#pragma unroll
                for (int dp = 0; dp < 4; dp++) {
                    uint4 vf = *(const uint4*)&Vf[(dp * 4 + j2) * 128 + 4 * lane];
                    mma_f16(outr[2 * dp],     a0, a1, a2, a3, vf.x, vf.y);
                    mma_f16(outr[2 * dp + 1], a0, a1, a2, a3, vf.z, vf.w);
                }
            }
        }
    }

    float inv0 = 1.0f / dacc[0];
    float inv1 = 1.0f / dacc[2];

    {
        size_t qb = (size_t)((b * SS + qt * 128 + w * 16) >> 4);
#pragma unroll
        for (int dn = 0; dn < 8; dn++) {
            size_t block = qb * 32 + h * 4 + (dn >> 1);
            int jA = 2 * (dn & 1);
            outaf[block * 128 + lane * 4 + jA]     = pack_h2(outr[dn][0] * inv0, outr[dn][1] * inv0);
            outaf[block * 128 + lane * 4 + jA + 1] = pack_h2(outr[dn][2] * inv1, outr[dn][3] * inv1);
        }
    }
}

// ---------------- launch ----------------
extern "C" void kernel_launch(void* const* d_in, const int* in_sizes, int n_in,
                              void* d_out, int out_size)
{
    const float*         x    = (const float*)d_in[0];
    const unsigned char* mask = (const unsigned char*)d_in[1];
    const float*         rot  = (const float*)d_in[2];
    const float*         Wt   = (const float*)d_in[3];
    const float*         Wo   = (const float*)d_in[4];
    float*               out  = (float*)d_out;

    float *qkv_p;
    uint32_t *attaf_p, *xaf_p, *wtbf_p, *wobf_p;
    cudaGetSymbolAddress((void**)&qkv_p,   g_qkv);
    cudaGetSymbolAddress((void**)&attaf_p, g_attaf);
    cudaGetSymbolAddress((void**)&xaf_p,   g_xaf);
    cudaGetSymbolAddress((void**)&wtbf_p,  g_wtbf);
    cudaGetSymbolAddress((void**)&wobf_p,  g_wobf);

    static const int ATT_SMEM   = 2 * STGW * 4;          // 65,536 B
    static const int GEMM1_SMEM = 3 * (8 * 128 + 1024) * 16;   // 98,304 B
    static const int GEMM2_SMEM = 3 * (4 * 128 + 1024) * 16;   // 73,728 B
    cudaFuncSetAttribute(attn_mma_kernel, cudaFuncAttributeMaxDynamicSharedMemorySize, ATT_SMEM);
    cudaFuncSetAttribute(gemm_af_kernel<8>, cudaFuncAttributeMaxDynamicSharedMemorySize, GEMM1_SMEM);
    cudaFuncSetAttribute(gemm_af_kernel<4>, cudaFuncAttributeMaxDynamicSharedMemorySize, GEMM2_SMEM);

    // fused prep
    prep_kernel<<<3074, 256>>>((const float4*)x, mask, (const float4*)Wt, (const float4*)Wo);

    // qkv = x @ W_trans^T  (128-row tiles, BK=64)
    gemm_af_kernel<8><<<dim3(ROWQ / 128, NP / 128), 256, GEMM1_SMEM>>>(xaf_p, wtbf_p, qkv_p, NP, ROWQ, DIM);

    // rotate q,k where masked; emit frag-ordered q + COMPACTED paired k/v
    rotate_kernel<<<NP, 256>>>(rot);

    // attention over compacted keys -> g_attaf
    attn_mma_kernel<<<dim3(SS / 128, BB * NH), 256, ATT_SMEM>>>(attaf_p);

    // out = att @ W_o^T  (64-row tiles, BK=64 -> 256 CTAs, 2/SM overlap)
    gemm_af_kernel<4><<<dim3(DIM / 128, NP / 64), 256, GEMM2_SMEM>>>(attaf_p, wobf_p, out, NP, DIM, DIM);
}